// round 1
// baseline (speedup 1.0000x reference)
#include <cuda_runtime.h>
#include <cstddef>
#include <cstdint>
#include <math.h>

// ---------------------------------------------------------------------------
// Problem constants
// ---------------------------------------------------------------------------
#define BATCH 8
#define CH    512
#define KDIM  128          // C/4 for q/k projections
#define EPSV  1e-5f

#define HW2 2304           // 48*48
#define HW3 576            // 24*24
#define HW4 144            // 12*12

// ---------------------------------------------------------------------------
// Scratch (allocation-free: __device__ globals)
// ---------------------------------------------------------------------------
__device__ float g_d2[BATCH * CH * HW2];
__device__ float g_d3[BATCH * CH * HW3];
__device__ float g_d4[BATCH * CH * HW4];
__device__ float g_q [BATCH * KDIM * HW2];
__device__ float g_kb[BATCH * KDIM * HW2];
__device__ float g_v [BATCH * CH * HW2];
__device__ float g_att[(size_t)BATCH * HW2 * HW2];   // 170 MB energy/attn
__device__ float g_p2[BATCH * CH * HW2];
__device__ float g_p3[BATCH * CH * HW3];
__device__ float g_p4[BATCH * CH * HW4];
__device__ float g_t3[BATCH * CH * HW3];
__device__ float g_t2[BATCH * CH * HW2];
__device__ float g_scale[CH];
__device__ float g_shift[CH];

// ---------------------------------------------------------------------------
// Direct 3x3 stride-2 pad-1 conv, C=512 -> C=512.
// grid: (OH, 512/64, B), block: (OW, 4). Each thread: 16 consecutive oc.
// ic chunks of 8 staged in smem; weights in smem with stride 68 (bank-spread,
// still 16B-aligned rows so the 16-wide oc reads vectorize to LDS.128).
// ---------------------------------------------------------------------------
template <int IH, int IW>
__global__ void conv3s2_kernel(const float* __restrict__ x,
                               const float* __restrict__ wgt,
                               float* __restrict__ y)
{
    constexpr int OH = IH / 2, OW = IW / 2, SW = IW + 2;
    __shared__ float in_s[8][3][SW];
    __shared__ float w_s[8][9][68];

    const int oh  = blockIdx.x;
    const int oc0 = blockIdx.y * 64;
    const int b   = blockIdx.z;
    const int ow  = threadIdx.x;
    const int ty  = threadIdx.y;
    const int tid = ty * OW + ow;
    constexpr int NT = OW * 4;

    const float* xb = x + (size_t)b * CH * IH * IW;

    float acc[16];
#pragma unroll
    for (int r = 0; r < 16; r++) acc[r] = 0.f;

    for (int c0 = 0; c0 < CH; c0 += 8) {
        __syncthreads();
        // stage input rows 2*oh-1 .. 2*oh+1 (padded) for 8 input channels
        for (int i = tid; i < 8 * 3 * SW; i += NT) {
            int icl = i / (3 * SW);
            int rem = i - icl * 3 * SW;
            int kh  = rem / SW;
            int s   = rem - kh * SW;
            int row = 2 * oh - 1 + kh;
            int col = s - 1;
            float v = 0.f;
            if (row >= 0 && row < IH && col >= 0 && col < IW)
                v = xb[(size_t)(c0 + icl) * IH * IW + row * IW + col];
            in_s[icl][kh][s] = v;
        }
        // stage weights for 64 oc x 8 ic x 9 (coalesced: 72 consecutive per oc)
        for (int i = tid; i < 64 * 72; i += NT) {
            int ocl = i / 72;
            int rem = i - ocl * 72;
            int icl = rem / 9;
            int kk  = rem - icl * 9;
            w_s[icl][kk][ocl] =
                wgt[(size_t)(oc0 + ocl) * (CH * 9) + (size_t)(c0 + icl) * 9 + kk];
        }
        __syncthreads();

        const int ob = ty * 16;
#pragma unroll
        for (int icl = 0; icl < 8; icl++) {
#pragma unroll
            for (int kh = 0; kh < 3; kh++) {
                float i0 = in_s[icl][kh][2 * ow + 0];
                float i1 = in_s[icl][kh][2 * ow + 1];
                float i2 = in_s[icl][kh][2 * ow + 2];
                const float* w0 = &w_s[icl][3 * kh + 0][ob];
                const float* w1 = &w_s[icl][3 * kh + 1][ob];
                const float* w2 = &w_s[icl][3 * kh + 2][ob];
#pragma unroll
                for (int r = 0; r < 16; r++)
                    acc[r] += i0 * w0[r] + i1 * w1[r] + i2 * w2[r];
            }
        }
    }

    const int ob = ty * 16;
#pragma unroll
    for (int r = 0; r < 16; r++) {
        int oc = oc0 + ob + r;
        y[(((size_t)b * CH + oc) * OH + oh) * OW + ow] = acc[r];
    }
}

// ---------------------------------------------------------------------------
// BN statistics: one block per channel, deterministic tree reduction.
// Produces scale = g*rsqrt(var+eps), shift = b - mean*scale.
// ---------------------------------------------------------------------------
__global__ void bn_stats_k(const float* __restrict__ y, int HW,
                           const float* __restrict__ gw,
                           const float* __restrict__ gb,
                           float* __restrict__ scale,
                           float* __restrict__ shift)
{
    const int c = blockIdx.x;
    const int t = threadIdx.x;
    float s = 0.f, s2 = 0.f;
    for (int b = 0; b < BATCH; b++) {
        const float* p = y + ((size_t)b * CH + c) * HW;
        for (int i = t; i < HW; i += 256) {
            float v = p[i];
            s += v; s2 += v * v;
        }
    }
#pragma unroll
    for (int o = 16; o; o >>= 1) {
        s  += __shfl_xor_sync(0xffffffffu, s, o);
        s2 += __shfl_xor_sync(0xffffffffu, s2, o);
    }
    __shared__ float r1[8], r2[8];
    if ((t & 31) == 0) { r1[t >> 5] = s; r2[t >> 5] = s2; }
    __syncthreads();
    if (t == 0) {
        float a = 0.f, b2 = 0.f;
        for (int i = 0; i < 8; i++) { a += r1[i]; b2 += r2[i]; }
        float n   = (float)(BATCH * HW);
        float m   = a / n;
        float var = b2 / n - m * m;
        float sc  = gw[c] * rsqrtf(var + EPSV);
        scale[c] = sc;
        shift[c] = gb[c] - m * sc;
    }
}

__global__ void bn_relu_k(float* __restrict__ y,
                          const float* __restrict__ scale,
                          const float* __restrict__ shift,
                          int HW, size_t total)
{
    size_t i = (size_t)blockIdx.x * blockDim.x + threadIdx.x;
    if (i >= total) return;
    int c = (int)((i / HW) & (CH - 1));
    float v = y[i] * scale[c] + shift[c];
    y[i] = v > 0.f ? v : 0.f;
}

// ---------------------------------------------------------------------------
// SGEMM, 128x64x16 tiles, 256 threads, 8x4 micro-tile. Row-major.
// TA: A stored (K,M). TB: B stored (N,K). Epilogue:
//   C = s*acc + bias[row] + addm   (each part optional; s read from *scl)
// All K values are multiples of 16; all M,N multiples of 4 -> float4 guards.
// ---------------------------------------------------------------------------
template <int TA, int TB>
__global__ void gemm_k(const float* __restrict__ A, const float* __restrict__ Bm,
                       float* __restrict__ C, int M, int N, int Kd,
                       long long sA, long long sB, long long sC,
                       const float* __restrict__ bias,
                       const float* __restrict__ addm,
                       const float* __restrict__ scl)
{
    __shared__ float As[16][128];
    __shared__ float Bs[16][64];

    const int bz = blockIdx.z;
    const float* Ab = A + (size_t)bz * sA;
    const float* Bb = Bm + (size_t)bz * sB;
    float* Cb = C + (size_t)bz * sC;

    const int m0 = blockIdx.y * 128, n0 = blockIdx.x * 64;
    const int t  = threadIdx.x;
    const int tx = t & 15, ty = t >> 4;
    const int lda = TA ? M : Kd;
    const int ldb = TB ? Kd : N;

    float acc[8][4];
#pragma unroll
    for (int i = 0; i < 8; i++)
#pragma unroll
        for (int j = 0; j < 4; j++) acc[i][j] = 0.f;

    for (int k0 = 0; k0 < Kd; k0 += 16) {
        if (TA) {
#pragma unroll
            for (int i = 0; i < 2; i++) {
                int e  = t + i * 256;
                int kk = e >> 5;
                int m4 = (e & 31) << 2;
                float4 v = make_float4(0.f, 0.f, 0.f, 0.f);
                if (m0 + m4 < M)
                    v = *(const float4*)(Ab + (size_t)(k0 + kk) * lda + m0 + m4);
                *(float4*)&As[kk][m4] = v;
            }
        } else {
#pragma unroll
            for (int i = 0; i < 2; i++) {
                int e   = t + i * 256;
                int row = e >> 2;
                int c4  = (e & 3) << 2;
                float4 v = make_float4(0.f, 0.f, 0.f, 0.f);
                if (m0 + row < M)
                    v = *(const float4*)(Ab + (size_t)(m0 + row) * lda + k0 + c4);
                As[c4 + 0][row] = v.x; As[c4 + 1][row] = v.y;
                As[c4 + 2][row] = v.z; As[c4 + 3][row] = v.w;
            }
        }
        if (!TB) {
            int kk = t >> 4, n4 = (t & 15) << 2;
            float4 v = make_float4(0.f, 0.f, 0.f, 0.f);
            if (n0 + n4 < N)
                v = *(const float4*)(Bb + (size_t)(k0 + kk) * ldb + n0 + n4);
            *(float4*)&Bs[kk][n4] = v;
        } else {
            int row = t >> 2, c4 = (t & 3) << 2;
            float4 v = make_float4(0.f, 0.f, 0.f, 0.f);
            if (n0 + row < N)
                v = *(const float4*)(Bb + (size_t)(n0 + row) * ldb + k0 + c4);
            Bs[c4 + 0][row] = v.x; Bs[c4 + 1][row] = v.y;
            Bs[c4 + 2][row] = v.z; Bs[c4 + 3][row] = v.w;
        }
        __syncthreads();

#pragma unroll
        for (int kk = 0; kk < 16; kk++) {
            float4 a0 = *(const float4*)&As[kk][ty * 8];
            float4 a1 = *(const float4*)&As[kk][ty * 8 + 4];
            float4 bv = *(const float4*)&Bs[kk][tx * 4];
            float av[8] = {a0.x, a0.y, a0.z, a0.w, a1.x, a1.y, a1.z, a1.w};
#pragma unroll
            for (int i = 0; i < 8; i++) {
                acc[i][0] += av[i] * bv.x;
                acc[i][1] += av[i] * bv.y;
                acc[i][2] += av[i] * bv.z;
                acc[i][3] += av[i] * bv.w;
            }
        }
        __syncthreads();
    }

    float s = scl ? *scl : 1.f;
#pragma unroll
    for (int i = 0; i < 8; i++) {
        int gr = m0 + ty * 8 + i;
        if (gr >= M) continue;
        float bi = bias ? bias[gr] : 0.f;
#pragma unroll
        for (int j = 0; j < 4; j++) {
            int gc = n0 + tx * 4 + j;
            if (gc >= N) continue;
            float v = s * acc[i][j] + bi;
            if (addm) v += addm[(size_t)bz * sC + (size_t)gr * N + gc];
            Cb[(size_t)gr * N + gc] = v;
        }
    }
}

// ---------------------------------------------------------------------------
// Row softmax, in place. One block per row; row staged in dynamic smem.
// ---------------------------------------------------------------------------
__global__ void softmax_k(float* __restrict__ E, int L)
{
    extern __shared__ float sm[];
    float* red = sm + L;
    const size_t row = blockIdx.x;
    float* p = E + row * (size_t)L;
    const int t = threadIdx.x;

    float mx = -3.4e38f;
    for (int i = t; i < L; i += 256) {
        float v = p[i];
        sm[i] = v;
        mx = fmaxf(mx, v);
    }
#pragma unroll
    for (int o = 16; o; o >>= 1) mx = fmaxf(mx, __shfl_xor_sync(0xffffffffu, mx, o));
    if ((t & 31) == 0) red[t >> 5] = mx;
    __syncthreads();
    if (t < 32) {
        float v = (t < 8) ? red[t] : -3.4e38f;
#pragma unroll
        for (int o = 4; o; o >>= 1) v = fmaxf(v, __shfl_xor_sync(0xffffffffu, v, o));
        if (t == 0) red[0] = v;
    }
    __syncthreads();
    mx = red[0];
    __syncthreads();

    float ss = 0.f;
    for (int i = t; i < L; i += 256) {
        float e = __expf(sm[i] - mx);
        sm[i] = e;
        ss += e;
    }
#pragma unroll
    for (int o = 16; o; o >>= 1) ss += __shfl_xor_sync(0xffffffffu, ss, o);
    if ((t & 31) == 0) red[t >> 5] = ss;
    __syncthreads();
    if (t < 32) {
        float v = (t < 8) ? red[t] : 0.f;
#pragma unroll
        for (int o = 4; o; o >>= 1) v += __shfl_xor_sync(0xffffffffu, v, o);
        if (t == 0) red[0] = v;
    }
    __syncthreads();
    float inv = 1.f / red[0];
    for (int i = t; i < L; i += 256) p[i] = sm[i] * inv;
}

// ---------------------------------------------------------------------------
// dst = add + g * bilinear_upsample(src)   (g from *gptr, or 1.0)
// Matches jnp.linspace(0, SH-1, DH) sampling.
// ---------------------------------------------------------------------------
__global__ void up_fma_k(const float* __restrict__ src, int SH, int SWd,
                         const float* __restrict__ add, float* __restrict__ dst,
                         int DH, int DW, const float* __restrict__ gptr,
                         size_t total)
{
    size_t i = (size_t)blockIdx.x * blockDim.x + threadIdx.x;
    if (i >= total) return;
    int ox = (int)(i % DW);
    int oy = (int)((i / DW) % DH);
    size_t bc = i / ((size_t)DW * DH);

    float ry = (float)(SH - 1) / (float)(DH - 1);
    float rx = (float)(SWd - 1) / (float)(DW - 1);
    float ys = oy * ry, xs = ox * rx;
    int y0 = (int)ys; if (y0 > SH - 1) y0 = SH - 1;
    int x0 = (int)xs; if (x0 > SWd - 1) x0 = SWd - 1;
    int y1 = min(y0 + 1, SH - 1);
    int x1 = min(x0 + 1, SWd - 1);
    float tty = ys - (float)y0, ttx = xs - (float)x0;

    const float* sp = src + bc * (size_t)(SH * SWd);
    float v00 = sp[y0 * SWd + x0], v01 = sp[y0 * SWd + x1];
    float v10 = sp[y1 * SWd + x0], v11 = sp[y1 * SWd + x1];
    float val = v00 * (1.f - tty) * (1.f - ttx) + v01 * (1.f - tty) * ttx
              + v10 * tty * (1.f - ttx) + v11 * tty * ttx;
    float g = gptr ? *gptr : 1.f;
    dst[i] = add[i] + g * val;
}

// ---------------------------------------------------------------------------
// Host side
// ---------------------------------------------------------------------------
static void run_pam(const float* d, int HW,
                    const float* qw, const float* qb,
                    const float* kw, const float* kb,
                    const float* vw, const float* vb,
                    const float* g, float* pout,
                    float* qbuf, float* kbuf, float* vbuf, float* att)
{
    dim3 thr(256);
    int tn = (HW + 63) / 64;
    long long dStride = (long long)CH * HW;
    long long qStride = (long long)KDIM * HW;
    long long aStride = (long long)HW * HW;

    // q = qw @ d + qb   (128 x HW)
    gemm_k<0, 0><<<dim3(tn, 1, BATCH), thr>>>(qw, d, qbuf, KDIM, HW, CH,
                                              0, dStride, qStride, qb, nullptr, nullptr);
    // k = kw @ d + kb
    gemm_k<0, 0><<<dim3(tn, 1, BATCH), thr>>>(kw, d, kbuf, KDIM, HW, CH,
                                              0, dStride, qStride, kb, nullptr, nullptr);
    // v = vw @ d + vb   (512 x HW)
    gemm_k<0, 0><<<dim3(tn, 4, BATCH), thr>>>(vw, d, vbuf, CH, HW, CH,
                                              0, dStride, dStride, vb, nullptr, nullptr);
    // energy = q^T k    (HW x HW)
    gemm_k<1, 0><<<dim3(tn, (HW + 127) / 128, BATCH), thr>>>(qbuf, kbuf, att, HW, HW, KDIM,
                                              qStride, qStride, aStride,
                                              nullptr, nullptr, nullptr);
    // softmax over rows
    softmax_k<<<BATCH * HW, 256, (HW + 32) * sizeof(float)>>>(att, HW);
    // p = g * (v @ attn^T) + v
    gemm_k<0, 1><<<dim3(tn, 4, BATCH), thr>>>(vbuf, att, pout, CH, HW, HW,
                                              dStride, aStride, dStride,
                                              nullptr, vbuf, g);
}

extern "C" void kernel_launch(void* const* d_in, const int* in_sizes, int n_in,
                              void* d_out, int out_size)
{
    (void)in_sizes; (void)n_in; (void)out_size;
    const float* x = (const float*)d_in[0];
    // per level: w, bnw, bnb, qw, qb, kw, kb, vw, vb, g
    const float* w2   = (const float*)d_in[1];
    const float* bnw2 = (const float*)d_in[2];
    const float* bnb2 = (const float*)d_in[3];
    const float* w3   = (const float*)d_in[11];
    const float* bnw3 = (const float*)d_in[12];
    const float* bnb3 = (const float*)d_in[13];
    const float* w4   = (const float*)d_in[21];
    const float* bnw4 = (const float*)d_in[22];
    const float* bnb4 = (const float*)d_in[23];
    const float* gamma = (const float*)d_in[31];
    float* out = (float*)d_out;

    void* p;
    cudaGetSymbolAddress(&p, g_d2);    float* d2    = (float*)p;
    cudaGetSymbolAddress(&p, g_d3);    float* d3    = (float*)p;
    cudaGetSymbolAddress(&p, g_d4);    float* d4    = (float*)p;
    cudaGetSymbolAddress(&p, g_q);     float* qbuf  = (float*)p;
    cudaGetSymbolAddress(&p, g_kb);    float* kbuf  = (float*)p;
    cudaGetSymbolAddress(&p, g_v);     float* vbuf  = (float*)p;
    cudaGetSymbolAddress(&p, g_att);   float* att   = (float*)p;
    cudaGetSymbolAddress(&p, g_p2);    float* p2    = (float*)p;
    cudaGetSymbolAddress(&p, g_p3);    float* p3    = (float*)p;
    cudaGetSymbolAddress(&p, g_p4);    float* p4    = (float*)p;
    cudaGetSymbolAddress(&p, g_t3);    float* t3    = (float*)p;
    cudaGetSymbolAddress(&p, g_t2);    float* t2    = (float*)p;
    cudaGetSymbolAddress(&p, g_scale); float* scale = (float*)p;
    cudaGetSymbolAddress(&p, g_shift); float* shift = (float*)p;

    // ---- encoder: conv3x3 s2 + BN(batch stats) + relu, 3 levels ----
    {
        conv3s2_kernel<96, 96><<<dim3(48, 8, BATCH), dim3(48, 4)>>>(x, w2, d2);
        bn_stats_k<<<CH, 256>>>(d2, HW2, bnw2, bnb2, scale, shift);
        size_t tot = (size_t)BATCH * CH * HW2;
        bn_relu_k<<<(unsigned)((tot + 255) / 256), 256>>>(d2, scale, shift, HW2, tot);
    }
    {
        conv3s2_kernel<48, 48><<<dim3(24, 8, BATCH), dim3(24, 4)>>>(d2, w3, d3);
        bn_stats_k<<<CH, 256>>>(d3, HW3, bnw3, bnb3, scale, shift);
        size_t tot = (size_t)BATCH * CH * HW3;
        bn_relu_k<<<(unsigned)((tot + 255) / 256), 256>>>(d3, scale, shift, HW3, tot);
    }
    {
        conv3s2_kernel<24, 24><<<dim3(12, 8, BATCH), dim3(12, 4)>>>(d3, w4, d4);
        bn_stats_k<<<CH, 256>>>(d4, HW4, bnw4, bnb4, scale, shift);
        size_t tot = (size_t)BATCH * CH * HW4;
        bn_relu_k<<<(unsigned)((tot + 255) / 256), 256>>>(d4, scale, shift, HW4, tot);
    }

    // ---- PAM at each level ----
    run_pam(d2, HW2, (const float*)d_in[4],  (const float*)d_in[5],
                     (const float*)d_in[6],  (const float*)d_in[7],
                     (const float*)d_in[8],  (const float*)d_in[9],
                     (const float*)d_in[10], p2, qbuf, kbuf, vbuf, att);
    run_pam(d3, HW3, (const float*)d_in[14], (const float*)d_in[15],
                     (const float*)d_in[16], (const float*)d_in[17],
                     (const float*)d_in[18], (const float*)d_in[19],
                     (const float*)d_in[20], p3, qbuf, kbuf, vbuf, att);
    run_pam(d4, HW4, (const float*)d_in[24], (const float*)d_in[25],
                     (const float*)d_in[26], (const float*)d_in[27],
                     (const float*)d_in[28], (const float*)d_in[29],
                     (const float*)d_in[30], p4, qbuf, kbuf, vbuf, att);

    // ---- top-down upsample chain ----
    {
        size_t tot = (size_t)BATCH * CH * HW3;   // 24x24
        up_fma_k<<<(unsigned)((tot + 255) / 256), 256>>>(p4, 12, 12, p3, t3, 24, 24,
                                                         nullptr, tot);
    }
    {
        size_t tot = (size_t)BATCH * CH * HW2;   // 48x48
        up_fma_k<<<(unsigned)((tot + 255) / 256), 256>>>(t3, 24, 24, p2, t2, 48, 48,
                                                         nullptr, tot);
    }
    {
        size_t tot = (size_t)BATCH * CH * 96 * 96;
        up_fma_k<<<(unsigned)((tot + 255) / 256), 256>>>(t2, 48, 48, x, out, 96, 96,
                                                         gamma, tot);
    }
}

// round 2
// speedup vs baseline: 2.2589x; 2.2589x over previous
#include <cuda_runtime.h>
#include <cstddef>
#include <cstdint>
#include <math.h>

// ---------------------------------------------------------------------------
// Problem constants
// ---------------------------------------------------------------------------
#define BATCH 8
#define CH    512
#define KDIM  128
#define EPSV  1e-5f

#define HW2 2304           // 48*48
#define HW3 576            // 24*24
#define HW4 144            // 12*12
#define KC  4608           // 512*9 im2col K

// ---------------------------------------------------------------------------
// Scratch (allocation-free: __device__ globals)
// ---------------------------------------------------------------------------
__device__ float g_d2[BATCH * CH * HW2];
__device__ float g_d3[BATCH * CH * HW3];
__device__ float g_d4[BATCH * CH * HW4];
__device__ float g_q [BATCH * KDIM * HW2];
__device__ float g_kb[BATCH * KDIM * HW2];
__device__ float g_v [BATCH * CH * HW2];
__device__ float g_att[(size_t)BATCH * HW2 * HW2];   // 170 MB energy/attn
__device__ float g_p2[BATCH * CH * HW2];
__device__ float g_p3[BATCH * CH * HW3];
__device__ float g_p4[BATCH * CH * HW4];
__device__ float g_t3[BATCH * CH * HW3];
__device__ float g_t2[BATCH * CH * HW2];
__device__ float g_scale[CH];
__device__ float g_shift[CH];
__device__ float g_col[(size_t)BATCH * KC * HW2];    // 340 MB im2col scratch

// ---------------------------------------------------------------------------
// tf32 rounding helper
// ---------------------------------------------------------------------------
__device__ __forceinline__ float tf32r(float x)
{
    unsigned u;
    asm("cvt.rna.tf32.f32 %0, %1;" : "=r"(u) : "f"(x));
    return __uint_as_float(u);
}

// ---------------------------------------------------------------------------
// im2col for 3x3 stride-2 pad-1 conv. Per-batch layout:
//   col[b][k = ic*9+kh*3+kw][pix = oh*OW+ow]
// ---------------------------------------------------------------------------
template <int IH, int IW>
__global__ void im2col_k(const float* __restrict__ x, float* __restrict__ col)
{
    constexpr int OH = IH / 2, OW = IW / 2, OHOW = OH * OW;
    size_t i = (size_t)blockIdx.x * blockDim.x + threadIdx.x;
    size_t total = (size_t)BATCH * KC * OHOW;
    if (i >= total) return;
    int pix = (int)(i % OHOW);
    size_t r = i / OHOW;
    int k = (int)(r % KC);
    int b = (int)(r / KC);
    int ic = k / 9;
    int kk = k - ic * 9;
    int kh = kk / 3, kw = kk - kh * 3;
    int oh = pix / OW, ow = pix - oh * OW;
    int ih = 2 * oh - 1 + kh;
    int iw = 2 * ow - 1 + kw;
    float v = 0.f;
    if (ih >= 0 && ih < IH && iw >= 0 && iw < IW)
        v = x[(((size_t)b * CH + ic) * IH + ih) * IW + iw];
    col[i] = v;
}

// ---------------------------------------------------------------------------
// Tensor-core tf32 GEMM. C(M,N) = op(A) * op(B), row-major C.
// TA=0: A is (M,K) row-major.  TA=1: A stored (K,M).
// TB=0: B is (K,N) row-major.  TB=1: B stored (N,K).
// Block tile 128x128x32, 8 warps, warp tile 64x32 via m16n8k8 tf32 mma.
// Epilogue: C = s*acc + bias[row] (+ addm), s from *scl (or 1).
// M,N,K are multiples of 16 in all our calls.
// ---------------------------------------------------------------------------
template <int TA, int TB>
__global__ __launch_bounds__(256, 2)
void gemm_tc(const float* __restrict__ A, const float* __restrict__ B,
             float* __restrict__ C, int M, int N, int K,
             long long sA, long long sB, long long sC,
             const float* __restrict__ bias,
             const float* __restrict__ addm,
             const float* __restrict__ scl)
{
    __shared__ float As[128][36];   // [m][k] padded
    __shared__ float Bs[128][36];   // [n][k] padded

    const int bz = blockIdx.z;
    const float* Ab = A + (size_t)bz * sA;
    const float* Bb = B + (size_t)bz * sB;
    float* Cb = C + (size_t)bz * sC;

    const int n0 = blockIdx.x * 128, m0 = blockIdx.y * 128;
    const int t = threadIdx.x, lane = t & 31, w = t >> 5;
    const int wm = w & 1, wn = w >> 1;          // 2 x 4 warp grid
    const int g = lane >> 2, tg = lane & 3;

    const int ldA = TA ? M : K;
    const int ldB = TB ? K : N;

    float acc[4][4][4];
#pragma unroll
    for (int a = 0; a < 4; a++)
#pragma unroll
        for (int b = 0; b < 4; b++)
#pragma unroll
            for (int c = 0; c < 4; c++) acc[a][b][c] = 0.f;

    for (int k0 = 0; k0 < K; k0 += 32) {
        // ---- stage A into As[m][k] ----
        if (!TA) {
#pragma unroll
            for (int i = 0; i < 4; i++) {
                int f = t + i * 256;
                int m = f >> 3, kc = (f & 7) << 2;
                float4 v = make_float4(0.f, 0.f, 0.f, 0.f);
                if (m0 + m < M && k0 + kc < K)
                    v = *(const float4*)(Ab + (size_t)(m0 + m) * ldA + k0 + kc);
                float4 o = make_float4(tf32r(v.x), tf32r(v.y), tf32r(v.z), tf32r(v.w));
                *(float4*)&As[m][kc] = o;
            }
        } else {
#pragma unroll
            for (int i = 0; i < 4; i++) {
                int f = t + i * 256;
                int k = f >> 5, mc = (f & 31) << 2;
                float4 v = make_float4(0.f, 0.f, 0.f, 0.f);
                if (k0 + k < K && m0 + mc < M)
                    v = *(const float4*)(Ab + (size_t)(k0 + k) * ldA + m0 + mc);
                As[mc + 0][k] = tf32r(v.x);
                As[mc + 1][k] = tf32r(v.y);
                As[mc + 2][k] = tf32r(v.z);
                As[mc + 3][k] = tf32r(v.w);
            }
        }
        // ---- stage B into Bs[n][k] ----
        if (TB) {
#pragma unroll
            for (int i = 0; i < 4; i++) {
                int f = t + i * 256;
                int n = f >> 3, kc = (f & 7) << 2;
                float4 v = make_float4(0.f, 0.f, 0.f, 0.f);
                if (n0 + n < N && k0 + kc < K)
                    v = *(const float4*)(Bb + (size_t)(n0 + n) * ldB + k0 + kc);
                float4 o = make_float4(tf32r(v.x), tf32r(v.y), tf32r(v.z), tf32r(v.w));
                *(float4*)&Bs[n][kc] = o;
            }
        } else {
#pragma unroll
            for (int i = 0; i < 4; i++) {
                int f = t + i * 256;
                int k = f >> 5, nc = (f & 31) << 2;
                float4 v = make_float4(0.f, 0.f, 0.f, 0.f);
                if (k0 + k < K && n0 + nc < N)
                    v = *(const float4*)(Bb + (size_t)(k0 + k) * ldB + n0 + nc);
                Bs[nc + 0][k] = tf32r(v.x);
                Bs[nc + 1][k] = tf32r(v.y);
                Bs[nc + 2][k] = tf32r(v.z);
                Bs[nc + 3][k] = tf32r(v.w);
            }
        }
        __syncthreads();

#pragma unroll
        for (int k8 = 0; k8 < 32; k8 += 8) {
            unsigned a[4][4], b[4][2];
#pragma unroll
            for (int mt = 0; mt < 4; mt++) {
                int r = wm * 64 + mt * 16 + g;
                a[mt][0] = __float_as_uint(As[r][k8 + tg]);
                a[mt][1] = __float_as_uint(As[r + 8][k8 + tg]);
                a[mt][2] = __float_as_uint(As[r][k8 + tg + 4]);
                a[mt][3] = __float_as_uint(As[r + 8][k8 + tg + 4]);
            }
#pragma unroll
            for (int nt = 0; nt < 4; nt++) {
                int cn = wn * 32 + nt * 8 + g;
                b[nt][0] = __float_as_uint(Bs[cn][k8 + tg]);
                b[nt][1] = __float_as_uint(Bs[cn][k8 + tg + 4]);
            }
#pragma unroll
            for (int mt = 0; mt < 4; mt++)
#pragma unroll
                for (int nt = 0; nt < 4; nt++) {
                    asm volatile(
                        "mma.sync.aligned.m16n8k8.row.col.f32.tf32.tf32.f32 "
                        "{%0,%1,%2,%3}, {%4,%5,%6,%7}, {%8,%9}, {%0,%1,%2,%3};"
                        : "+f"(acc[mt][nt][0]), "+f"(acc[mt][nt][1]),
                          "+f"(acc[mt][nt][2]), "+f"(acc[mt][nt][3])
                        : "r"(a[mt][0]), "r"(a[mt][1]), "r"(a[mt][2]), "r"(a[mt][3]),
                          "r"(b[nt][0]), "r"(b[nt][1]));
                }
        }
        __syncthreads();
    }

    float s = scl ? *scl : 1.f;
#pragma unroll
    for (int mt = 0; mt < 4; mt++) {
#pragma unroll
        for (int half = 0; half < 2; half++) {
            int gr = m0 + wm * 64 + mt * 16 + g + half * 8;
            if (gr >= M) continue;
            float bi = bias ? bias[gr] : 0.f;
#pragma unroll
            for (int nt = 0; nt < 4; nt++) {
                int gc = n0 + wn * 32 + nt * 8 + tg * 2;
#pragma unroll
                for (int j = 0; j < 2; j++) {
                    if (gc + j >= N) continue;
                    float v = s * acc[mt][nt][half * 2 + j] + bi;
                    if (addm) v += addm[(size_t)bz * sC + (size_t)gr * N + gc + j];
                    Cb[(size_t)gr * N + gc + j] = v;
                }
            }
        }
    }
}

// ---------------------------------------------------------------------------
// BN statistics: one block per channel, deterministic tree reduction.
// ---------------------------------------------------------------------------
__global__ void bn_stats_k(const float* __restrict__ y, int HW,
                           const float* __restrict__ gw,
                           const float* __restrict__ gb,
                           float* __restrict__ scale,
                           float* __restrict__ shift)
{
    const int c = blockIdx.x;
    const int t = threadIdx.x;
    float s = 0.f, s2 = 0.f;
    for (int b = 0; b < BATCH; b++) {
        const float* p = y + ((size_t)b * CH + c) * HW;
        for (int i = t; i < HW; i += 256) {
            float v = p[i];
            s += v; s2 += v * v;
        }
    }
#pragma unroll
    for (int o = 16; o; o >>= 1) {
        s  += __shfl_xor_sync(0xffffffffu, s, o);
        s2 += __shfl_xor_sync(0xffffffffu, s2, o);
    }
    __shared__ float r1[8], r2[8];
    if ((t & 31) == 0) { r1[t >> 5] = s; r2[t >> 5] = s2; }
    __syncthreads();
    if (t == 0) {
        float a = 0.f, b2 = 0.f;
        for (int i = 0; i < 8; i++) { a += r1[i]; b2 += r2[i]; }
        float n   = (float)(BATCH * HW);
        float m   = a / n;
        float var = b2 / n - m * m;
        float sc  = gw[c] * rsqrtf(var + EPSV);
        scale[c] = sc;
        shift[c] = gb[c] - m * sc;
    }
}

__global__ void bn_relu_k(float* __restrict__ y,
                          const float* __restrict__ scale,
                          const float* __restrict__ shift,
                          int HW, size_t total)
{
    size_t i = (size_t)blockIdx.x * blockDim.x + threadIdx.x;
    if (i >= total) return;
    int c = (int)((i / HW) & (CH - 1));
    float v = y[i] * scale[c] + shift[c];
    y[i] = v > 0.f ? v : 0.f;
}

// ---------------------------------------------------------------------------
// Row softmax, in place. One block per row; row staged in dynamic smem.
// ---------------------------------------------------------------------------
__global__ void softmax_k(float* __restrict__ E, int L)
{
    extern __shared__ float sm[];
    float* red = sm + L;
    const size_t row = blockIdx.x;
    float* p = E + row * (size_t)L;
    const int t = threadIdx.x;

    float mx = -3.4e38f;
    for (int i = t; i < L; i += 256) {
        float v = p[i];
        sm[i] = v;
        mx = fmaxf(mx, v);
    }
#pragma unroll
    for (int o = 16; o; o >>= 1) mx = fmaxf(mx, __shfl_xor_sync(0xffffffffu, mx, o));
    if ((t & 31) == 0) red[t >> 5] = mx;
    __syncthreads();
    if (t < 32) {
        float v = (t < 8) ? red[t] : -3.4e38f;
#pragma unroll
        for (int o = 4; o; o >>= 1) v = fmaxf(v, __shfl_xor_sync(0xffffffffu, v, o));
        if (t == 0) red[0] = v;
    }
    __syncthreads();
    mx = red[0];
    __syncthreads();

    float ss = 0.f;
    for (int i = t; i < L; i += 256) {
        float e = __expf(sm[i] - mx);
        sm[i] = e;
        ss += e;
    }
#pragma unroll
    for (int o = 16; o; o >>= 1) ss += __shfl_xor_sync(0xffffffffu, ss, o);
    if ((t & 31) == 0) red[t >> 5] = ss;
    __syncthreads();
    if (t < 32) {
        float v = (t < 8) ? red[t] : 0.f;
#pragma unroll
        for (int o = 4; o; o >>= 1) v += __shfl_xor_sync(0xffffffffu, v, o);
        if (t == 0) red[0] = v;
    }
    __syncthreads();
    float inv = 1.f / red[0];
    for (int i = t; i < L; i += 256) p[i] = sm[i] * inv;
}

// ---------------------------------------------------------------------------
// dst = add + g * bilinear_upsample(src)
// ---------------------------------------------------------------------------
__global__ void up_fma_k(const float* __restrict__ src, int SH, int SWd,
                         const float* __restrict__ add, float* __restrict__ dst,
                         int DH, int DW, const float* __restrict__ gptr,
                         size_t total)
{
    size_t i = (size_t)blockIdx.x * blockDim.x + threadIdx.x;
    if (i >= total) return;
    int ox = (int)(i % DW);
    int oy = (int)((i / DW) % DH);
    size_t bc = i / ((size_t)DW * DH);

    float ry = (float)(SH - 1) / (float)(DH - 1);
    float rx = (float)(SWd - 1) / (float)(DW - 1);
    float ys = oy * ry, xs = ox * rx;
    int y0 = (int)ys; if (y0 > SH - 1) y0 = SH - 1;
    int x0 = (int)xs; if (x0 > SWd - 1) x0 = SWd - 1;
    int y1 = min(y0 + 1, SH - 1);
    int x1 = min(x0 + 1, SWd - 1);
    float tty = ys - (float)y0, ttx = xs - (float)x0;

    const float* sp = src + bc * (size_t)(SH * SWd);
    float v00 = sp[y0 * SWd + x0], v01 = sp[y0 * SWd + x1];
    float v10 = sp[y1 * SWd + x0], v11 = sp[y1 * SWd + x1];
    float val = v00 * (1.f - tty) * (1.f - ttx) + v01 * (1.f - tty) * ttx
              + v10 * tty * (1.f - ttx) + v11 * tty * ttx;
    float g = gptr ? *gptr : 1.f;
    dst[i] = add[i] + g * val;
}

// ---------------------------------------------------------------------------
// Host side
// ---------------------------------------------------------------------------
static inline unsigned cdiv(unsigned a, unsigned b) { return (a + b - 1) / b; }

static void run_pam(const float* d, int HW,
                    const float* qw, const float* qb,
                    const float* kw, const float* kb,
                    const float* vw, const float* vb,
                    const float* g, float* pout,
                    float* qbuf, float* kbuf, float* vbuf, float* att)
{
    dim3 thr(256);
    long long dStride = (long long)CH * HW;
    long long qStride = (long long)KDIM * HW;
    long long aStride = (long long)HW * HW;
    unsigned nb = cdiv(HW, 128);

    // q = qw @ d + qb (128 x HW)
    gemm_tc<0, 0><<<dim3(nb, 1, BATCH), thr>>>(qw, d, qbuf, KDIM, HW, CH,
                                               0, dStride, qStride, qb, nullptr, nullptr);
    // k = kw @ d + kb
    gemm_tc<0, 0><<<dim3(nb, 1, BATCH), thr>>>(kw, d, kbuf, KDIM, HW, CH,
                                               0, dStride, qStride, kb, nullptr, nullptr);
    // v = vw @ d + vb (512 x HW)
    gemm_tc<0, 0><<<dim3(nb, 4, BATCH), thr>>>(vw, d, vbuf, CH, HW, CH,
                                               0, dStride, dStride, vb, nullptr, nullptr);
    // energy = q^T k (HW x HW)
    gemm_tc<1, 0><<<dim3(nb, nb, BATCH), thr>>>(qbuf, kbuf, att, HW, HW, KDIM,
                                                qStride, qStride, aStride,
                                                nullptr, nullptr, nullptr);
    // softmax over rows
    softmax_k<<<BATCH * HW, 256, (HW + 32) * sizeof(float)>>>(att, HW);
    // p = g * (v @ attn^T) + v
    gemm_tc<0, 1><<<dim3(nb, 4, BATCH), thr>>>(vbuf, att, pout, CH, HW, HW,
                                               dStride, aStride, dStride,
                                               nullptr, vbuf, g);
}

template <int IH, int IW>
static void run_conv(const float* in, const float* wgt, float* col, float* out)
{
    constexpr int OH = IH / 2, OW = IW / 2, OHOW = OH * OW;
    size_t total = (size_t)BATCH * KC * OHOW;
    im2col_k<IH, IW><<<(unsigned)((total + 255) / 256), 256>>>(in, col);
    long long colStride = (long long)KC * OHOW;
    long long outStride = (long long)CH * OHOW;
    gemm_tc<0, 0><<<dim3(cdiv(OHOW, 128), 4, BATCH), dim3(256)>>>(
        wgt, col, out, CH, OHOW, KC, 0, colStride, outStride,
        nullptr, nullptr, nullptr);
}

extern "C" void kernel_launch(void* const* d_in, const int* in_sizes, int n_in,
                              void* d_out, int out_size)
{
    (void)in_sizes; (void)n_in; (void)out_size;
    const float* x = (const float*)d_in[0];
    const float* w2   = (const float*)d_in[1];
    const float* bnw2 = (const float*)d_in[2];
    const float* bnb2 = (const float*)d_in[3];
    const float* w3   = (const float*)d_in[11];
    const float* bnw3 = (const float*)d_in[12];
    const float* bnb3 = (const float*)d_in[13];
    const float* w4   = (const float*)d_in[21];
    const float* bnw4 = (const float*)d_in[22];
    const float* bnb4 = (const float*)d_in[23];
    const float* gamma = (const float*)d_in[31];
    float* out = (float*)d_out;

    void* p;
    cudaGetSymbolAddress(&p, g_d2);    float* d2    = (float*)p;
    cudaGetSymbolAddress(&p, g_d3);    float* d3    = (float*)p;
    cudaGetSymbolAddress(&p, g_d4);    float* d4    = (float*)p;
    cudaGetSymbolAddress(&p, g_q);     float* qbuf  = (float*)p;
    cudaGetSymbolAddress(&p, g_kb);    float* kbuf  = (float*)p;
    cudaGetSymbolAddress(&p, g_v);     float* vbuf  = (float*)p;
    cudaGetSymbolAddress(&p, g_att);   float* att   = (float*)p;
    cudaGetSymbolAddress(&p, g_p2);    float* p2    = (float*)p;
    cudaGetSymbolAddress(&p, g_p3);    float* p3    = (float*)p;
    cudaGetSymbolAddress(&p, g_p4);    float* p4    = (float*)p;
    cudaGetSymbolAddress(&p, g_t3);    float* t3    = (float*)p;
    cudaGetSymbolAddress(&p, g_t2);    float* t2    = (float*)p;
    cudaGetSymbolAddress(&p, g_scale); float* scale = (float*)p;
    cudaGetSymbolAddress(&p, g_shift); float* shift = (float*)p;
    cudaGetSymbolAddress(&p, g_col);   float* col   = (float*)p;

    // ---- encoder: conv3x3 s2 (implicit GEMM) + BN(batch stats) + relu ----
    {
        run_conv<96, 96>(x, w2, col, d2);
        bn_stats_k<<<CH, 256>>>(d2, HW2, bnw2, bnb2, scale, shift);
        size_t tot = (size_t)BATCH * CH * HW2;
        bn_relu_k<<<(unsigned)((tot + 255) / 256), 256>>>(d2, scale, shift, HW2, tot);
    }
    {
        run_conv<48, 48>(d2, w3, col, d3);
        bn_stats_k<<<CH, 256>>>(d3, HW3, bnw3, bnb3, scale, shift);
        size_t tot = (size_t)BATCH * CH * HW3;
        bn_relu_k<<<(unsigned)((tot + 255) / 256), 256>>>(d3, scale, shift, HW3, tot);
    }
    {
        run_conv<24, 24>(d3, w4, col, d4);
        bn_stats_k<<<CH, 256>>>(d4, HW4, bnw4, bnb4, scale, shift);
        size_t tot = (size_t)BATCH * CH * HW4;
        bn_relu_k<<<(unsigned)((tot + 255) / 256), 256>>>(d4, scale, shift, HW4, tot);
    }

    // ---- PAM at each level ----
    run_pam(d2, HW2, (const float*)d_in[4],  (const float*)d_in[5],
                     (const float*)d_in[6],  (const float*)d_in[7],
                     (const float*)d_in[8],  (const float*)d_in[9],
                     (const float*)d_in[10], p2, qbuf, kbuf, vbuf, att);
    run_pam(d3, HW3, (const float*)d_in[14], (const float*)d_in[15],
                     (const float*)d_in[16], (const float*)d_in[17],
                     (const float*)d_in[18], (const float*)d_in[19],
                     (const float*)d_in[20], p3, qbuf, kbuf, vbuf, att);
    run_pam(d4, HW4, (const float*)d_in[24], (const float*)d_in[25],
                     (const float*)d_in[26], (const float*)d_in[27],
                     (const float*)d_in[28], (const float*)d_in[29],
                     (const float*)d_in[30], p4, qbuf, kbuf, vbuf, att);

    // ---- top-down upsample chain ----
    {
        size_t tot = (size_t)BATCH * CH * HW3;
        up_fma_k<<<(unsigned)((tot + 255) / 256), 256>>>(p4, 12, 12, p3, t3, 24, 24,
                                                         nullptr, tot);
    }
    {
        size_t tot = (size_t)BATCH * CH * HW2;
        up_fma_k<<<(unsigned)((tot + 255) / 256), 256>>>(t3, 24, 24, p2, t2, 48, 48,
                                                         nullptr, tot);
    }
    {
        size_t tot = (size_t)BATCH * CH * 96 * 96;
        up_fma_k<<<(unsigned)((tot + 255) / 256), 256>>>(t2, 48, 48, x, out, 96, 96,
                                                         gamma, tot);
    }
}

// round 4
// speedup vs baseline: 3.5693x; 1.5801x over previous
#include <cuda_runtime.h>
#include <cstddef>
#include <cstdint>
#include <math.h>

// ---------------------------------------------------------------------------
// Problem constants
// ---------------------------------------------------------------------------
#define BATCH 8
#define CH    512
#define KDIM  128
#define EPSV  1e-5f

#define HW2 2304           // 48*48
#define HW3 576            // 24*24
#define HW4 144            // 12*12
#define KC  4608           // 512*9 im2col K

// ---------------------------------------------------------------------------
// Scratch (allocation-free: __device__ globals)
// ---------------------------------------------------------------------------
__device__ float g_d2[BATCH * CH * HW2];
__device__ float g_d3[BATCH * CH * HW3];
__device__ float g_d4[BATCH * CH * HW4];
__device__ float g_q [BATCH * KDIM * HW2];
__device__ float g_kb[BATCH * KDIM * HW2];
__device__ float g_v [BATCH * CH * HW2];
__device__ float g_att[(size_t)BATCH * HW2 * HW2];   // 170 MB energy/attn
__device__ float g_p2[BATCH * CH * HW2];
__device__ float g_p3[BATCH * CH * HW3];
__device__ float g_p4[BATCH * CH * HW4];
__device__ float g_t3[BATCH * CH * HW3];
__device__ float g_t2[BATCH * CH * HW2];
__device__ float g_scale[CH];
__device__ float g_shift[CH];
__device__ float g_col[(size_t)BATCH * KC * HW2];    // 340 MB im2col scratch

// ---------------------------------------------------------------------------
// cp.async helpers. pred=false -> zero-fill (src-size 0); src clamped to a
// always-valid address so no OOB pointer is ever presented to the LSU.
// ---------------------------------------------------------------------------
__device__ __forceinline__ void cp16(uint32_t dst, const float* src,
                                     const float* safe, bool pred)
{
    const float* sp = pred ? src : safe;
    asm volatile("cp.async.cg.shared.global [%0], [%1], 16, %2;"
                 :: "r"(dst), "l"(sp), "r"(pred ? 16 : 0));
}
__device__ __forceinline__ void cp_commit()
{
    asm volatile("cp.async.commit_group;");
}
__device__ __forceinline__ void cp_wait1()
{
    asm volatile("cp.async.wait_group 1;");
}

// ---------------------------------------------------------------------------
// im2col for 3x3 stride-2 pad-1 conv. Per-batch layout:
//   col[b][k = ic*9+kh*3+kw][pix = oh*OW+ow]
// ---------------------------------------------------------------------------
template <int IH, int IW>
__global__ void im2col_k(const float* __restrict__ x, float* __restrict__ col)
{
    constexpr int OH = IH / 2, OW = IW / 2, OHOW = OH * OW;
    size_t i = (size_t)blockIdx.x * blockDim.x + threadIdx.x;
    size_t total = (size_t)BATCH * KC * OHOW;
    if (i >= total) return;
    int pix = (int)(i % OHOW);
    size_t r = i / OHOW;
    int k = (int)(r % KC);
    int b = (int)(r / KC);
    int ic = k / 9;
    int kk = k - ic * 9;
    int kh = kk / 3, kw = kk - kh * 3;
    int oh = pix / OW, ow = pix - oh * OW;
    int ih = 2 * oh - 1 + kh;
    int iw = 2 * ow - 1 + kw;
    float v = 0.f;
    if (ih >= 0 && ih < IH && iw >= 0 && iw < IW)
        v = x[(((size_t)b * CH + ic) * IH + ih) * IW + iw];
    col[i] = v;
}

// ---------------------------------------------------------------------------
// Tensor-core tf32 GEMM, cp.async double-buffered.
// C(M,N) = op(A)*op(B); TA=1: A stored (K,M); TB=1: B stored (N,K).
// Block 128x128x32, 8 warps (2x4), warp tile 64x32, m16n8k8 tf32 mma.
// smem per stage: A-> TA=0: [m][k] ld36 ; TA=1: [k][m] ld132
//                 B-> TB=1: [n][k] ld36 ; TB=0: [k][n] ld132
// All strides are 16B multiples -> straight cp.async row copies, no transpose.
// Epilogue: C = s*acc + bias[row] (+ addm). M,N,K multiples of 16.
// ---------------------------------------------------------------------------
#define STG_F 4608                  // floats per stage per operand
#define GEMM_SMEM (4 * STG_F * 4)   // 73728 bytes

template <int TA, int TB>
__global__ __launch_bounds__(256)
void gemm_tc(const float* __restrict__ A, const float* __restrict__ B,
             float* __restrict__ C, int M, int N, int K,
             long long sA, long long sB, long long sC,
             const float* __restrict__ bias,
             const float* __restrict__ addm,
             const float* __restrict__ scl)
{
    extern __shared__ float smp[];

    const int bz = blockIdx.z;
    const float* Ab = A + (size_t)bz * sA;
    const float* Bb = B + (size_t)bz * sB;
    float* Cb = C + (size_t)bz * sC;

    const int n0 = blockIdx.x * 128, m0 = blockIdx.y * 128;
    const int t = threadIdx.x, lane = t & 31, w = t >> 5;
    const int wm = w & 1, wn = w >> 1;
    const int g = lane >> 2, tg = lane & 3;

    const int ldA = TA ? M : K;
    const int ldB = TB ? K : N;

    const uint32_t smem_base = (uint32_t)__cvta_generic_to_shared(smp);

    // stage loaders ---------------------------------------------------------
    auto loadA = [&](int s, int k0) {
        uint32_t base = smem_base + (uint32_t)(s * STG_F) * 4u;
#pragma unroll
        for (int i = 0; i < 4; i++) {
            int u = t + i * 256;
            if (!TA) {
                int m = u >> 3, ku = (u & 7) << 2;
                bool p = (m0 + m < M) && (k0 + ku < K);
                cp16(base + (uint32_t)(m * 36 + ku) * 4u,
                     Ab + (size_t)(m0 + m) * ldA + k0 + ku, Ab, p);
            } else {
                int k = u >> 5, mu = (u & 31) << 2;
                bool p = (k0 + k < K) && (m0 + mu < M);
                cp16(base + (uint32_t)(k * 132 + mu) * 4u,
                     Ab + (size_t)(k0 + k) * ldA + m0 + mu, Ab, p);
            }
        }
    };
    auto loadB = [&](int s, int k0) {
        uint32_t base = smem_base + (uint32_t)((2 + s) * STG_F) * 4u;
#pragma unroll
        for (int i = 0; i < 4; i++) {
            int u = t + i * 256;
            if (TB) {
                int n = u >> 3, ku = (u & 7) << 2;
                bool p = (n0 + n < N) && (k0 + ku < K);
                cp16(base + (uint32_t)(n * 36 + ku) * 4u,
                     Bb + (size_t)(n0 + n) * ldB + k0 + ku, Bb, p);
            } else {
                int k = u >> 5, nu = (u & 31) << 2;
                bool p = (k0 + k < K) && (n0 + nu < N);
                cp16(base + (uint32_t)(k * 132 + nu) * 4u,
                     Bb + (size_t)(k0 + k) * ldB + n0 + nu, Bb, p);
            }
        }
    };

    float acc[4][4][4];
#pragma unroll
    for (int a = 0; a < 4; a++)
#pragma unroll
        for (int b = 0; b < 4; b++)
#pragma unroll
            for (int c = 0; c < 4; c++) acc[a][b][c] = 0.f;

    const int nk = (K + 31) >> 5;
    loadA(0, 0); loadB(0, 0); cp_commit();

    for (int kt = 0; kt < nk; kt++) {
        if (kt + 1 < nk) { loadA((kt + 1) & 1, (kt + 1) * 32);
                           loadB((kt + 1) & 1, (kt + 1) * 32); }
        cp_commit();
        cp_wait1();
        __syncthreads();

        const float* As = smp + (kt & 1) * STG_F;
        const float* Bs = smp + (2 + (kt & 1)) * STG_F;

#pragma unroll
        for (int k8 = 0; k8 < 32; k8 += 8) {
            unsigned a[4][4], b[4][2];
#pragma unroll
            for (int mt = 0; mt < 4; mt++) {
                int r = wm * 64 + mt * 16 + g;
                if (!TA) {
                    a[mt][0] = __float_as_uint(As[(r)     * 36 + k8 + tg]);
                    a[mt][1] = __float_as_uint(As[(r + 8) * 36 + k8 + tg]);
                    a[mt][2] = __float_as_uint(As[(r)     * 36 + k8 + tg + 4]);
                    a[mt][3] = __float_as_uint(As[(r + 8) * 36 + k8 + tg + 4]);
                } else {
                    a[mt][0] = __float_as_uint(As[(k8 + tg)     * 132 + r]);
                    a[mt][1] = __float_as_uint(As[(k8 + tg)     * 132 + r + 8]);
                    a[mt][2] = __float_as_uint(As[(k8 + tg + 4) * 132 + r]);
                    a[mt][3] = __float_as_uint(As[(k8 + tg + 4) * 132 + r + 8]);
                }
            }
#pragma unroll
            for (int nt = 0; nt < 4; nt++) {
                int cn = wn * 32 + nt * 8 + g;
                if (TB) {
                    b[nt][0] = __float_as_uint(Bs[cn * 36 + k8 + tg]);
                    b[nt][1] = __float_as_uint(Bs[cn * 36 + k8 + tg + 4]);
                } else {
                    b[nt][0] = __float_as_uint(Bs[(k8 + tg)     * 132 + cn]);
                    b[nt][1] = __float_as_uint(Bs[(k8 + tg + 4) * 132 + cn]);
                }
            }
#pragma unroll
            for (int mt = 0; mt < 4; mt++)
#pragma unroll
                for (int nt = 0; nt < 4; nt++) {
                    asm volatile(
                        "mma.sync.aligned.m16n8k8.row.col.f32.tf32.tf32.f32 "
                        "{%0,%1,%2,%3}, {%4,%5,%6,%7}, {%8,%9}, {%0,%1,%2,%3};"
                        : "+f"(acc[mt][nt][0]), "+f"(acc[mt][nt][1]),
                          "+f"(acc[mt][nt][2]), "+f"(acc[mt][nt][3])
                        : "r"(a[mt][0]), "r"(a[mt][1]), "r"(a[mt][2]), "r"(a[mt][3]),
                          "r"(b[nt][0]), "r"(b[nt][1]));
                }
        }
        __syncthreads();
    }

    float s = scl ? *scl : 1.f;
#pragma unroll
    for (int mt = 0; mt < 4; mt++) {
#pragma unroll
        for (int half = 0; half < 2; half++) {
            int gr = m0 + wm * 64 + mt * 16 + g + half * 8;
            if (gr >= M) continue;
            float bi = bias ? bias[gr] : 0.f;
#pragma unroll
            for (int nt = 0; nt < 4; nt++) {
                int gc = n0 + wn * 32 + nt * 8 + tg * 2;
#pragma unroll
                for (int j = 0; j < 2; j++) {
                    if (gc + j >= N) continue;
                    float v = s * acc[mt][nt][half * 2 + j] + bi;
                    if (addm) v += addm[(size_t)bz * sC + (size_t)gr * N + gc + j];
                    Cb[(size_t)gr * N + gc + j] = v;
                }
            }
        }
    }
}

// ---------------------------------------------------------------------------
// BN statistics: one block per channel, deterministic tree reduction.
// ---------------------------------------------------------------------------
__global__ void bn_stats_k(const float* __restrict__ y, int HW,
                           const float* __restrict__ gw,
                           const float* __restrict__ gb,
                           float* __restrict__ scale,
                           float* __restrict__ shift)
{
    const int c = blockIdx.x;
    const int t = threadIdx.x;
    float s = 0.f, s2 = 0.f;
    for (int b = 0; b < BATCH; b++) {
        const float* p = y + ((size_t)b * CH + c) * HW;
        for (int i = t; i < HW; i += 256) {
            float v = p[i];
            s += v; s2 += v * v;
        }
    }
#pragma unroll
    for (int o = 16; o; o >>= 1) {
        s  += __shfl_xor_sync(0xffffffffu, s, o);
        s2 += __shfl_xor_sync(0xffffffffu, s2, o);
    }
    __shared__ float r1[8], r2[8];
    if ((t & 31) == 0) { r1[t >> 5] = s; r2[t >> 5] = s2; }
    __syncthreads();
    if (t == 0) {
        float a = 0.f, b2 = 0.f;
        for (int i = 0; i < 8; i++) { a += r1[i]; b2 += r2[i]; }
        float n   = (float)(BATCH * HW);
        float m   = a / n;
        float var = b2 / n - m * m;
        float sc  = gw[c] * rsqrtf(var + EPSV);
        scale[c] = sc;
        shift[c] = gb[c] - m * sc;
    }
}

__global__ void bn_relu_k(float* __restrict__ y,
                          const float* __restrict__ scale,
                          const float* __restrict__ shift,
                          int HW, size_t total)
{
    size_t i = (size_t)blockIdx.x * blockDim.x + threadIdx.x;
    if (i >= total) return;
    int c = (int)((i / HW) & (CH - 1));
    float v = y[i] * scale[c] + shift[c];
    y[i] = v > 0.f ? v : 0.f;
}

// ---------------------------------------------------------------------------
// Row softmax, in place. One block per row; row staged in dynamic smem.
// ---------------------------------------------------------------------------
__global__ void softmax_k(float* __restrict__ E, int L)
{
    extern __shared__ float sm[];
    float* red = sm + L;
    const size_t row = blockIdx.x;
    float* p = E + row * (size_t)L;
    const int t = threadIdx.x;

    float mx = -3.4e38f;
    for (int i = t; i < L; i += 256) {
        float v = p[i];
        sm[i] = v;
        mx = fmaxf(mx, v);
    }
#pragma unroll
    for (int o = 16; o; o >>= 1) mx = fmaxf(mx, __shfl_xor_sync(0xffffffffu, mx, o));
    if ((t & 31) == 0) red[t >> 5] = mx;
    __syncthreads();
    if (t < 32) {
        float v = (t < 8) ? red[t] : -3.4e38f;
#pragma unroll
        for (int o = 4; o; o >>= 1) v = fmaxf(v, __shfl_xor_sync(0xffffffffu, v, o));
        if (t == 0) red[0] = v;
    }
    __syncthreads();
    mx = red[0];
    __syncthreads();

    float ss = 0.f;
    for (int i = t; i < L; i += 256) {
        float e = __expf(sm[i] - mx);
        sm[i] = e;
        ss += e;
    }
#pragma unroll
    for (int o = 16; o; o >>= 1) ss += __shfl_xor_sync(0xffffffffu, ss, o);
    if ((t & 31) == 0) red[t >> 5] = ss;
    __syncthreads();
    if (t < 32) {
        float v = (t < 8) ? red[t] : 0.f;
#pragma unroll
        for (int o = 4; o; o >>= 1) v += __shfl_xor_sync(0xffffffffu, v, o);
        if (t == 0) red[0] = v;
    }
    __syncthreads();
    float inv = 1.f / red[0];
    for (int i = t; i < L; i += 256) p[i] = sm[i] * inv;
}

// ---------------------------------------------------------------------------
// dst = add + g * bilinear_upsample(src)
// ---------------------------------------------------------------------------
__global__ void up_fma_k(const float* __restrict__ src, int SH, int SWd,
                         const float* __restrict__ add, float* __restrict__ dst,
                         int DH, int DW, const float* __restrict__ gptr,
                         size_t total)
{
    size_t i = (size_t)blockIdx.x * blockDim.x + threadIdx.x;
    if (i >= total) return;
    int ox = (int)(i % DW);
    int oy = (int)((i / DW) % DH);
    size_t bc = i / ((size_t)DW * DH);

    float ry = (float)(SH - 1) / (float)(DH - 1);
    float rx = (float)(SWd - 1) / (float)(DW - 1);
    float ys = oy * ry, xs = ox * rx;
    int y0 = (int)ys; if (y0 > SH - 1) y0 = SH - 1;
    int x0 = (int)xs; if (x0 > SWd - 1) x0 = SWd - 1;
    int y1 = min(y0 + 1, SH - 1);
    int x1 = min(x0 + 1, SWd - 1);
    float tty = ys - (float)y0, ttx = xs - (float)x0;

    const float* sp = src + bc * (size_t)(SH * SWd);
    float v00 = sp[y0 * SWd + x0], v01 = sp[y0 * SWd + x1];
    float v10 = sp[y1 * SWd + x0], v11 = sp[y1 * SWd + x1];
    float val = v00 * (1.f - tty) * (1.f - ttx) + v01 * (1.f - tty) * ttx
              + v10 * tty * (1.f - ttx) + v11 * tty * ttx;
    float g = gptr ? *gptr : 1.f;
    dst[i] = add[i] + g * val;
}

// ---------------------------------------------------------------------------
// Host side
// ---------------------------------------------------------------------------
static inline unsigned cdiv(unsigned a, unsigned b) { return (a + b - 1) / b; }

static void run_pam(const float* d, int HW,
                    const float* qw, const float* qb,
                    const float* kw, const float* kb,
                    const float* vw, const float* vb,
                    const float* g, float* pout,
                    float* qbuf, float* kbuf, float* vbuf, float* att)
{
    dim3 thr(256);
    long long dStride = (long long)CH * HW;
    long long qStride = (long long)KDIM * HW;
    long long aStride = (long long)HW * HW;
    unsigned nb = cdiv(HW, 128);

    gemm_tc<0, 0><<<dim3(nb, 1, BATCH), thr, GEMM_SMEM>>>(qw, d, qbuf, KDIM, HW, CH,
                                               0, dStride, qStride, qb, nullptr, nullptr);
    gemm_tc<0, 0><<<dim3(nb, 1, BATCH), thr, GEMM_SMEM>>>(kw, d, kbuf, KDIM, HW, CH,
                                               0, dStride, qStride, kb, nullptr, nullptr);
    gemm_tc<0, 0><<<dim3(nb, 4, BATCH), thr, GEMM_SMEM>>>(vw, d, vbuf, CH, HW, CH,
                                               0, dStride, dStride, vb, nullptr, nullptr);
    gemm_tc<1, 0><<<dim3(nb, nb, BATCH), thr, GEMM_SMEM>>>(qbuf, kbuf, att, HW, HW, KDIM,
                                                qStride, qStride, aStride,
                                                nullptr, nullptr, nullptr);
    softmax_k<<<BATCH * HW, 256, (HW + 32) * sizeof(float)>>>(att, HW);
    gemm_tc<0, 1><<<dim3(nb, 4, BATCH), thr, GEMM_SMEM>>>(vbuf, att, pout, CH, HW, HW,
                                               dStride, aStride, dStride,
                                               nullptr, vbuf, g);
}

template <int IH, int IW>
static void run_conv(const float* in, const float* wgt, float* col, float* out)
{
    constexpr int OH = IH / 2, OW = IW / 2, OHOW = OH * OW;
    size_t total = (size_t)BATCH * KC * OHOW;
    im2col_k<IH, IW><<<(unsigned)((total + 255) / 256), 256>>>(in, col);
    long long colStride = (long long)KC * OHOW;
    long long outStride = (long long)CH * OHOW;
    gemm_tc<0, 0><<<dim3(cdiv(OHOW, 128), 4, BATCH), dim3(256), GEMM_SMEM>>>(
        wgt, col, out, CH, OHOW, KC, 0, colStride, outStride,
        nullptr, nullptr, nullptr);
}

extern "C" void kernel_launch(void* const* d_in, const int* in_sizes, int n_in,
                              void* d_out, int out_size)
{
    (void)in_sizes; (void)n_in; (void)out_size;

    cudaFuncSetAttribute(gemm_tc<0, 0>, cudaFuncAttributeMaxDynamicSharedMemorySize, GEMM_SMEM);
    cudaFuncSetAttribute(gemm_tc<1, 0>, cudaFuncAttributeMaxDynamicSharedMemorySize, GEMM_SMEM);
    cudaFuncSetAttribute(gemm_tc<0, 1>, cudaFuncAttributeMaxDynamicSharedMemorySize, GEMM_SMEM);

    const float* x = (const float*)d_in[0];
    const float* w2   = (const float*)d_in[1];
    const float* bnw2 = (const float*)d_in[2];
    const float* bnb2 = (const float*)d_in[3];
    const float* w3   = (const float*)d_in[11];
    const float* bnw3 = (const float*)d_in[12];
    const float* bnb3 = (const float*)d_in[13];
    const float* w4   = (const float*)d_in[21];
    const float* bnw4 = (const float*)d_in[22];
    const float* bnb4 = (const float*)d_in[23];
    const float* gamma = (const float*)d_in[31];
    float* out = (float*)d_out;

    void* p;
    cudaGetSymbolAddress(&p, g_d2);    float* d2    = (float*)p;
    cudaGetSymbolAddress(&p, g_d3);    float* d3    = (float*)p;
    cudaGetSymbolAddress(&p, g_d4);    float* d4    = (float*)p;
    cudaGetSymbolAddress(&p, g_q);     float* qbuf  = (float*)p;
    cudaGetSymbolAddress(&p, g_kb);    float* kbuf  = (float*)p;
    cudaGetSymbolAddress(&p, g_v);     float* vbuf  = (float*)p;
    cudaGetSymbolAddress(&p, g_att);   float* att   = (float*)p;
    cudaGetSymbolAddress(&p, g_p2);    float* p2    = (float*)p;
    cudaGetSymbolAddress(&p, g_p3);    float* p3    = (float*)p;
    cudaGetSymbolAddress(&p, g_p4);    float* p4    = (float*)p;
    cudaGetSymbolAddress(&p, g_t3);    float* t3    = (float*)p;
    cudaGetSymbolAddress(&p, g_t2);    float* t2    = (float*)p;
    cudaGetSymbolAddress(&p, g_scale); float* scale = (float*)p;
    cudaGetSymbolAddress(&p, g_shift); float* shift = (float*)p;
    cudaGetSymbolAddress(&p, g_col);   float* col   = (float*)p;

    // ---- encoder: conv3x3 s2 (implicit GEMM) + BN(batch stats) + relu ----
    {
        run_conv<96, 96>(x, w2, col, d2);
        bn_stats_k<<<CH, 256>>>(d2, HW2, bnw2, bnb2, scale, shift);
        size_t tot = (size_t)BATCH * CH * HW2;
        bn_relu_k<<<(unsigned)((tot + 255) / 256), 256>>>(d2, scale, shift, HW2, tot);
    }
    {
        run_conv<48, 48>(d2, w3, col, d3);
        bn_stats_k<<<CH, 256>>>(d3, HW3, bnw3, bnb3, scale, shift);
        size_t tot = (size_t)BATCH * CH * HW3;
        bn_relu_k<<<(unsigned)((tot + 255) / 256), 256>>>(d3, scale, shift, HW3, tot);
    }
    {
        run_conv<24, 24>(d3, w4, col, d4);
        bn_stats_k<<<CH, 256>>>(d4, HW4, bnw4, bnb4, scale, shift);
        size_t tot = (size_t)BATCH * CH * HW4;
        bn_relu_k<<<(unsigned)((tot + 255) / 256), 256>>>(d4, scale, shift, HW4, tot);
    }

    // ---- PAM at each level ----
    run_pam(d2, HW2, (const float*)d_in[4],  (const float*)d_in[5],
                     (const float*)d_in[6],  (const float*)d_in[7],
                     (const float*)d_in[8],  (const float*)d_in[9],
                     (const float*)d_in[10], p2, qbuf, kbuf, vbuf, att);
    run_pam(d3, HW3, (const float*)d_in[14], (const float*)d_in[15],
                     (const float*)d_in[16], (const float*)d_in[17],
                     (const float*)d_in[18], (const float*)d_in[19],
                     (const float*)d_in[20], p3, qbuf, kbuf, vbuf, att);
    run_pam(d4, HW4, (const float*)d_in[24], (const float*)d_in[25],
                     (const float*)d_in[26], (const float*)d_in[27],
                     (const float*)d_in[28], (const float*)d_in[29],
                     (const float*)d_in[30], p4, qbuf, kbuf, vbuf, att);

    // ---- top-down upsample chain ----
    {
        size_t tot = (size_t)BATCH * CH * HW3;
        up_fma_k<<<(unsigned)((tot + 255) / 256), 256>>>(p4, 12, 12, p3, t3, 24, 24,
                                                         nullptr, tot);
    }
    {
        size_t tot = (size_t)BATCH * CH * HW2;
        up_fma_k<<<(unsigned)((tot + 255) / 256), 256>>>(t3, 24, 24, p2, t2, 48, 48,
                                                         nullptr, tot);
    }
    {
        size_t tot = (size_t)BATCH * CH * 96 * 96;
        up_fma_k<<<(unsigned)((tot + 255) / 256), 256>>>(t2, 48, 48, x, out, 96, 96,
                                                         gamma, tot);
    }
}

// round 5
// speedup vs baseline: 5.5644x; 1.5590x over previous
#include <cuda_runtime.h>
#include <cuda_fp16.h>
#include <cstddef>
#include <cstdint>
#include <math.h>

// ---------------------------------------------------------------------------
// Problem constants
// ---------------------------------------------------------------------------
#define BATCH 8
#define CH    512
#define KDIM  128
#define EPSV  1e-5f

#define HW1 9216           // 96*96
#define HW2 2304           // 48*48
#define HW3 576            // 24*24
#define HW4 144            // 12*12
#define KC  4608           // 512*9 im2col K

// ---------------------------------------------------------------------------
// Scratch (allocation-free: __device__ globals)
// ---------------------------------------------------------------------------
__device__ float g_d2[BATCH * CH * HW2];
__device__ float g_d3[BATCH * CH * HW3];
__device__ float g_d4[BATCH * CH * HW4];
__device__ float g_att[(size_t)BATCH * HW2 * HW2];   // 170 MB energy (fp32)
__device__ float g_p2[BATCH * CH * HW2];
__device__ float g_p3[BATCH * CH * HW3];
__device__ float g_p4[BATCH * CH * HW4];
__device__ float g_t3[BATCH * CH * HW3];
__device__ float g_t2[BATCH * CH * HW2];
__device__ float g_scale[CH];
__device__ float g_shift[CH];

__device__ __half g_xh [(size_t)BATCH * HW1 * CH];   // x transposed fp16 [pix][c]
__device__ __half g_colh[(size_t)BATCH * HW2 * KC];  // im2col fp16 [pix][k]
__device__ __half g_d2h[(size_t)BATCH * HW2 * CH];   // bn+relu+T fp16
__device__ __half g_d3h[(size_t)BATCH * HW3 * CH];
__device__ __half g_d4h[(size_t)BATCH * HW4 * CH];
__device__ __half g_qt [(size_t)BATCH * HW2 * KDIM]; // q^T fp16 [pix][kd]
__device__ __half g_kt [(size_t)BATCH * HW2 * KDIM];
__device__ __half g_vh [(size_t)BATCH * CH * HW2];   // v fp16 [c][pix]
__device__ __half g_ph [(size_t)BATCH * HW2 * HW2];  // softmax probs fp16
__device__ __half g_wh [CH * KC];                    // conv weight fp16 [oc][kk][ic]
__device__ __half g_qwh[KDIM * CH];
__device__ __half g_kwh[KDIM * CH];
__device__ __half g_vwh[CH * CH];

// ---------------------------------------------------------------------------
// Conversion kernels
// ---------------------------------------------------------------------------
__global__ void f2h_k(const float* __restrict__ in, __half* __restrict__ out, int n)
{
    int i = blockIdx.x * blockDim.x + threadIdx.x;
    if (i < n) out[i] = __float2half(in[i]);
}

// conv weight (oc, ic, kh, kw) -> fp16 [oc][kk][ic]
__global__ void conv_w2h_k(const float* __restrict__ w, __half* __restrict__ out)
{
    int i = blockIdx.x * blockDim.x + threadIdx.x;
    if (i >= CH * KC) return;
    int ic = i & 511;
    int kk = (i >> 9) % 9;
    int oc = i / KC;
    out[i] = __float2half(w[((size_t)oc * CH + ic) * 9 + kk]);
}

// ---------------------------------------------------------------------------
// Transpose (+optional BN+ReLU): fp32 [b][c][pix] -> fp16 [b][pix][c]
// grid (cdiv(HW,32), 16, B), block (32, 8)
// ---------------------------------------------------------------------------
template <int BN_ON>
__global__ void bnT_k(const float* __restrict__ y,
                      const float* __restrict__ scale,
                      const float* __restrict__ shift,
                      __half* __restrict__ out, int HW)
{
    __shared__ float tile[32][33];
    int b = blockIdx.z;
    int p0 = blockIdx.x * 32, c0 = blockIdx.y * 32;
    int tx = threadIdx.x, ty = threadIdx.y;
#pragma unroll
    for (int j = 0; j < 4; j++) {
        int c = c0 + ty + j * 8;
        int p = p0 + tx;
        float v = 0.f;
        if (p < HW) v = y[((size_t)b * CH + c) * HW + p];
        if (BN_ON) { v = v * scale[c] + shift[c]; v = v > 0.f ? v : 0.f; }
        tile[ty + j * 8][tx] = v;
    }
    __syncthreads();
#pragma unroll
    for (int j = 0; j < 4; j++) {
        int p = p0 + ty + j * 8;
        int c = c0 + tx;
        if (p < HW) out[((size_t)b * HW + p) * CH + c] = __float2half(tile[tx][ty + j * 8]);
    }
}

// ---------------------------------------------------------------------------
// im2col fp16: src [b][pix_in][c] -> col [b][pix_out][kk*512+ic]
// one thread = 8 consecutive ic (16B vector both sides)
// ---------------------------------------------------------------------------
template <int IH, int IW>
__global__ void im2col_h_k(const __half* __restrict__ src, __half* __restrict__ col)
{
    constexpr int OH = IH / 2, OW = IW / 2, OHOW = OH * OW;
    size_t i = (size_t)blockIdx.x * blockDim.x + threadIdx.x;
    size_t total = (size_t)BATCH * OHOW * 9 * 64;
    if (i >= total) return;
    int ic8 = (int)(i & 63) << 3;
    int kk  = (int)((i >> 6) % 9);
    size_t r = i / 576;
    int pix = (int)(r % OHOW);
    int b   = (int)(r / OHOW);
    int kh = kk / 3, kw = kk - kh * 3;
    int oh = pix / OW, ow = pix - oh * OW;
    int ih = 2 * oh - 1 + kh, iw = 2 * ow - 1 + kw;
    float4 v;
    if (ih >= 0 && ih < IH && iw >= 0 && iw < IW) {
        v = *(const float4*)(src + ((size_t)b * IH * IW + ih * IW + iw) * CH + ic8);
    } else {
        v = make_float4(0.f, 0.f, 0.f, 0.f);
    }
    *(float4*)(col + ((size_t)b * OHOW + pix) * KC + kk * CH + ic8) = v;
}

// ---------------------------------------------------------------------------
// fp16 tensor-core GEMM, cp.async double-buffered.
// C(M,N) = A(M,K)[m][k] * B(N,K)[n][k]^T ; both operands k-contiguous fp16.
// Block 128x128x32, 8 warps (2x4), warp tile 64x32, m16n8k16 f16->f32 mma.
// smem rows padded to 40 halves (80B = 5x16B): cp.async aligned + LDS
// conflict-free.  OUT=0: fp32 C; OUT=1: fp16 C.
// Epilogue: C = s*acc + biasM[row] + biasN[col] + addm (all optional).
// ---------------------------------------------------------------------------
template <int OUT>
__global__ __launch_bounds__(256)
void gemm_h(const __half* __restrict__ A, const __half* __restrict__ B,
            float* __restrict__ Cf, __half* __restrict__ Ch,
            int M, int N, int K, int lda, int ldb,
            long long sA, long long sB, long long sC,
            const float* __restrict__ biasM, const float* __restrict__ biasN,
            const __half* __restrict__ addm, const float* __restrict__ scl)
{
    __shared__ __align__(16) __half smm[4 * 128 * 40];   // 40 KB

    const int bz = blockIdx.z;
    const __half* Ab = A + (size_t)bz * sA;
    const __half* Bb = B + (size_t)bz * sB;

    const int n0 = blockIdx.x * 128, m0 = blockIdx.y * 128;
    const int t = threadIdx.x, lane = t & 31, w = t >> 5;
    const int wm = w & 1, wn = w >> 1;
    const int g = lane >> 2, tg = lane & 3;

    const uint32_t smem_base = (uint32_t)__cvta_generic_to_shared(smm);

    auto loadOp = [&](const __half* src, int ld, int r0, int lim,
                      uint32_t sb, int k0) {
#pragma unroll
        for (int i = 0; i < 2; i++) {
            int u = t + i * 256;
            int row = u >> 2, ch = (u & 3) << 3;   // halves: 0,8,16,24
            bool p = (r0 + row < lim) && (k0 + ch < K);
            const __half* sp = p ? src + (size_t)(r0 + row) * ld + k0 + ch : src;
            asm volatile("cp.async.cg.shared.global [%0], [%1], 16, %2;"
                         :: "r"(sb + (uint32_t)(row * 40 + ch) * 2u),
                            "l"(sp), "r"(p ? 16 : 0));
        }
    };

    float acc[4][4][4];
#pragma unroll
    for (int a = 0; a < 4; a++)
#pragma unroll
        for (int b = 0; b < 4; b++)
#pragma unroll
            for (int c = 0; c < 4; c++) acc[a][b][c] = 0.f;

    const uint32_t stA0 = smem_base;
    const uint32_t stA1 = smem_base + 128 * 40 * 2;
    const uint32_t stB0 = smem_base + 2 * 128 * 40 * 2;
    const uint32_t stB1 = smem_base + 3 * 128 * 40 * 2;

    const int nk = (K + 31) >> 5;
    loadOp(Ab, lda, m0, M, stA0, 0);
    loadOp(Bb, ldb, n0, N, stB0, 0);
    asm volatile("cp.async.commit_group;");

    for (int kt = 0; kt < nk; kt++) {
        if (kt + 1 < nk) {
            loadOp(Ab, lda, m0, M, ((kt + 1) & 1) ? stA1 : stA0, (kt + 1) * 32);
            loadOp(Bb, ldb, n0, N, ((kt + 1) & 1) ? stB1 : stB0, (kt + 1) * 32);
        }
        asm volatile("cp.async.commit_group;");
        asm volatile("cp.async.wait_group 1;");
        __syncthreads();

        const __half* As = smm + (kt & 1) * 128 * 40;
        const __half* Bs = smm + (2 + (kt & 1)) * 128 * 40;

#pragma unroll
        for (int s16 = 0; s16 < 32; s16 += 16) {
            uint32_t a[4][4], b[4][2];
#pragma unroll
            for (int mt = 0; mt < 4; mt++) {
                int r = wm * 64 + mt * 16 + g;
                a[mt][0] = *(const uint32_t*)&As[r * 40 + s16 + 2 * tg];
                a[mt][1] = *(const uint32_t*)&As[(r + 8) * 40 + s16 + 2 * tg];
                a[mt][2] = *(const uint32_t*)&As[r * 40 + s16 + 2 * tg + 8];
                a[mt][3] = *(const uint32_t*)&As[(r + 8) * 40 + s16 + 2 * tg + 8];
            }
#pragma unroll
            for (int nt = 0; nt < 4; nt++) {
                int cn = wn * 32 + nt * 8 + g;
                b[nt][0] = *(const uint32_t*)&Bs[cn * 40 + s16 + 2 * tg];
                b[nt][1] = *(const uint32_t*)&Bs[cn * 40 + s16 + 2 * tg + 8];
            }
#pragma unroll
            for (int mt = 0; mt < 4; mt++)
#pragma unroll
                for (int nt = 0; nt < 4; nt++) {
                    asm volatile(
                        "mma.sync.aligned.m16n8k16.row.col.f32.f16.f16.f32 "
                        "{%0,%1,%2,%3}, {%4,%5,%6,%7}, {%8,%9}, {%0,%1,%2,%3};"
                        : "+f"(acc[mt][nt][0]), "+f"(acc[mt][nt][1]),
                          "+f"(acc[mt][nt][2]), "+f"(acc[mt][nt][3])
                        : "r"(a[mt][0]), "r"(a[mt][1]), "r"(a[mt][2]), "r"(a[mt][3]),
                          "r"(b[nt][0]), "r"(b[nt][1]));
                }
        }
        __syncthreads();
    }

    float s = scl ? *scl : 1.f;
#pragma unroll
    for (int mt = 0; mt < 4; mt++) {
#pragma unroll
        for (int half = 0; half < 2; half++) {
            int gr = m0 + wm * 64 + mt * 16 + g + half * 8;
            if (gr >= M) continue;
            float bm = biasM ? biasM[gr] : 0.f;
#pragma unroll
            for (int nt = 0; nt < 4; nt++) {
                int gc = n0 + wn * 32 + nt * 8 + tg * 2;
#pragma unroll
                for (int j = 0; j < 2; j++) {
                    if (gc + j >= N) continue;
                    float v = s * acc[mt][nt][half * 2 + j] + bm;
                    if (biasN) v += biasN[gc + j];
                    size_t idx = (size_t)bz * sC + (size_t)gr * N + gc + j;
                    if (addm) v += __half2float(addm[idx]);
                    if (OUT == 0) Cf[idx] = v;
                    else          Ch[idx] = __float2half(v);
                }
            }
        }
    }
}

// ---------------------------------------------------------------------------
// BN statistics: one block per channel, deterministic tree reduction.
// ---------------------------------------------------------------------------
__global__ void bn_stats_k(const float* __restrict__ y, int HW,
                           const float* __restrict__ gw,
                           const float* __restrict__ gb,
                           float* __restrict__ scale,
                           float* __restrict__ shift)
{
    const int c = blockIdx.x;
    const int t = threadIdx.x;
    float s = 0.f, s2 = 0.f;
    for (int b = 0; b < BATCH; b++) {
        const float* p = y + ((size_t)b * CH + c) * HW;
        for (int i = t; i < HW; i += 256) {
            float v = p[i];
            s += v; s2 += v * v;
        }
    }
#pragma unroll
    for (int o = 16; o; o >>= 1) {
        s  += __shfl_xor_sync(0xffffffffu, s, o);
        s2 += __shfl_xor_sync(0xffffffffu, s2, o);
    }
    __shared__ float r1[8], r2[8];
    if ((t & 31) == 0) { r1[t >> 5] = s; r2[t >> 5] = s2; }
    __syncthreads();
    if (t == 0) {
        float a = 0.f, b2 = 0.f;
        for (int i = 0; i < 8; i++) { a += r1[i]; b2 += r2[i]; }
        float n   = (float)(BATCH * HW);
        float m   = a / n;
        float var = b2 / n - m * m;
        float sc  = gw[c] * rsqrtf(var + EPSV);
        scale[c] = sc;
        shift[c] = gb[c] - m * sc;
    }
}

// ---------------------------------------------------------------------------
// Row softmax: fp32 energy in, fp16 probs out. One block per row.
// ---------------------------------------------------------------------------
__global__ void softmax_k(const float* __restrict__ E, __half* __restrict__ P, int L)
{
    extern __shared__ float sm[];
    float* red = sm + L;
    const size_t row = blockIdx.x;
    const float* p = E + row * (size_t)L;
    __half* q = P + row * (size_t)L;
    const int t = threadIdx.x;

    float mx = -3.4e38f;
    for (int i = t; i < L; i += 256) {
        float v = p[i];
        sm[i] = v;
        mx = fmaxf(mx, v);
    }
#pragma unroll
    for (int o = 16; o; o >>= 1) mx = fmaxf(mx, __shfl_xor_sync(0xffffffffu, mx, o));
    if ((t & 31) == 0) red[t >> 5] = mx;
    __syncthreads();
    if (t < 32) {
        float v = (t < 8) ? red[t] : -3.4e38f;
#pragma unroll
        for (int o = 4; o; o >>= 1) v = fmaxf(v, __shfl_xor_sync(0xffffffffu, v, o));
        if (t == 0) red[0] = v;
    }
    __syncthreads();
    mx = red[0];
    __syncthreads();

    float ss = 0.f;
    for (int i = t; i < L; i += 256) {
        float e = __expf(sm[i] - mx);
        sm[i] = e;
        ss += e;
    }
#pragma unroll
    for (int o = 16; o; o >>= 1) ss += __shfl_xor_sync(0xffffffffu, ss, o);
    if ((t & 31) == 0) red[t >> 5] = ss;
    __syncthreads();
    if (t < 32) {
        float v = (t < 8) ? red[t] : 0.f;
#pragma unroll
        for (int o = 4; o; o >>= 1) v += __shfl_xor_sync(0xffffffffu, v, o);
        if (t == 0) red[0] = v;
    }
    __syncthreads();
    float inv = 1.f / red[0];
    for (int i = t; i < L; i += 256) q[i] = __float2half(sm[i] * inv);
}

// ---------------------------------------------------------------------------
// dst = add + g * bilinear_upsample(src)
// ---------------------------------------------------------------------------
__global__ void up_fma_k(const float* __restrict__ src, int SH, int SWd,
                         const float* __restrict__ add, float* __restrict__ dst,
                         int DH, int DW, const float* __restrict__ gptr,
                         size_t total)
{
    size_t i = (size_t)blockIdx.x * blockDim.x + threadIdx.x;
    if (i >= total) return;
    int ox = (int)(i % DW);
    int oy = (int)((i / DW) % DH);
    size_t bc = i / ((size_t)DW * DH);

    float ry = (float)(SH - 1) / (float)(DH - 1);
    float rx = (float)(SWd - 1) / (float)(DW - 1);
    float ys = oy * ry, xs = ox * rx;
    int y0 = (int)ys; if (y0 > SH - 1) y0 = SH - 1;
    int x0 = (int)xs; if (x0 > SWd - 1) x0 = SWd - 1;
    int y1 = min(y0 + 1, SH - 1);
    int x1 = min(x0 + 1, SWd - 1);
    float tty = ys - (float)y0, ttx = xs - (float)x0;

    const float* sp = src + bc * (size_t)(SH * SWd);
    float v00 = sp[y0 * SWd + x0], v01 = sp[y0 * SWd + x1];
    float v10 = sp[y1 * SWd + x0], v11 = sp[y1 * SWd + x1];
    float val = v00 * (1.f - tty) * (1.f - ttx) + v01 * (1.f - tty) * ttx
              + v10 * tty * (1.f - ttx) + v11 * tty * ttx;
    float g = gptr ? *gptr : 1.f;
    dst[i] = add[i] + g * val;
}

// ---------------------------------------------------------------------------
// Host side
// ---------------------------------------------------------------------------
static inline unsigned cdiv(unsigned a, unsigned b) { return (a + b - 1) / b; }

struct Bufs {
    float *d2, *d3, *d4, *att, *p2, *p3, *p4, *t3, *t2, *scale, *shift;
    __half *xh, *colh, *d2h, *d3h, *d4h, *qt, *kt, *vh, *ph, *wh, *qwh, *kwh, *vwh;
};

static void run_pam(const __half* dh, int HW,
                    const float* qw, const float* qb,
                    const float* kw, const float* kb,
                    const float* vw, const float* vb,
                    const float* g, float* pout, const Bufs& B)
{
    dim3 thr(256);
    unsigned nb = cdiv(HW, 128);
    long long dhS = (long long)HW * CH;
    long long qtS = (long long)HW * KDIM;
    long long vS  = (long long)CH * HW;
    long long aS  = (long long)HW * HW;

    f2h_k<<<cdiv(KDIM * CH, 256), 256>>>(qw, B.qwh, KDIM * CH);
    f2h_k<<<cdiv(KDIM * CH, 256), 256>>>(kw, B.kwh, KDIM * CH);
    f2h_k<<<cdiv(CH * CH, 256), 256>>>(vw, B.vwh, CH * CH);

    // q^T = dh * qw^T + qb  (M=HW, N=128, K=512), fp16 out [pix][kd]
    gemm_h<1><<<dim3(1, nb, BATCH), thr>>>(dh, B.qwh, nullptr, B.qt,
        HW, KDIM, CH, CH, CH, dhS, 0, qtS, nullptr, qb, nullptr, nullptr);
    gemm_h<1><<<dim3(1, nb, BATCH), thr>>>(dh, B.kwh, nullptr, B.kt,
        HW, KDIM, CH, CH, CH, dhS, 0, qtS, nullptr, kb, nullptr, nullptr);
    // v = vw * d + vb  (M=512, N=HW, K=512), fp16 out [c][pix]
    gemm_h<1><<<dim3(nb, 4, BATCH), thr>>>(B.vwh, dh, nullptr, B.vh,
        CH, HW, CH, CH, CH, 0, dhS, vS, vb, nullptr, nullptr, nullptr);
    // energy = q^T k  (M=N=HW, K=128), fp32 out
    gemm_h<0><<<dim3(nb, nb, BATCH), thr>>>(B.qt, B.kt, B.att, nullptr,
        HW, HW, KDIM, KDIM, KDIM, qtS, qtS, aS, nullptr, nullptr, nullptr, nullptr);
    // softmax rows -> fp16 probs
    softmax_k<<<BATCH * HW, 256, (HW + 32) * sizeof(float)>>>(B.att, B.ph, HW);
    // p = g*(v @ attn^T) + v  (M=512, N=HW, K=HW), fp32 out
    gemm_h<0><<<dim3(nb, 4, BATCH), thr>>>(B.vh, B.ph, pout, nullptr,
        CH, HW, HW, HW, HW, vS, aS, vS, nullptr, nullptr, B.vh, g);
}

template <int IH, int IW>
static void run_conv(const __half* src_h, const float* wgt, float* out,
                     const Bufs& B)
{
    constexpr int OH = IH / 2, OW = IW / 2, OHOW = OH * OW;
    conv_w2h_k<<<cdiv(CH * KC, 256), 256>>>(wgt, B.wh);
    size_t total = (size_t)BATCH * OHOW * 9 * 64;
    im2col_h_k<IH, IW><<<(unsigned)((total + 255) / 256), 256>>>(src_h, B.colh);
    gemm_h<0><<<dim3(cdiv(OHOW, 128), 4, BATCH), dim3(256)>>>(
        B.wh, B.colh, out, nullptr, CH, OHOW, KC, KC, KC,
        0, (long long)KC * OHOW, (long long)CH * OHOW,
        nullptr, nullptr, nullptr, nullptr);
}

extern "C" void kernel_launch(void* const* d_in, const int* in_sizes, int n_in,
                              void* d_out, int out_size)
{
    (void)in_sizes; (void)n_in; (void)out_size;

    const float* x = (const float*)d_in[0];
    const float* w2   = (const float*)d_in[1];
    const float* bnw2 = (const float*)d_in[2];
    const float* bnb2 = (const float*)d_in[3];
    const float* w3   = (const float*)d_in[11];
    const float* bnw3 = (const float*)d_in[12];
    const float* bnb3 = (const float*)d_in[13];
    const float* w4   = (const float*)d_in[21];
    const float* bnw4 = (const float*)d_in[22];
    const float* bnb4 = (const float*)d_in[23];
    const float* gamma = (const float*)d_in[31];
    float* out = (float*)d_out;

    Bufs B;
    void* p;
    cudaGetSymbolAddress(&p, g_d2);    B.d2    = (float*)p;
    cudaGetSymbolAddress(&p, g_d3);    B.d3    = (float*)p;
    cudaGetSymbolAddress(&p, g_d4);    B.d4    = (float*)p;
    cudaGetSymbolAddress(&p, g_att);   B.att   = (float*)p;
    cudaGetSymbolAddress(&p, g_p2);    B.p2    = (float*)p;
    cudaGetSymbolAddress(&p, g_p3);    B.p3    = (float*)p;
    cudaGetSymbolAddress(&p, g_p4);    B.p4    = (float*)p;
    cudaGetSymbolAddress(&p, g_t3);    B.t3    = (float*)p;
    cudaGetSymbolAddress(&p, g_t2);    B.t2    = (float*)p;
    cudaGetSymbolAddress(&p, g_scale); B.scale = (float*)p;
    cudaGetSymbolAddress(&p, g_shift); B.shift = (float*)p;
    cudaGetSymbolAddress(&p, g_xh);    B.xh    = (__half*)p;
    cudaGetSymbolAddress(&p, g_colh);  B.colh  = (__half*)p;
    cudaGetSymbolAddress(&p, g_d2h);   B.d2h   = (__half*)p;
    cudaGetSymbolAddress(&p, g_d3h);   B.d3h   = (__half*)p;
    cudaGetSymbolAddress(&p, g_d4h);   B.d4h   = (__half*)p;
    cudaGetSymbolAddress(&p, g_qt);    B.qt    = (__half*)p;
    cudaGetSymbolAddress(&p, g_kt);    B.kt    = (__half*)p;
    cudaGetSymbolAddress(&p, g_vh);    B.vh    = (__half*)p;
    cudaGetSymbolAddress(&p, g_ph);    B.ph    = (__half*)p;
    cudaGetSymbolAddress(&p, g_wh);    B.wh    = (__half*)p;
    cudaGetSymbolAddress(&p, g_qwh);   B.qwh   = (__half*)p;
    cudaGetSymbolAddress(&p, g_kwh);   B.kwh   = (__half*)p;
    cudaGetSymbolAddress(&p, g_vwh);   B.vwh   = (__half*)p;

    dim3 tb(32, 8);

    // x -> fp16 transposed [pix][c]
    bnT_k<0><<<dim3(cdiv(HW1, 32), 16, BATCH), tb>>>(x, nullptr, nullptr, B.xh, HW1);

    // ---- encoder ----
    run_conv<96, 96>(B.xh, w2, B.d2, B);
    bn_stats_k<<<CH, 256>>>(B.d2, HW2, bnw2, bnb2, B.scale, B.shift);
    bnT_k<1><<<dim3(cdiv(HW2, 32), 16, BATCH), tb>>>(B.d2, B.scale, B.shift, B.d2h, HW2);

    run_conv<48, 48>(B.d2h, w3, B.d3, B);
    bn_stats_k<<<CH, 256>>>(B.d3, HW3, bnw3, bnb3, B.scale, B.shift);
    bnT_k<1><<<dim3(cdiv(HW3, 32), 16, BATCH), tb>>>(B.d3, B.scale, B.shift, B.d3h, HW3);

    run_conv<24, 24>(B.d3h, w4, B.d4, B);
    bn_stats_k<<<CH, 256>>>(B.d4, HW4, bnw4, bnb4, B.scale, B.shift);
    bnT_k<1><<<dim3(cdiv(HW4, 32), 16, BATCH), tb>>>(B.d4, B.scale, B.shift, B.d4h, HW4);

    // ---- PAM at each level ----
    run_pam(B.d2h, HW2, (const float*)d_in[4],  (const float*)d_in[5],
                        (const float*)d_in[6],  (const float*)d_in[7],
                        (const float*)d_in[8],  (const float*)d_in[9],
                        (const float*)d_in[10], B.p2, B);
    run_pam(B.d3h, HW3, (const float*)d_in[14], (const float*)d_in[15],
                        (const float*)d_in[16], (const float*)d_in[17],
                        (const float*)d_in[18], (const float*)d_in[19],
                        (const float*)d_in[20], B.p3, B);
    run_pam(B.d4h, HW4, (const float*)d_in[24], (const float*)d_in[25],
                        (const float*)d_in[26], (const float*)d_in[27],
                        (const float*)d_in[28], (const float*)d_in[29],
                        (const float*)d_in[30], B.p4, B);

    // ---- top-down upsample chain ----
    {
        size_t tot = (size_t)BATCH * CH * HW3;
        up_fma_k<<<(unsigned)((tot + 255) / 256), 256>>>(B.p4, 12, 12, B.p3, B.t3,
                                                         24, 24, nullptr, tot);
    }
    {
        size_t tot = (size_t)BATCH * CH * HW2;
        up_fma_k<<<(unsigned)((tot + 255) / 256), 256>>>(B.t3, 24, 24, B.p2, B.t2,
                                                         48, 48, nullptr, tot);
    }
    {
        size_t tot = (size_t)BATCH * CH * HW1;
        up_fma_k<<<(unsigned)((tot + 255) / 256), 256>>>(B.t2, 48, 48, x, out,
                                                         96, 96, gamma, tot);
    }
}

// round 6
// speedup vs baseline: 6.5748x; 1.1816x over previous
#include <cuda_runtime.h>
#include <cuda_fp16.h>
#include <cstddef>
#include <cstdint>
#include <math.h>

// ---------------------------------------------------------------------------
// Problem constants
// ---------------------------------------------------------------------------
#define BATCH 8
#define CH    512
#define KDIM  128
#define EPSV  1e-5f

#define HW1 9216           // 96*96
#define HW2 2304           // 48*48
#define HW3 576            // 24*24
#define HW4 144            // 12*12
#define KC  4608           // 512*9 im2col K

// ---------------------------------------------------------------------------
// Scratch (allocation-free: __device__ globals)
// ---------------------------------------------------------------------------
__device__ float g_d2[BATCH * CH * HW2];
__device__ float g_d3[BATCH * CH * HW3];
__device__ float g_d4[BATCH * CH * HW4];
__device__ float g_att[(size_t)BATCH * HW2 * HW2];   // 170 MB energy (fp32)
__device__ float g_p2[BATCH * CH * HW2];
__device__ float g_p3[BATCH * CH * HW3];
__device__ float g_p4[BATCH * CH * HW4];
__device__ float g_t3[BATCH * CH * HW3];
__device__ float g_t2[BATCH * CH * HW2];
__device__ float g_scale[CH];
__device__ float g_shift[CH];

__device__ __half g_xh [(size_t)BATCH * HW1 * CH];   // x transposed fp16 [pix][c]
__device__ __half g_colh[(size_t)BATCH * HW2 * KC];  // im2col fp16 [pix][k]
__device__ __half g_d2h[(size_t)BATCH * HW2 * CH];   // bn+relu+T fp16
__device__ __half g_d3h[(size_t)BATCH * HW3 * CH];
__device__ __half g_d4h[(size_t)BATCH * HW4 * CH];
__device__ __half g_qt [(size_t)BATCH * HW2 * KDIM]; // q^T fp16 [pix][kd]
__device__ __half g_kt [(size_t)BATCH * HW2 * KDIM];
__device__ __half g_vh [(size_t)BATCH * CH * HW2];   // v fp16 [c][pix]
__device__ __half g_ph [(size_t)BATCH * HW2 * HW2];  // softmax probs fp16
__device__ __half g_wh [CH * KC];                    // conv weight fp16 [oc][kk][ic]
__device__ __half g_qwh[KDIM * CH];
__device__ __half g_kwh[KDIM * CH];
__device__ __half g_vwh[CH * CH];

// ---------------------------------------------------------------------------
// Conversion kernels
// ---------------------------------------------------------------------------
__global__ void f2h_k(const float* __restrict__ in, __half* __restrict__ out, int n)
{
    int i = blockIdx.x * blockDim.x + threadIdx.x;
    if (i < n) out[i] = __float2half(in[i]);
}

// conv weight (oc, ic, kh, kw) -> fp16 [oc][kk][ic]
__global__ void conv_w2h_k(const float* __restrict__ w, __half* __restrict__ out)
{
    int i = blockIdx.x * blockDim.x + threadIdx.x;
    if (i >= CH * KC) return;
    int ic = i & 511;
    int kk = (i >> 9) % 9;
    int oc = i / KC;
    out[i] = __float2half(w[((size_t)oc * CH + ic) * 9 + kk]);
}

// ---------------------------------------------------------------------------
// Transpose (+optional BN+ReLU): fp32 [b][c][pix] -> fp16 [b][pix][c]
// ---------------------------------------------------------------------------
template <int BN_ON>
__global__ void bnT_k(const float* __restrict__ y,
                      const float* __restrict__ scale,
                      const float* __restrict__ shift,
                      __half* __restrict__ out, int HW)
{
    __shared__ float tile[32][33];
    int b = blockIdx.z;
    int p0 = blockIdx.x * 32, c0 = blockIdx.y * 32;
    int tx = threadIdx.x, ty = threadIdx.y;
#pragma unroll
    for (int j = 0; j < 4; j++) {
        int c = c0 + ty + j * 8;
        int p = p0 + tx;
        float v = 0.f;
        if (p < HW) v = y[((size_t)b * CH + c) * HW + p];
        if (BN_ON) { v = v * scale[c] + shift[c]; v = v > 0.f ? v : 0.f; }
        tile[ty + j * 8][tx] = v;
    }
    __syncthreads();
#pragma unroll
    for (int j = 0; j < 4; j++) {
        int p = p0 + ty + j * 8;
        int c = c0 + tx;
        if (p < HW) out[((size_t)b * HW + p) * CH + c] = __float2half(tile[tx][ty + j * 8]);
    }
}

// ---------------------------------------------------------------------------
// im2col fp16: src [b][pix_in][c] -> col [b][pix_out][kk*512+ic]
// ---------------------------------------------------------------------------
template <int IH, int IW>
__global__ void im2col_h_k(const __half* __restrict__ src, __half* __restrict__ col)
{
    constexpr int OH = IH / 2, OW = IW / 2, OHOW = OH * OW;
    size_t i = (size_t)blockIdx.x * blockDim.x + threadIdx.x;
    size_t total = (size_t)BATCH * OHOW * 9 * 64;
    if (i >= total) return;
    int ic8 = (int)(i & 63) << 3;
    int kk  = (int)((i >> 6) % 9);
    size_t r = i / 576;
    int pix = (int)(r % OHOW);
    int b   = (int)(r / OHOW);
    int kh = kk / 3, kw = kk - kh * 3;
    int oh = pix / OW, ow = pix - oh * OW;
    int ih = 2 * oh - 1 + kh, iw = 2 * ow - 1 + kw;
    float4 v;
    if (ih >= 0 && ih < IH && iw >= 0 && iw < IW) {
        v = *(const float4*)(src + ((size_t)b * IH * IW + ih * IW + iw) * CH + ic8);
    } else {
        v = make_float4(0.f, 0.f, 0.f, 0.f);
    }
    *(float4*)(col + ((size_t)b * OHOW + pix) * KC + kk * CH + ic8) = v;
}

// ---------------------------------------------------------------------------
// fp16 tensor-core GEMM, cp.async double-buffered, K-chunk 64, ldmatrix.
// C(M,N) = A(M,K)[m][k] * B(N,K)[n][k]^T, k-contiguous fp16 operands.
// Block 128x128x64, 8 warps (2x4), warp tile 64x32, m16n8k16 f16->f32 mma.
// smem rows padded to 72 halves (144B): cp.async 16B aligned, ldmatrix
// bank-conflict-free.  OUT=0: fp32 C; OUT=1: fp16 C.
// Epilogue: C = s*acc + biasM[row] + biasN[col] + addm (all optional).
// ---------------------------------------------------------------------------
#define GH_STG (128 * 72)                 // halves per operand per stage
#define GH_SMEM (4 * GH_STG * 2)          // 73728 bytes

template <int OUT>
__global__ __launch_bounds__(256)
void gemm_h(const __half* __restrict__ A, const __half* __restrict__ B,
            float* __restrict__ Cf, __half* __restrict__ Ch,
            int M, int N, int K, int lda, int ldb,
            long long sA, long long sB, long long sC,
            const float* __restrict__ biasM, const float* __restrict__ biasN,
            const __half* __restrict__ addm, const float* __restrict__ scl)
{
    extern __shared__ __align__(16) __half smh[];

    const int bz = blockIdx.z;
    const __half* Ab = A + (size_t)bz * sA;
    const __half* Bb = B + (size_t)bz * sB;

    const int n0 = blockIdx.x * 128, m0 = blockIdx.y * 128;
    const int t = threadIdx.x, lane = t & 31, w = t >> 5;
    const int wm = w & 1, wn = w >> 1;
    const int g = lane >> 2, tg = lane & 3;

    const uint32_t sb0 = (uint32_t)__cvta_generic_to_shared(smh);

    // ldmatrix per-lane offsets (halves)
    const int aRow = (lane & 7) + ((lane >> 3) & 1) * 8;   // row-in-16
    const int aK   = ((lane >> 4) & 1) * 8;                // k-in-16
    const int bRow = (lane & 7) + ((lane >> 4) & 1) * 8;   // n-in-16
    const int bK   = ((lane >> 3) & 1) * 8;                // k-in-16

    auto loadOp = [&](const __half* src, int ld, int r0, int lim,
                      uint32_t sb, int k0) {
#pragma unroll
        for (int i = 0; i < 4; i++) {
            int u = t + i * 256;
            int row = u >> 3, ch = (u & 7) << 3;   // halves 0..56
            bool p = (r0 + row < lim) && (k0 + ch < K);
            const __half* sp = p ? src + (size_t)(r0 + row) * ld + k0 + ch : src;
            asm volatile("cp.async.cg.shared.global [%0], [%1], 16, %2;"
                         :: "r"(sb + (uint32_t)(row * 72 + ch) * 2u),
                            "l"(sp), "r"(p ? 16 : 0));
        }
    };

    float acc[4][4][4];
#pragma unroll
    for (int a = 0; a < 4; a++)
#pragma unroll
        for (int b = 0; b < 4; b++)
#pragma unroll
            for (int c = 0; c < 4; c++) acc[a][b][c] = 0.f;

    const uint32_t stA[2] = { sb0, sb0 + GH_STG * 2 };
    const uint32_t stB[2] = { sb0 + 2 * GH_STG * 2, sb0 + 3 * GH_STG * 2 };

    const int nk = (K + 63) >> 6;
    loadOp(Ab, lda, m0, M, stA[0], 0);
    loadOp(Bb, ldb, n0, N, stB[0], 0);
    asm volatile("cp.async.commit_group;");

    for (int kt = 0; kt < nk; kt++) {
        if (kt + 1 < nk) {
            loadOp(Ab, lda, m0, M, stA[(kt + 1) & 1], (kt + 1) * 64);
            loadOp(Bb, ldb, n0, N, stB[(kt + 1) & 1], (kt + 1) * 64);
        }
        asm volatile("cp.async.commit_group;");
        asm volatile("cp.async.wait_group 1;");
        __syncthreads();

        const uint32_t As = stA[kt & 1];
        const uint32_t Bs = stB[kt & 1];

#pragma unroll
        for (int s = 0; s < 64; s += 16) {
            uint32_t a[4][4], b[4][2];
#pragma unroll
            for (int mt = 0; mt < 4; mt++) {
                uint32_t ad = As + (uint32_t)((wm * 64 + mt * 16 + aRow) * 72
                                              + s + aK) * 2u;
                asm volatile(
                    "ldmatrix.sync.aligned.m8n8.x4.shared.b16 {%0,%1,%2,%3}, [%4];"
                    : "=r"(a[mt][0]), "=r"(a[mt][1]), "=r"(a[mt][2]), "=r"(a[mt][3])
                    : "r"(ad));
            }
#pragma unroll
            for (int nt2 = 0; nt2 < 2; nt2++) {
                uint32_t bd = Bs + (uint32_t)((wn * 32 + nt2 * 16 + bRow) * 72
                                              + s + bK) * 2u;
                asm volatile(
                    "ldmatrix.sync.aligned.m8n8.x4.shared.b16 {%0,%1,%2,%3}, [%4];"
                    : "=r"(b[2 * nt2][0]), "=r"(b[2 * nt2][1]),
                      "=r"(b[2 * nt2 + 1][0]), "=r"(b[2 * nt2 + 1][1])
                    : "r"(bd));
            }
#pragma unroll
            for (int mt = 0; mt < 4; mt++)
#pragma unroll
                for (int nt = 0; nt < 4; nt++) {
                    asm volatile(
                        "mma.sync.aligned.m16n8k16.row.col.f32.f16.f16.f32 "
                        "{%0,%1,%2,%3}, {%4,%5,%6,%7}, {%8,%9}, {%0,%1,%2,%3};"
                        : "+f"(acc[mt][nt][0]), "+f"(acc[mt][nt][1]),
                          "+f"(acc[mt][nt][2]), "+f"(acc[mt][nt][3])
                        : "r"(a[mt][0]), "r"(a[mt][1]), "r"(a[mt][2]), "r"(a[mt][3]),
                          "r"(b[nt][0]), "r"(b[nt][1]));
                }
        }
        __syncthreads();
    }

    float s = scl ? *scl : 1.f;
#pragma unroll
    for (int mt = 0; mt < 4; mt++) {
#pragma unroll
        for (int half = 0; half < 2; half++) {
            int gr = m0 + wm * 64 + mt * 16 + g + half * 8;
            if (gr >= M) continue;
            float bm = biasM ? biasM[gr] : 0.f;
#pragma unroll
            for (int nt = 0; nt < 4; nt++) {
                int gc = n0 + wn * 32 + nt * 8 + tg * 2;
                if (gc + 1 >= N) continue;
                float v0 = s * acc[mt][nt][half * 2 + 0] + bm;
                float v1 = s * acc[mt][nt][half * 2 + 1] + bm;
                if (biasN) { v0 += biasN[gc]; v1 += biasN[gc + 1]; }
                size_t idx = (size_t)bz * sC + (size_t)gr * N + gc;
                if (addm) {
                    __half2 av = *(const __half2*)(addm + idx);
                    v0 += __half2float(av.x);
                    v1 += __half2float(av.y);
                }
                if (OUT == 0) {
                    *(float2*)(Cf + idx) = make_float2(v0, v1);
                } else {
                    *(__half2*)(Ch + idx) = __floats2half2_rn(v0, v1);
                }
            }
        }
    }
}

// ---------------------------------------------------------------------------
// BN statistics: one block per channel, deterministic tree reduction.
// ---------------------------------------------------------------------------
__global__ void bn_stats_k(const float* __restrict__ y, int HW,
                           const float* __restrict__ gw,
                           const float* __restrict__ gb,
                           float* __restrict__ scale,
                           float* __restrict__ shift)
{
    const int c = blockIdx.x;
    const int t = threadIdx.x;
    float s = 0.f, s2 = 0.f;
    for (int b = 0; b < BATCH; b++) {
        const float* p = y + ((size_t)b * CH + c) * HW;
        for (int i = t; i < HW; i += 256) {
            float v = p[i];
            s += v; s2 += v * v;
        }
    }
#pragma unroll
    for (int o = 16; o; o >>= 1) {
        s  += __shfl_xor_sync(0xffffffffu, s, o);
        s2 += __shfl_xor_sync(0xffffffffu, s2, o);
    }
    __shared__ float r1[8], r2[8];
    if ((t & 31) == 0) { r1[t >> 5] = s; r2[t >> 5] = s2; }
    __syncthreads();
    if (t == 0) {
        float a = 0.f, b2 = 0.f;
        for (int i = 0; i < 8; i++) { a += r1[i]; b2 += r2[i]; }
        float n   = (float)(BATCH * HW);
        float m   = a / n;
        float var = b2 / n - m * m;
        float sc  = gw[c] * rsqrtf(var + EPSV);
        scale[c] = sc;
        shift[c] = gb[c] - m * sc;
    }
}

// ---------------------------------------------------------------------------
// Row softmax: fp32 energy in, fp16 probs out. One block per row.
// ---------------------------------------------------------------------------
__global__ void softmax_k(const float* __restrict__ E, __half* __restrict__ P, int L)
{
    extern __shared__ float sm[];
    float* red = sm + L;
    const size_t row = blockIdx.x;
    const float* p = E + row * (size_t)L;
    __half* q = P + row * (size_t)L;
    const int t = threadIdx.x;

    float mx = -3.4e38f;
    for (int i = t; i < L; i += 256) {
        float v = p[i];
        sm[i] = v;
        mx = fmaxf(mx, v);
    }
#pragma unroll
    for (int o = 16; o; o >>= 1) mx = fmaxf(mx, __shfl_xor_sync(0xffffffffu, mx, o));
    if ((t & 31) == 0) red[t >> 5] = mx;
    __syncthreads();
    if (t < 32) {
        float v = (t < 8) ? red[t] : -3.4e38f;
#pragma unroll
        for (int o = 4; o; o >>= 1) v = fmaxf(v, __shfl_xor_sync(0xffffffffu, v, o));
        if (t == 0) red[0] = v;
    }
    __syncthreads();
    mx = red[0];
    __syncthreads();

    float ss = 0.f;
    for (int i = t; i < L; i += 256) {
        float e = __expf(sm[i] - mx);
        sm[i] = e;
        ss += e;
    }
#pragma unroll
    for (int o = 16; o; o >>= 1) ss += __shfl_xor_sync(0xffffffffu, ss, o);
    if ((t & 31) == 0) red[t >> 5] = ss;
    __syncthreads();
    if (t < 32) {
        float v = (t < 8) ? red[t] : 0.f;
#pragma unroll
        for (int o = 4; o; o >>= 1) v += __shfl_xor_sync(0xffffffffu, v, o);
        if (t == 0) red[0] = v;
    }
    __syncthreads();
    float inv = 1.f / red[0];
    for (int i = t; i < L; i += 256) q[i] = __float2half(sm[i] * inv);
}

// ---------------------------------------------------------------------------
// dst = add + g * bilinear_upsample(src)
// ---------------------------------------------------------------------------
__global__ void up_fma_k(const float* __restrict__ src, int SH, int SWd,
                         const float* __restrict__ add, float* __restrict__ dst,
                         int DH, int DW, const float* __restrict__ gptr,
                         size_t total)
{
    size_t i = (size_t)blockIdx.x * blockDim.x + threadIdx.x;
    if (i >= total) return;
    int ox = (int)(i % DW);
    int oy = (int)((i / DW) % DH);
    size_t bc = i / ((size_t)DW * DH);

    float ry = (float)(SH - 1) / (float)(DH - 1);
    float rx = (float)(SWd - 1) / (float)(DW - 1);
    float ys = oy * ry, xs = ox * rx;
    int y0 = (int)ys; if (y0 > SH - 1) y0 = SH - 1;
    int x0 = (int)xs; if (x0 > SWd - 1) x0 = SWd - 1;
    int y1 = min(y0 + 1, SH - 1);
    int x1 = min(x0 + 1, SWd - 1);
    float tty = ys - (float)y0, ttx = xs - (float)x0;

    const float* sp = src + bc * (size_t)(SH * SWd);
    float v00 = sp[y0 * SWd + x0], v01 = sp[y0 * SWd + x1];
    float v10 = sp[y1 * SWd + x0], v11 = sp[y1 * SWd + x1];
    float val = v00 * (1.f - tty) * (1.f - ttx) + v01 * (1.f - tty) * ttx
              + v10 * tty * (1.f - ttx) + v11 * tty * ttx;
    float g = gptr ? *gptr : 1.f;
    dst[i] = add[i] + g * val;
}

// ---------------------------------------------------------------------------
// Host side
// ---------------------------------------------------------------------------
static inline unsigned cdiv(unsigned a, unsigned b) { return (a + b - 1) / b; }

struct Bufs {
    float *d2, *d3, *d4, *att, *p2, *p3, *p4, *t3, *t2, *scale, *shift;
    __half *xh, *colh, *d2h, *d3h, *d4h, *qt, *kt, *vh, *ph, *wh, *qwh, *kwh, *vwh;
};

static void run_pam(const __half* dh, int HW,
                    const float* qw, const float* qb,
                    const float* kw, const float* kb,
                    const float* vw, const float* vb,
                    const float* g, float* pout, const Bufs& B)
{
    dim3 thr(256);
    unsigned nb = cdiv(HW, 128);
    long long dhS = (long long)HW * CH;
    long long qtS = (long long)HW * KDIM;
    long long vS  = (long long)CH * HW;
    long long aS  = (long long)HW * HW;

    f2h_k<<<cdiv(KDIM * CH, 256), 256>>>(qw, B.qwh, KDIM * CH);
    f2h_k<<<cdiv(KDIM * CH, 256), 256>>>(kw, B.kwh, KDIM * CH);
    f2h_k<<<cdiv(CH * CH, 256), 256>>>(vw, B.vwh, CH * CH);

    gemm_h<1><<<dim3(1, nb, BATCH), thr, GH_SMEM>>>(dh, B.qwh, nullptr, B.qt,
        HW, KDIM, CH, CH, CH, dhS, 0, qtS, nullptr, qb, nullptr, nullptr);
    gemm_h<1><<<dim3(1, nb, BATCH), thr, GH_SMEM>>>(dh, B.kwh, nullptr, B.kt,
        HW, KDIM, CH, CH, CH, dhS, 0, qtS, nullptr, kb, nullptr, nullptr);
    gemm_h<1><<<dim3(nb, 4, BATCH), thr, GH_SMEM>>>(B.vwh, dh, nullptr, B.vh,
        CH, HW, CH, CH, CH, 0, dhS, vS, vb, nullptr, nullptr, nullptr);
    gemm_h<0><<<dim3(nb, nb, BATCH), thr, GH_SMEM>>>(B.qt, B.kt, B.att, nullptr,
        HW, HW, KDIM, KDIM, KDIM, qtS, qtS, aS, nullptr, nullptr, nullptr, nullptr);
    softmax_k<<<BATCH * HW, 256, (HW + 32) * sizeof(float)>>>(B.att, B.ph, HW);
    gemm_h<0><<<dim3(nb, 4, BATCH), thr, GH_SMEM>>>(B.vh, B.ph, pout, nullptr,
        CH, HW, HW, HW, HW, vS, aS, vS, nullptr, nullptr, B.vh, g);
}

template <int IH, int IW>
static void run_conv(const __half* src_h, const float* wgt, float* out,
                     const Bufs& B)
{
    constexpr int OH = IH / 2, OW = IW / 2, OHOW = OH * OW;
    conv_w2h_k<<<cdiv(CH * KC, 256), 256>>>(wgt, B.wh);
    size_t total = (size_t)BATCH * OHOW * 9 * 64;
    im2col_h_k<IH, IW><<<(unsigned)((total + 255) / 256), 256>>>(src_h, B.colh);
    gemm_h<0><<<dim3(cdiv(OHOW, 128), 4, BATCH), dim3(256), GH_SMEM>>>(
        B.wh, B.colh, out, nullptr, CH, OHOW, KC, KC, KC,
        0, (long long)KC * OHOW, (long long)CH * OHOW,
        nullptr, nullptr, nullptr, nullptr);
}

extern "C" void kernel_launch(void* const* d_in, const int* in_sizes, int n_in,
                              void* d_out, int out_size)
{
    (void)in_sizes; (void)n_in; (void)out_size;

    cudaFuncSetAttribute(gemm_h<0>, cudaFuncAttributeMaxDynamicSharedMemorySize, GH_SMEM);
    cudaFuncSetAttribute(gemm_h<1>, cudaFuncAttributeMaxDynamicSharedMemorySize, GH_SMEM);

    const float* x = (const float*)d_in[0];
    const float* w2   = (const float*)d_in[1];
    const float* bnw2 = (const float*)d_in[2];
    const float* bnb2 = (const float*)d_in[3];
    const float* w3   = (const float*)d_in[11];
    const float* bnw3 = (const float*)d_in[12];
    const float* bnb3 = (const float*)d_in[13];
    const float* w4   = (const float*)d_in[21];
    const float* bnw4 = (const float*)d_in[22];
    const float* bnb4 = (const float*)d_in[23];
    const float* gamma = (const float*)d_in[31];
    float* out = (float*)d_out;

    Bufs B;
    void* p;
    cudaGetSymbolAddress(&p, g_d2);    B.d2    = (float*)p;
    cudaGetSymbolAddress(&p, g_d3);    B.d3    = (float*)p;
    cudaGetSymbolAddress(&p, g_d4);    B.d4    = (float*)p;
    cudaGetSymbolAddress(&p, g_att);   B.att   = (float*)p;
    cudaGetSymbolAddress(&p, g_p2);    B.p2    = (float*)p;
    cudaGetSymbolAddress(&p, g_p3);    B.p3    = (float*)p;
    cudaGetSymbolAddress(&p, g_p4);    B.p4    = (float*)p;
    cudaGetSymbolAddress(&p, g_t3);    B.t3    = (float*)p;
    cudaGetSymbolAddress(&p, g_t2);    B.t2    = (float*)p;
    cudaGetSymbolAddress(&p, g_scale); B.scale = (float*)p;
    cudaGetSymbolAddress(&p, g_shift); B.shift = (float*)p;
    cudaGetSymbolAddress(&p, g_xh);    B.xh    = (__half*)p;
    cudaGetSymbolAddress(&p, g_colh);  B.colh  = (__half*)p;
    cudaGetSymbolAddress(&p, g_d2h);   B.d2h   = (__half*)p;
    cudaGetSymbolAddress(&p, g_d3h);   B.d3h   = (__half*)p;
    cudaGetSymbolAddress(&p, g_d4h);   B.d4h   = (__half*)p;
    cudaGetSymbolAddress(&p, g_qt);    B.qt    = (__half*)p;
    cudaGetSymbolAddress(&p, g_kt);    B.kt    = (__half*)p;
    cudaGetSymbolAddress(&p, g_vh);    B.vh    = (__half*)p;
    cudaGetSymbolAddress(&p, g_ph);    B.ph    = (__half*)p;
    cudaGetSymbolAddress(&p, g_wh);    B.wh    = (__half*)p;
    cudaGetSymbolAddress(&p, g_qwh);   B.qwh   = (__half*)p;
    cudaGetSymbolAddress(&p, g_kwh);   B.kwh   = (__half*)p;
    cudaGetSymbolAddress(&p, g_vwh);   B.vwh   = (__half*)p;

    dim3 tb(32, 8);

    // x -> fp16 transposed [pix][c]
    bnT_k<0><<<dim3(cdiv(HW1, 32), 16, BATCH), tb>>>(x, nullptr, nullptr, B.xh, HW1);

    // ---- encoder ----
    run_conv<96, 96>(B.xh, w2, B.d2, B);
    bn_stats_k<<<CH, 256>>>(B.d2, HW2, bnw2, bnb2, B.scale, B.shift);
    bnT_k<1><<<dim3(cdiv(HW2, 32), 16, BATCH), tb>>>(B.d2, B.scale, B.shift, B.d2h, HW2);

    run_conv<48, 48>(B.d2h, w3, B.d3, B);
    bn_stats_k<<<CH, 256>>>(B.d3, HW3, bnw3, bnb3, B.scale, B.shift);
    bnT_k<1><<<dim3(cdiv(HW3, 32), 16, BATCH), tb>>>(B.d3, B.scale, B.shift, B.d3h, HW3);

    run_conv<24, 24>(B.d3h, w4, B.d4, B);
    bn_stats_k<<<CH, 256>>>(B.d4, HW4, bnw4, bnb4, B.scale, B.shift);
    bnT_k<1><<<dim3(cdiv(HW4, 32), 16, BATCH), tb>>>(B.d4, B.scale, B.shift, B.d4h, HW4);

    // ---- PAM at each level ----
    run_pam(B.d2h, HW2, (const float*)d_in[4],  (const float*)d_in[5],
                        (const float*)d_in[6],  (const float*)d_in[7],
                        (const float*)d_in[8],  (const float*)d_in[9],
                        (const float*)d_in[10], B.p2, B);
    run_pam(B.d3h, HW3, (const float*)d_in[14], (const float*)d_in[15],
                        (const float*)d_in[16], (const float*)d_in[17],
                        (const float*)d_in[18], (const float*)d_in[19],
                        (const float*)d_in[20], B.p3, B);
    run_pam(B.d4h, HW4, (const float*)d_in[24], (const float*)d_in[25],
                        (const float*)d_in[26], (const float*)d_in[27],
                        (const float*)d_in[28], (const float*)d_in[29],
                        (const float*)d_in[30], B.p4, B);

    // ---- top-down upsample chain ----
    {
        size_t tot = (size_t)BATCH * CH * HW3;
        up_fma_k<<<(unsigned)((tot + 255) / 256), 256>>>(B.p4, 12, 12, B.p3, B.t3,
                                                         24, 24, nullptr, tot);
    }
    {
        size_t tot = (size_t)BATCH * CH * HW2;
        up_fma_k<<<(unsigned)((tot + 255) / 256), 256>>>(B.t3, 24, 24, B.p2, B.t2,
                                                         48, 48, nullptr, tot);
    }
    {
        size_t tot = (size_t)BATCH * CH * HW1;
        up_fma_k<<<(unsigned)((tot + 255) / 256), 256>>>(B.t2, 48, 48, x, out,
                                                         96, 96, gamma, tot);
    }
}

// round 7
// speedup vs baseline: 6.7177x; 1.0217x over previous
#include <cuda_runtime.h>
#include <cuda_fp16.h>
#include <cstddef>
#include <cstdint>
#include <math.h>

// ---------------------------------------------------------------------------
// Problem constants
// ---------------------------------------------------------------------------
#define BATCH 8
#define CH    512
#define KDIM  128
#define EPSV  1e-5f

#define HW1 9216           // 96*96
#define HW2 2304           // 48*48
#define HW3 576            // 24*24
#define HW4 144            // 12*12
#define KC  4608           // 512*9 im2col K

// ---------------------------------------------------------------------------
// Scratch (allocation-free: __device__ globals)
// ---------------------------------------------------------------------------
__device__ float g_d2[BATCH * CH * HW2];
__device__ float g_d3[BATCH * CH * HW3];
__device__ float g_d4[BATCH * CH * HW4];
__device__ float g_att[(size_t)BATCH * HW2 * HW2];   // 170 MB energy (fp32)
__device__ float g_p2[BATCH * CH * HW2];
__device__ float g_p3[BATCH * CH * HW3];
__device__ float g_p4[BATCH * CH * HW4];
__device__ float g_t3[BATCH * CH * HW3];
__device__ float g_t2[BATCH * CH * HW2];
__device__ float g_scale[CH];
__device__ float g_shift[CH];
__device__ float g_qkb[2 * KDIM];                    // concat q,k bias

__device__ __half g_xh [(size_t)BATCH * HW1 * CH];   // x transposed fp16 [pix][c]
__device__ __half g_colh[(size_t)BATCH * HW2 * KC];  // im2col fp16 [pix][k]
__device__ __half g_d2h[(size_t)BATCH * HW2 * CH];   // bn+relu+T fp16
__device__ __half g_d3h[(size_t)BATCH * HW3 * CH];
__device__ __half g_d4h[(size_t)BATCH * HW4 * CH];
__device__ __half g_qkt[(size_t)BATCH * HW2 * 2 * KDIM]; // q|k fp16 [pix][256]
__device__ __half g_vh [(size_t)BATCH * CH * HW2];   // v fp16 [c][pix]
__device__ __half g_ph [(size_t)BATCH * HW2 * HW2];  // softmax probs fp16
__device__ __half g_wh [CH * KC];                    // conv weight fp16 [oc][kk][ic]
__device__ __half g_qkwh[2 * KDIM * CH];             // concat q,k weights fp16
__device__ __half g_vwh[CH * CH];

// ---------------------------------------------------------------------------
// Conversion kernels
// ---------------------------------------------------------------------------
__global__ void f2h_k(const float* __restrict__ in, __half* __restrict__ out, int n)
{
    int i = blockIdx.x * blockDim.x + threadIdx.x;
    if (i < n) out[i] = __float2half(in[i]);
}

// conv weight (oc, ic, kh, kw) -> fp16 [oc][kk][ic]
__global__ void conv_w2h_k(const float* __restrict__ w, __half* __restrict__ out)
{
    int i = blockIdx.x * blockDim.x + threadIdx.x;
    if (i >= CH * KC) return;
    int ic = i & 511;
    int kk = (i >> 9) % 9;
    int oc = i / KC;
    out[i] = __float2half(w[((size_t)oc * CH + ic) * 9 + kk]);
}

// ---------------------------------------------------------------------------
// Transpose (+optional BN+ReLU): fp32 [b][c][pix] -> fp16 [b][pix][c]
// ---------------------------------------------------------------------------
template <int BN_ON>
__global__ void bnT_k(const float* __restrict__ y,
                      const float* __restrict__ scale,
                      const float* __restrict__ shift,
                      __half* __restrict__ out, int HW)
{
    __shared__ float tile[32][33];
    int b = blockIdx.z;
    int p0 = blockIdx.x * 32, c0 = blockIdx.y * 32;
    int tx = threadIdx.x, ty = threadIdx.y;
#pragma unroll
    for (int j = 0; j < 4; j++) {
        int c = c0 + ty + j * 8;
        int p = p0 + tx;
        float v = 0.f;
        if (p < HW) v = y[((size_t)b * CH + c) * HW + p];
        if (BN_ON) { v = v * scale[c] + shift[c]; v = v > 0.f ? v : 0.f; }
        tile[ty + j * 8][tx] = v;
    }
    __syncthreads();
#pragma unroll
    for (int j = 0; j < 4; j++) {
        int p = p0 + ty + j * 8;
        int c = c0 + tx;
        if (p < HW) out[((size_t)b * HW + p) * CH + c] = __float2half(tile[tx][ty + j * 8]);
    }
}

// ---------------------------------------------------------------------------
// im2col fp16: src [b][pix_in][c] -> col [b][pix_out][kk*512+ic]
// ---------------------------------------------------------------------------
template <int IH, int IW>
__global__ void im2col_h_k(const __half* __restrict__ src, __half* __restrict__ col)
{
    constexpr int OH = IH / 2, OW = IW / 2, OHOW = OH * OW;
    size_t i = (size_t)blockIdx.x * blockDim.x + threadIdx.x;
    size_t total = (size_t)BATCH * OHOW * 9 * 64;
    if (i >= total) return;
    int ic8 = (int)(i & 63) << 3;
    int kk  = (int)((i >> 6) % 9);
    size_t r = i / 576;
    int pix = (int)(r % OHOW);
    int b   = (int)(r / OHOW);
    int kh = kk / 3, kw = kk - kh * 3;
    int oh = pix / OW, ow = pix - oh * OW;
    int ih = 2 * oh - 1 + kh, iw = 2 * ow - 1 + kw;
    float4 v;
    if (ih >= 0 && ih < IH && iw >= 0 && iw < IW) {
        v = *(const float4*)(src + ((size_t)b * IH * IW + ih * IW + iw) * CH + ic8);
    } else {
        v = make_float4(0.f, 0.f, 0.f, 0.f);
    }
    *(float4*)(col + ((size_t)b * OHOW + pix) * KC + kk * CH + ic8) = v;
}

// ---------------------------------------------------------------------------
// fp16 tensor-core GEMM, cp.async 3-stage pipeline, K-chunk 64, ldmatrix.
// C(M,N) = A(M,K)[m][k] * B(N,K)[n][k]^T, k-contiguous fp16 operands.
// Block 128x128x64, 8 warps (2x4), warp tile 64x32, m16n8k16 f16->f32 mma.
// smem rows padded to 72 halves (144B). One __syncthreads per K-chunk;
// prefetch distance 2 chunks. OUT=0: fp32 C; OUT=1: fp16 C.
// Epilogue: C = s*acc + biasM[row] + biasN[col] + addm (all optional).
// ---------------------------------------------------------------------------
#define GH_STG (128 * 72)                 // halves per operand per stage
#define GH_SMEM (6 * GH_STG * 2)          // 110592 bytes (3 stages x 2 ops)

template <int OUT>
__global__ __launch_bounds__(256)
void gemm_h(const __half* __restrict__ A, const __half* __restrict__ B,
            float* __restrict__ Cf, __half* __restrict__ Ch,
            int M, int N, int K, int lda, int ldb,
            long long sA, long long sB, long long sC,
            const float* __restrict__ biasM, const float* __restrict__ biasN,
            const __half* __restrict__ addm, const float* __restrict__ scl)
{
    extern __shared__ __align__(16) __half smh[];

    const int bz = blockIdx.z;
    const __half* Ab = A + (size_t)bz * sA;
    const __half* Bb = B + (size_t)bz * sB;

    const int n0 = blockIdx.x * 128, m0 = blockIdx.y * 128;
    const int t = threadIdx.x, lane = t & 31, w = t >> 5;
    const int wm = w & 1, wn = w >> 1;
    const int g = lane >> 2, tg = lane & 3;

    const uint32_t sb0 = (uint32_t)__cvta_generic_to_shared(smh);

    // ldmatrix per-lane offsets (halves)
    const int aRow = (lane & 7) + ((lane >> 3) & 1) * 8;
    const int aK   = ((lane >> 4) & 1) * 8;
    const int bRow = (lane & 7) + ((lane >> 4) & 1) * 8;
    const int bK   = ((lane >> 3) & 1) * 8;

    auto loadOp = [&](const __half* src, int ld, int r0, int lim,
                      uint32_t sb, int k0) {
#pragma unroll
        for (int i = 0; i < 4; i++) {
            int u = t + i * 256;
            int row = u >> 3, ch = (u & 7) << 3;
            bool p = (r0 + row < lim) && (k0 + ch < K);
            const __half* sp = p ? src + (size_t)(r0 + row) * ld + k0 + ch : src;
            asm volatile("cp.async.cg.shared.global [%0], [%1], 16, %2;"
                         :: "r"(sb + (uint32_t)(row * 72 + ch) * 2u),
                            "l"(sp), "r"(p ? 16 : 0));
        }
    };

    float acc[4][4][4];
#pragma unroll
    for (int a = 0; a < 4; a++)
#pragma unroll
        for (int b = 0; b < 4; b++)
#pragma unroll
            for (int c = 0; c < 4; c++) acc[a][b][c] = 0.f;

    const uint32_t stA[3] = { sb0, sb0 + GH_STG * 2, sb0 + 2 * GH_STG * 2 };
    const uint32_t stB[3] = { sb0 + 3 * GH_STG * 2, sb0 + 4 * GH_STG * 2,
                              sb0 + 5 * GH_STG * 2 };

    const int nk = (K + 63) >> 6;
    loadOp(Ab, lda, m0, M, stA[0], 0);
    loadOp(Bb, ldb, n0, N, stB[0], 0);
    asm volatile("cp.async.commit_group;");
    if (nk > 1) {
        loadOp(Ab, lda, m0, M, stA[1], 64);
        loadOp(Bb, ldb, n0, N, stB[1], 64);
    }
    asm volatile("cp.async.commit_group;");

    int cur = 0, nxt = 2;                  // stage indices mod 3
    for (int kt = 0; kt < nk; kt++) {
        asm volatile("cp.async.wait_group 1;");
        __syncthreads();

        if (kt + 2 < nk) {
            loadOp(Ab, lda, m0, M, stA[nxt], (kt + 2) * 64);
            loadOp(Bb, ldb, n0, N, stB[nxt], (kt + 2) * 64);
        }
        asm volatile("cp.async.commit_group;");

        const uint32_t As = stA[cur];
        const uint32_t Bs = stB[cur];

#pragma unroll
        for (int s = 0; s < 64; s += 16) {
            uint32_t a[4][4], b[4][2];
#pragma unroll
            for (int mt = 0; mt < 4; mt++) {
                uint32_t ad = As + (uint32_t)((wm * 64 + mt * 16 + aRow) * 72
                                              + s + aK) * 2u;
                asm volatile(
                    "ldmatrix.sync.aligned.m8n8.x4.shared.b16 {%0,%1,%2,%3}, [%4];"
                    : "=r"(a[mt][0]), "=r"(a[mt][1]), "=r"(a[mt][2]), "=r"(a[mt][3])
                    : "r"(ad));
            }
#pragma unroll
            for (int nt2 = 0; nt2 < 2; nt2++) {
                uint32_t bd = Bs + (uint32_t)((wn * 32 + nt2 * 16 + bRow) * 72
                                              + s + bK) * 2u;
                asm volatile(
                    "ldmatrix.sync.aligned.m8n8.x4.shared.b16 {%0,%1,%2,%3}, [%4];"
                    : "=r"(b[2 * nt2][0]), "=r"(b[2 * nt2][1]),
                      "=r"(b[2 * nt2 + 1][0]), "=r"(b[2 * nt2 + 1][1])
                    : "r"(bd));
            }
#pragma unroll
            for (int mt = 0; mt < 4; mt++)
#pragma unroll
                for (int nt = 0; nt < 4; nt++) {
                    asm volatile(
                        "mma.sync.aligned.m16n8k16.row.col.f32.f16.f16.f32 "
                        "{%0,%1,%2,%3}, {%4,%5,%6,%7}, {%8,%9}, {%0,%1,%2,%3};"
                        : "+f"(acc[mt][nt][0]), "+f"(acc[mt][nt][1]),
                          "+f"(acc[mt][nt][2]), "+f"(acc[mt][nt][3])
                        : "r"(a[mt][0]), "r"(a[mt][1]), "r"(a[mt][2]), "r"(a[mt][3]),
                          "r"(b[nt][0]), "r"(b[nt][1]));
                }
        }
        cur = (cur + 1) == 3 ? 0 : cur + 1;
        nxt = (nxt + 1) == 3 ? 0 : nxt + 1;
    }

    float s = scl ? *scl : 1.f;
#pragma unroll
    for (int mt = 0; mt < 4; mt++) {
#pragma unroll
        for (int half = 0; half < 2; half++) {
            int gr = m0 + wm * 64 + mt * 16 + g + half * 8;
            if (gr >= M) continue;
            float bm = biasM ? biasM[gr] : 0.f;
#pragma unroll
            for (int nt = 0; nt < 4; nt++) {
                int gc = n0 + wn * 32 + nt * 8 + tg * 2;
                if (gc + 1 >= N) continue;
                float v0 = s * acc[mt][nt][half * 2 + 0] + bm;
                float v1 = s * acc[mt][nt][half * 2 + 1] + bm;
                if (biasN) { v0 += biasN[gc]; v1 += biasN[gc + 1]; }
                size_t idx = (size_t)bz * sC + (size_t)gr * N + gc;
                if (addm) {
                    __half2 av = *(const __half2*)(addm + idx);
                    v0 += __half2float(av.x);
                    v1 += __half2float(av.y);
                }
                if (OUT == 0) {
                    *(float2*)(Cf + idx) = make_float2(v0, v1);
                } else {
                    *(__half2*)(Ch + idx) = __floats2half2_rn(v0, v1);
                }
            }
        }
    }
}

// ---------------------------------------------------------------------------
// BN statistics: one block per channel, deterministic tree reduction.
// ---------------------------------------------------------------------------
__global__ void bn_stats_k(const float* __restrict__ y, int HW,
                           const float* __restrict__ gw,
                           const float* __restrict__ gb,
                           float* __restrict__ scale,
                           float* __restrict__ shift)
{
    const int c = blockIdx.x;
    const int t = threadIdx.x;
    float s = 0.f, s2 = 0.f;
    for (int b = 0; b < BATCH; b++) {
        const float* p = y + ((size_t)b * CH + c) * HW;
        for (int i = t; i < HW; i += 256) {
            float v = p[i];
            s += v; s2 += v * v;
        }
    }
#pragma unroll
    for (int o = 16; o; o >>= 1) {
        s  += __shfl_xor_sync(0xffffffffu, s, o);
        s2 += __shfl_xor_sync(0xffffffffu, s2, o);
    }
    __shared__ float r1[8], r2[8];
    if ((t & 31) == 0) { r1[t >> 5] = s; r2[t >> 5] = s2; }
    __syncthreads();
    if (t == 0) {
        float a = 0.f, b2 = 0.f;
        for (int i = 0; i < 8; i++) { a += r1[i]; b2 += r2[i]; }
        float n   = (float)(BATCH * HW);
        float m   = a / n;
        float var = b2 / n - m * m;
        float sc  = gw[c] * rsqrtf(var + EPSV);
        scale[c] = sc;
        shift[c] = gb[c] - m * sc;
    }
}

// ---------------------------------------------------------------------------
// Row softmax: fp32 energy in, fp16 probs out. One block per row.
// ---------------------------------------------------------------------------
__global__ void softmax_k(const float* __restrict__ E, __half* __restrict__ P, int L)
{
    extern __shared__ float sm[];
    float* red = sm + L;
    const size_t row = blockIdx.x;
    const float* p = E + row * (size_t)L;
    __half* q = P + row * (size_t)L;
    const int t = threadIdx.x;

    float mx = -3.4e38f;
    for (int i = t; i < L; i += 256) {
        float v = p[i];
        sm[i] = v;
        mx = fmaxf(mx, v);
    }
#pragma unroll
    for (int o = 16; o; o >>= 1) mx = fmaxf(mx, __shfl_xor_sync(0xffffffffu, mx, o));
    if ((t & 31) == 0) red[t >> 5] = mx;
    __syncthreads();
    if (t < 32) {
        float v = (t < 8) ? red[t] : -3.4e38f;
#pragma unroll
        for (int o = 4; o; o >>= 1) v = fmaxf(v, __shfl_xor_sync(0xffffffffu, v, o));
        if (t == 0) red[0] = v;
    }
    __syncthreads();
    mx = red[0];
    __syncthreads();

    float ss = 0.f;
    for (int i = t; i < L; i += 256) {
        float e = __expf(sm[i] - mx);
        sm[i] = e;
        ss += e;
    }
#pragma unroll
    for (int o = 16; o; o >>= 1) ss += __shfl_xor_sync(0xffffffffu, ss, o);
    if ((t & 31) == 0) red[t >> 5] = ss;
    __syncthreads();
    if (t < 32) {
        float v = (t < 8) ? red[t] : 0.f;
#pragma unroll
        for (int o = 4; o; o >>= 1) v += __shfl_xor_sync(0xffffffffu, v, o);
        if (t == 0) red[0] = v;
    }
    __syncthreads();
    float inv = 1.f / red[0];
    for (int i = t; i < L; i += 256) q[i] = __float2half(sm[i] * inv);
}

// ---------------------------------------------------------------------------
// dst = add + g * bilinear_upsample(src)
// ---------------------------------------------------------------------------
__global__ void up_fma_k(const float* __restrict__ src, int SH, int SWd,
                         const float* __restrict__ add, float* __restrict__ dst,
                         int DH, int DW, const float* __restrict__ gptr,
                         size_t total)
{
    size_t i = (size_t)blockIdx.x * blockDim.x + threadIdx.x;
    if (i >= total) return;
    int ox = (int)(i % DW);
    int oy = (int)((i / DW) % DH);
    size_t bc = i / ((size_t)DW * DH);

    float ry = (float)(SH - 1) / (float)(DH - 1);
    float rx = (float)(SWd - 1) / (float)(DW - 1);
    float ys = oy * ry, xs = ox * rx;
    int y0 = (int)ys; if (y0 > SH - 1) y0 = SH - 1;
    int x0 = (int)xs; if (x0 > SWd - 1) x0 = SWd - 1;
    int y1 = min(y0 + 1, SH - 1);
    int x1 = min(x0 + 1, SWd - 1);
    float tty = ys - (float)y0, ttx = xs - (float)x0;

    const float* sp = src + bc * (size_t)(SH * SWd);
    float v00 = sp[y0 * SWd + x0], v01 = sp[y0 * SWd + x1];
    float v10 = sp[y1 * SWd + x0], v11 = sp[y1 * SWd + x1];
    float val = v00 * (1.f - tty) * (1.f - ttx) + v01 * (1.f - tty) * ttx
              + v10 * tty * (1.f - ttx) + v11 * tty * ttx;
    float g = gptr ? *gptr : 1.f;
    dst[i] = add[i] + g * val;
}

// ---------------------------------------------------------------------------
// Host side
// ---------------------------------------------------------------------------
static inline unsigned cdiv(unsigned a, unsigned b) { return (a + b - 1) / b; }

struct Bufs {
    float *d2, *d3, *d4, *att, *p2, *p3, *p4, *t3, *t2, *scale, *shift, *qkb;
    __half *xh, *colh, *d2h, *d3h, *d4h, *qkt, *vh, *ph, *wh, *qkwh, *vwh;
};

static void run_pam(const __half* dh, int HW,
                    const float* qw, const float* qb,
                    const float* kw, const float* kb,
                    const float* vw, const float* vb,
                    const float* g, float* pout, const Bufs& B)
{
    dim3 thr(256);
    unsigned nb = cdiv(HW, 128);
    long long dhS  = (long long)HW * CH;
    long long qkS  = (long long)HW * 2 * KDIM;
    long long vS   = (long long)CH * HW;
    long long aS   = (long long)HW * HW;

    f2h_k<<<cdiv(KDIM * CH, 256), 256>>>(qw, B.qkwh, KDIM * CH);
    f2h_k<<<cdiv(KDIM * CH, 256), 256>>>(kw, B.qkwh + KDIM * CH, KDIM * CH);
    f2h_k<<<cdiv(CH * CH, 256), 256>>>(vw, B.vwh, CH * CH);
    cudaMemcpyAsync(B.qkb, qb, KDIM * sizeof(float), cudaMemcpyDeviceToDevice);
    cudaMemcpyAsync(B.qkb + KDIM, kb, KDIM * sizeof(float), cudaMemcpyDeviceToDevice);

    // [q|k]^T = dh * qkw^T + qkb  (M=HW, N=256, K=512), fp16 out [pix][256]
    gemm_h<1><<<dim3(2, nb, BATCH), thr, GH_SMEM>>>(dh, B.qkwh, nullptr, B.qkt,
        HW, 2 * KDIM, CH, CH, CH, dhS, 0, qkS, nullptr, B.qkb, nullptr, nullptr);
    // v = vw * d + vb  (M=512, N=HW, K=512), fp16 out [c][pix]
    gemm_h<1><<<dim3(nb, 4, BATCH), thr, GH_SMEM>>>(B.vwh, dh, nullptr, B.vh,
        CH, HW, CH, CH, CH, 0, dhS, vS, vb, nullptr, nullptr, nullptr);
    // energy = q^T k  (M=N=HW, K=128), fp32 out
    gemm_h<0><<<dim3(nb, nb, BATCH), thr, GH_SMEM>>>(B.qkt, B.qkt + KDIM,
        B.att, nullptr, HW, HW, KDIM, 2 * KDIM, 2 * KDIM, qkS, qkS, aS,
        nullptr, nullptr, nullptr, nullptr);
    softmax_k<<<BATCH * HW, 256, (HW + 32) * sizeof(float)>>>(B.att, B.ph, HW);
    // p = g*(v @ attn^T) + v  (M=512, N=HW, K=HW), fp32 out
    gemm_h<0><<<dim3(nb, 4, BATCH), thr, GH_SMEM>>>(B.vh, B.ph, pout, nullptr,
        CH, HW, HW, HW, HW, vS, aS, vS, nullptr, nullptr, B.vh, g);
}

template <int IH, int IW>
static void run_conv(const __half* src_h, const float* wgt, float* out,
                     const Bufs& B)
{
    constexpr int OH = IH / 2, OW = IW / 2, OHOW = OH * OW;
    conv_w2h_k<<<cdiv(CH * KC, 256), 256>>>(wgt, B.wh);
    size_t total = (size_t)BATCH * OHOW * 9 * 64;
    im2col_h_k<IH, IW><<<(unsigned)((total + 255) / 256), 256>>>(src_h, B.colh);
    gemm_h<0><<<dim3(cdiv(OHOW, 128), 4, BATCH), dim3(256), GH_SMEM>>>(
        B.wh, B.colh, out, nullptr, CH, OHOW, KC, KC, KC,
        0, (long long)KC * OHOW, (long long)CH * OHOW,
        nullptr, nullptr, nullptr, nullptr);
}

extern "C" void kernel_launch(void* const* d_in, const int* in_sizes, int n_in,
                              void* d_out, int out_size)
{
    (void)in_sizes; (void)n_in; (void)out_size;

    cudaFuncSetAttribute(gemm_h<0>, cudaFuncAttributeMaxDynamicSharedMemorySize, GH_SMEM);
    cudaFuncSetAttribute(gemm_h<1>, cudaFuncAttributeMaxDynamicSharedMemorySize, GH_SMEM);

    const float* x = (const float*)d_in[0];
    const float* w2   = (const float*)d_in[1];
    const float* bnw2 = (const float*)d_in[2];
    const float* bnb2 = (const float*)d_in[3];
    const float* w3   = (const float*)d_in[11];
    const float* bnw3 = (const float*)d_in[12];
    const float* bnb3 = (const float*)d_in[13];
    const float* w4   = (const float*)d_in[21];
    const float* bnw4 = (const float*)d_in[22];
    const float* bnb4 = (const float*)d_in[23];
    const float* gamma = (const float*)d_in[31];
    float* out = (float*)d_out;

    Bufs B;
    void* p;
    cudaGetSymbolAddress(&p, g_d2);    B.d2    = (float*)p;
    cudaGetSymbolAddress(&p, g_d3);    B.d3    = (float*)p;
    cudaGetSymbolAddress(&p, g_d4);    B.d4    = (float*)p;
    cudaGetSymbolAddress(&p, g_att);   B.att   = (float*)p;
    cudaGetSymbolAddress(&p, g_p2);    B.p2    = (float*)p;
    cudaGetSymbolAddress(&p, g_p3);    B.p3    = (float*)p;
    cudaGetSymbolAddress(&p, g_p4);    B.p4    = (float*)p;
    cudaGetSymbolAddress(&p, g_t3);    B.t3    = (float*)p;
    cudaGetSymbolAddress(&p, g_t2);    B.t2    = (float*)p;
    cudaGetSymbolAddress(&p, g_scale); B.scale = (float*)p;
    cudaGetSymbolAddress(&p, g_shift); B.shift = (float*)p;
    cudaGetSymbolAddress(&p, g_qkb);   B.qkb   = (float*)p;
    cudaGetSymbolAddress(&p, g_xh);    B.xh    = (__half*)p;
    cudaGetSymbolAddress(&p, g_colh);  B.colh  = (__half*)p;
    cudaGetSymbolAddress(&p, g_d2h);   B.d2h   = (__half*)p;
    cudaGetSymbolAddress(&p, g_d3h);   B.d3h   = (__half*)p;
    cudaGetSymbolAddress(&p, g_d4h);   B.d4h   = (__half*)p;
    cudaGetSymbolAddress(&p, g_qkt);   B.qkt   = (__half*)p;
    cudaGetSymbolAddress(&p, g_vh);    B.vh    = (__half*)p;
    cudaGetSymbolAddress(&p, g_ph);    B.ph    = (__half*)p;
    cudaGetSymbolAddress(&p, g_wh);    B.wh    = (__half*)p;
    cudaGetSymbolAddress(&p, g_qkwh);  B.qkwh  = (__half*)p;
    cudaGetSymbolAddress(&p, g_vwh);   B.vwh   = (__half*)p;

    dim3 tb(32, 8);

    // x -> fp16 transposed [pix][c]
    bnT_k<0><<<dim3(cdiv(HW1, 32), 16, BATCH), tb>>>(x, nullptr, nullptr, B.xh, HW1);

    // ---- encoder ----
    run_conv<96, 96>(B.xh, w2, B.d2, B);
    bn_stats_k<<<CH, 256>>>(B.d2, HW2, bnw2, bnb2, B.scale, B.shift);
    bnT_k<1><<<dim3(cdiv(HW2, 32), 16, BATCH), tb>>>(B.d2, B.scale, B.shift, B.d2h, HW2);

    run_conv<48, 48>(B.d2h, w3, B.d3, B);
    bn_stats_k<<<CH, 256>>>(B.d3, HW3, bnw3, bnb3, B.scale, B.shift);
    bnT_k<1><<<dim3(cdiv(HW3, 32), 16, BATCH), tb>>>(B.d3, B.scale, B.shift, B.d3h, HW3);

    run_conv<24, 24>(B.d3h, w4, B.d4, B);
    bn_stats_k<<<CH, 256>>>(B.d4, HW4, bnw4, bnb4, B.scale, B.shift);
    bnT_k<1><<<dim3(cdiv(HW4, 32), 16, BATCH), tb>>>(B.d4, B.scale, B.shift, B.d4h, HW4);

    // ---- PAM at each level ----
    run_pam(B.d2h, HW2, (const float*)d_in[4],  (const float*)d_in[5],
                        (const float*)d_in[6],  (const float*)d_in[7],
                        (const float*)d_in[8],  (const float*)d_in[9],
                        (const float*)d_in[10], B.p2, B);
    run_pam(B.d3h, HW3, (const float*)d_in[14], (const float*)d_in[15],
                        (const float*)d_in[16], (const float*)d_in[17],
                        (const float*)d_in[18], (const float*)d_in[19],
                        (const float*)d_in[20], B.p3, B);
    run_pam(B.d4h, HW4, (const float*)d_in[24], (const float*)d_in[25],
                        (const float*)d_in[26], (const float*)d_in[27],
                        (const float*)d_in[28], (const float*)d_in[29],
                        (const float*)d_in[30], B.p4, B);

    // ---- top-down upsample chain ----
    {
        size_t tot = (size_t)BATCH * CH * HW3;
        up_fma_k<<<(unsigned)((tot + 255) / 256), 256>>>(B.p4, 12, 12, B.p3, B.t3,
                                                         24, 24, nullptr, tot);
    }
    {
        size_t tot = (size_t)BATCH * CH * HW2;
        up_fma_k<<<(unsigned)((tot + 255) / 256), 256>>>(B.t3, 24, 24, B.p2, B.t2,
                                                         48, 48, nullptr, tot);
    }
    {
        size_t tot = (size_t)BATCH * CH * HW1;
        up_fma_k<<<(unsigned)((tot + 255) / 256), 256>>>(B.t2, 48, 48, x, out,
                                                         96, 96, gamma, tot);
    }
}

// round 9
// speedup vs baseline: 6.8660x; 1.0221x over previous
#include <cuda_runtime.h>
#include <cuda_fp16.h>
#include <cstddef>
#include <cstdint>
#include <math.h>

// ---------------------------------------------------------------------------
// Problem constants
// ---------------------------------------------------------------------------
#define BATCH 8
#define CH    512
#define KDIM  128
#define EPSV  1e-5f

#define HW1 9216           // 96*96
#define HW2 2304           // 48*48
#define HW3 576            // 24*24
#define HW4 144            // 12*12
#define KC  4608           // 512*9 im2col K

// ---------------------------------------------------------------------------
// Scratch (allocation-free: __device__ globals)
// ---------------------------------------------------------------------------
__device__ float g_d2[BATCH * CH * HW2];
__device__ float g_d3[BATCH * CH * HW3];
__device__ float g_d4[BATCH * CH * HW4];
__device__ float g_att[(size_t)BATCH * HW2 * HW2];   // fp32 energy
__device__ float g_p2[BATCH * CH * HW2];
__device__ float g_p3[BATCH * CH * HW3];
__device__ float g_p4[BATCH * CH * HW4];
__device__ float g_t3[BATCH * CH * HW3];
__device__ float g_t2[BATCH * CH * HW2];
__device__ float g_scale[CH];
__device__ float g_shift[CH];
__device__ float g_qkb[2 * KDIM];

__device__ __half g_xh [(size_t)BATCH * HW1 * CH];   // x transposed fp16 [pix][c]
__device__ __half g_d2h[(size_t)BATCH * HW2 * CH];   // bn+relu+T fp16
__device__ __half g_d3h[(size_t)BATCH * HW3 * CH];
__device__ __half g_d4h[(size_t)BATCH * HW4 * CH];
__device__ __half g_qkt[(size_t)BATCH * HW2 * 2 * KDIM]; // q|k fp16 [pix][256]
__device__ __half g_vh [(size_t)BATCH * CH * HW2];   // v fp16 [c][pix]
__device__ __half g_ph [(size_t)BATCH * HW2 * HW2];  // softmax probs fp16
__device__ __half g_wh [CH * KC];                    // conv weight fp16 [oc][kk][ic]
__device__ __half g_qkwh[2 * KDIM * CH];             // concat q,k weights fp16
__device__ __half g_vwh[CH * CH];

// ---------------------------------------------------------------------------
// Conversion kernels
// ---------------------------------------------------------------------------
__global__ void f2h_k(const float* __restrict__ in, __half* __restrict__ out, int n)
{
    int i = blockIdx.x * blockDim.x + threadIdx.x;
    if (i < n) out[i] = __float2half(in[i]);
}

// conv weight (oc, ic, kh, kw) -> fp16 [oc][kk][ic]
__global__ void conv_w2h_k(const float* __restrict__ w, __half* __restrict__ out)
{
    int i = blockIdx.x * blockDim.x + threadIdx.x;
    if (i >= CH * KC) return;
    int ic = i & 511;
    int kk = (i >> 9) % 9;
    int oc = i / KC;
    out[i] = __float2half(w[((size_t)oc * CH + ic) * 9 + kk]);
}

// ---------------------------------------------------------------------------
// Transpose (+optional BN+ReLU): fp32 [b][c][pix] -> fp16 [b][pix][c]
// ---------------------------------------------------------------------------
template <int BN_ON>
__global__ void bnT_k(const float* __restrict__ y,
                      const float* __restrict__ scale,
                      const float* __restrict__ shift,
                      __half* __restrict__ out, int HW)
{
    __shared__ float tile[32][33];
    int b = blockIdx.z;
    int p0 = blockIdx.x * 32, c0 = blockIdx.y * 32;
    int tx = threadIdx.x, ty = threadIdx.y;
#pragma unroll
    for (int j = 0; j < 4; j++) {
        int c = c0 + ty + j * 8;
        int p = p0 + tx;
        float v = 0.f;
        if (p < HW) v = y[((size_t)b * CH + c) * HW + p];
        if (BN_ON) { v = v * scale[c] + shift[c]; v = v > 0.f ? v : 0.f; }
        tile[ty + j * 8][tx] = v;
    }
    __syncthreads();
#pragma unroll
    for (int j = 0; j < 4; j++) {
        int p = p0 + ty + j * 8;
        int c = c0 + tx;
        if (p < HW) out[((size_t)b * HW + p) * CH + c] = __float2half(tile[tx][ty + j * 8]);
    }
}

// ---------------------------------------------------------------------------
// fp16 tensor-core GEMM, cp.async 3-stage pipeline, K-chunk 64, ldmatrix.
// C(M,N) = A(M,K)[m][k] * B(N,K)[n][k]^T, k-contiguous fp16 operands.
// Block 128x128x64, 8 warps (2x4), warp tile 64x32, m16n8k16 f16->f32 mma.
// CDIM > 0: implicit-im2col B operand for 3x3 s2 p1 conv with input
// [pix][c] fp16 of spatial size CDIM x CDIM (N = (CDIM/2)^2, K = 4608).
// smem rows padded to 72 halves. One __syncthreads per K-chunk; prefetch
// distance 2. OUT=0: fp32 C; OUT=1: fp16 C.
// Epilogue: C = s*acc + biasM[row] + biasN[col] + addm (all optional).
// ---------------------------------------------------------------------------
#define GH_STG (128 * 72)                 // halves per operand per stage
#define GH_SMEM (6 * GH_STG * 2)          // 110592 bytes (3 stages x 2 ops)

template <int OUT, int CDIM>
__global__ __launch_bounds__(256)
void gemm_h(const __half* __restrict__ A, const __half* __restrict__ B,
            float* __restrict__ Cf, __half* __restrict__ Ch,
            int M, int N, int K, int lda, int ldb,
            long long sA, long long sB, long long sC,
            const float* __restrict__ biasM, const float* __restrict__ biasN,
            const __half* __restrict__ addm, const float* __restrict__ scl)
{
    extern __shared__ __align__(16) __half smh[];

    const int bz = blockIdx.z;
    const __half* Ab = A + (size_t)bz * sA;
    const __half* Bb = B + (size_t)bz * sB;

    const int n0 = blockIdx.x * 128, m0 = blockIdx.y * 128;
    const int t = threadIdx.x, lane = t & 31, w = t >> 5;
    const int wm = w & 1, wn = w >> 1;
    const int g = lane >> 2, tg = lane & 3;

    const uint32_t sb0 = (uint32_t)__cvta_generic_to_shared(smh);

    // ldmatrix per-lane offsets (halves)
    const int aRow = (lane & 7) + ((lane >> 3) & 1) * 8;
    const int aK   = ((lane >> 4) & 1) * 8;
    const int bRow = (lane & 7) + ((lane >> 4) & 1) * 8;
    const int bK   = ((lane >> 3) & 1) * 8;

    auto loadA = [&](uint32_t sb, int k0) {
#pragma unroll
        for (int i = 0; i < 4; i++) {
            int u = t + i * 256;
            int row = u >> 3, ch = (u & 7) << 3;
            bool p = (m0 + row < M) && (k0 + ch < K);
            const __half* sp = p ? Ab + (size_t)(m0 + row) * lda + k0 + ch : Ab;
            asm volatile("cp.async.cg.shared.global [%0], [%1], 16, %2;"
                         :: "r"(sb + (uint32_t)(row * 72 + ch) * 2u),
                            "l"(sp), "r"(p ? 16 : 0));
        }
    };
    auto loadB = [&](uint32_t sb, int k0) {
#pragma unroll
        for (int i = 0; i < 4; i++) {
            int u = t + i * 256;
            int row = u >> 3, ch = (u & 7) << 3;
            if (CDIM == 0) {
                bool p = (n0 + row < N) && (k0 + ch < K);
                const __half* sp = p ? Bb + (size_t)(n0 + row) * ldb + k0 + ch : Bb;
                asm volatile("cp.async.cg.shared.global [%0], [%1], 16, %2;"
                             :: "r"(sb + (uint32_t)(row * 72 + ch) * 2u),
                                "l"(sp), "r"(p ? 16 : 0));
            } else {
                constexpr int OW = CDIM / 2;
                int k   = k0 + ch;            // half index in [0, 4608)
                int kk  = k >> 9;             // 0..8
                int icc = k & 511;
                int pix = n0 + row;
                int oh = pix / OW, ow = pix - oh * OW;
                int kh = kk / 3, kw = kk - kh * 3;
                int ih = 2 * oh - 1 + kh, iw = 2 * ow - 1 + kw;
                bool p = (pix < N) && (ih >= 0) && (ih < CDIM)
                       && (iw >= 0) && (iw < CDIM);
                const __half* sp = p ? Bb + ((size_t)ih * CDIM + iw) * CH + icc : Bb;
                asm volatile("cp.async.cg.shared.global [%0], [%1], 16, %2;"
                             :: "r"(sb + (uint32_t)(row * 72 + ch) * 2u),
                                "l"(sp), "r"(p ? 16 : 0));
            }
        }
    };

    float acc[4][4][4];
#pragma unroll
    for (int a = 0; a < 4; a++)
#pragma unroll
        for (int b = 0; b < 4; b++)
#pragma unroll
            for (int c = 0; c < 4; c++) acc[a][b][c] = 0.f;

    const uint32_t stA[3] = { sb0, sb0 + GH_STG * 2, sb0 + 2 * GH_STG * 2 };
    const uint32_t stB[3] = { sb0 + 3 * GH_STG * 2, sb0 + 4 * GH_STG * 2,
                              sb0 + 5 * GH_STG * 2 };

    const int nk = (K + 63) >> 6;
    loadA(stA[0], 0);
    loadB(stB[0], 0);
    asm volatile("cp.async.commit_group;");
    if (nk > 1) {
        loadA(stA[1], 64);
        loadB(stB[1], 64);
    }
    asm volatile("cp.async.commit_group;");

    int cur = 0, nxt = 2;
    for (int kt = 0; kt < nk; kt++) {
        asm volatile("cp.async.wait_group 1;");
        __syncthreads();

        if (kt + 2 < nk) {
            loadA(stA[nxt], (kt + 2) * 64);
            loadB(stB[nxt], (kt + 2) * 64);
        }
        asm volatile("cp.async.commit_group;");

        const uint32_t As = stA[cur];
        const uint32_t Bs = stB[cur];

#pragma unroll
        for (int s = 0; s < 64; s += 16) {
            uint32_t a[4][4], b[4][2];
#pragma unroll
            for (int mt = 0; mt < 4; mt++) {
                uint32_t ad = As + (uint32_t)((wm * 64 + mt * 16 + aRow) * 72
                                              + s + aK) * 2u;
                asm volatile(
                    "ldmatrix.sync.aligned.m8n8.x4.shared.b16 {%0,%1,%2,%3}, [%4];"
                    : "=r"(a[mt][0]), "=r"(a[mt][1]), "=r"(a[mt][2]), "=r"(a[mt][3])
                    : "r"(ad));
            }
#pragma unroll
            for (int nt2 = 0; nt2 < 2; nt2++) {
                uint32_t bd = Bs + (uint32_t)((wn * 32 + nt2 * 16 + bRow) * 72
                                              + s + bK) * 2u;
                asm volatile(
                    "ldmatrix.sync.aligned.m8n8.x4.shared.b16 {%0,%1,%2,%3}, [%4];"
                    : "=r"(b[2 * nt2][0]), "=r"(b[2 * nt2][1]),
                      "=r"(b[2 * nt2 + 1][0]), "=r"(b[2 * nt2 + 1][1])
                    : "r"(bd));
            }
#pragma unroll
            for (int mt = 0; mt < 4; mt++)
#pragma unroll
                for (int nt = 0; nt < 4; nt++) {
                    asm volatile(
                        "mma.sync.aligned.m16n8k16.row.col.f32.f16.f16.f32 "
                        "{%0,%1,%2,%3}, {%4,%5,%6,%7}, {%8,%9}, {%0,%1,%2,%3};"
                        : "+f"(acc[mt][nt][0]), "+f"(acc[mt][nt][1]),
                          "+f"(acc[mt][nt][2]), "+f"(acc[mt][nt][3])
                        : "r"(a[mt][0]), "r"(a[mt][1]), "r"(a[mt][2]), "r"(a[mt][3]),
                          "r"(b[nt][0]), "r"(b[nt][1]));
                }
        }
        cur = (cur + 1) == 3 ? 0 : cur + 1;
        nxt = (nxt + 1) == 3 ? 0 : nxt + 1;
    }

    float s = scl ? *scl : 1.f;
#pragma unroll
    for (int mt = 0; mt < 4; mt++) {
#pragma unroll
        for (int half = 0; half < 2; half++) {
            int gr = m0 + wm * 64 + mt * 16 + g + half * 8;
            if (gr >= M) continue;
            float bm = biasM ? biasM[gr] : 0.f;
#pragma unroll
            for (int nt = 0; nt < 4; nt++) {
                int gc = n0 + wn * 32 + nt * 8 + tg * 2;
                if (gc + 1 >= N) continue;
                float v0 = s * acc[mt][nt][half * 2 + 0] + bm;
                float v1 = s * acc[mt][nt][half * 2 + 1] + bm;
                if (biasN) { v0 += biasN[gc]; v1 += biasN[gc + 1]; }
                size_t idx = (size_t)bz * sC + (size_t)gr * N + gc;
                if (addm) {
                    __half2 av = *(const __half2*)(addm + idx);
                    v0 += __half2float(av.x);
                    v1 += __half2float(av.y);
                }
                if (OUT == 0) {
                    *(float2*)(Cf + idx) = make_float2(v0, v1);
                } else {
                    *(__half2*)(Ch + idx) = __floats2half2_rn(v0, v1);
                }
            }
        }
    }
}

// ---------------------------------------------------------------------------
// BN statistics: one block per channel, deterministic tree reduction.
// ---------------------------------------------------------------------------
__global__ void bn_stats_k(const float* __restrict__ y, int HW,
                           const float* __restrict__ gw,
                           const float* __restrict__ gb,
                           float* __restrict__ scale,
                           float* __restrict__ shift)
{
    const int c = blockIdx.x;
    const int t = threadIdx.x;
    float s = 0.f, s2 = 0.f;
    for (int b = 0; b < BATCH; b++) {
        const float* p = y + ((size_t)b * CH + c) * HW;
        for (int i = t; i < HW; i += 256) {
            float v = p[i];
            s += v; s2 += v * v;
        }
    }
#pragma unroll
    for (int o = 16; o; o >>= 1) {
        s  += __shfl_xor_sync(0xffffffffu, s, o);
        s2 += __shfl_xor_sync(0xffffffffu, s2, o);
    }
    __shared__ float r1[8], r2[8];
    if ((t & 31) == 0) { r1[t >> 5] = s; r2[t >> 5] = s2; }
    __syncthreads();
    if (t == 0) {
        float a = 0.f, b2 = 0.f;
        for (int i = 0; i < 8; i++) { a += r1[i]; b2 += r2[i]; }
        float n   = (float)(BATCH * HW);
        float m   = a / n;
        float var = b2 / n - m * m;
        float sc  = gw[c] * rsqrtf(var + EPSV);
        scale[c] = sc;
        shift[c] = gb[c] - m * sc;
    }
}

// ---------------------------------------------------------------------------
// Row softmax: fp32 energy in, fp16 probs out. One block per row.
// ---------------------------------------------------------------------------
__global__ void softmax_k(const float* __restrict__ E, __half* __restrict__ P, int L)
{
    extern __shared__ float sm[];
    float* red = sm + L;
    const size_t row = blockIdx.x;
    const float* p = E + row * (size_t)L;
    __half* q = P + row * (size_t)L;
    const int t = threadIdx.x;

    float mx = -3.4e38f;
    for (int i = t; i < L; i += 256) {
        float v = p[i];
        sm[i] = v;
        mx = fmaxf(mx, v);
    }
#pragma unroll
    for (int o = 16; o; o >>= 1) mx = fmaxf(mx, __shfl_xor_sync(0xffffffffu, mx, o));
    if ((t & 31) == 0) red[t >> 5] = mx;
    __syncthreads();
    if (t < 32) {
        float v = (t < 8) ? red[t] : -3.4e38f;
#pragma unroll
        for (int o = 4; o; o >>= 1) v = fmaxf(v, __shfl_xor_sync(0xffffffffu, v, o));
        if (t == 0) red[0] = v;
    }
    __syncthreads();
    mx = red[0];
    __syncthreads();

    float ss = 0.f;
    for (int i = t; i < L; i += 256) {
        float e = __expf(sm[i] - mx);
        sm[i] = e;
        ss += e;
    }
#pragma unroll
    for (int o = 16; o; o >>= 1) ss += __shfl_xor_sync(0xffffffffu, ss, o);
    if ((t & 31) == 0) red[t >> 5] = ss;
    __syncthreads();
    if (t < 32) {
        float v = (t < 8) ? red[t] : 0.f;
#pragma unroll
        for (int o = 4; o; o >>= 1) v += __shfl_xor_sync(0xffffffffu, v, o);
        if (t == 0) red[0] = v;
    }
    __syncthreads();
    float inv = 1.f / red[0];
    for (int i = t; i < L; i += 256) q[i] = __float2half(sm[i] * inv);
}

// ---------------------------------------------------------------------------
// dst = add + g * bilinear_upsample(src)
// ---------------------------------------------------------------------------
__global__ void up_fma_k(const float* __restrict__ src, int SH, int SWd,
                         const float* __restrict__ add, float* __restrict__ dst,
                         int DH, int DW, const float* __restrict__ gptr,
                         size_t total)
{
    size_t i = (size_t)blockIdx.x * blockDim.x + threadIdx.x;
    if (i >= total) return;
    int ox = (int)(i % DW);
    int oy = (int)((i / DW) % DH);
    size_t bc = i / ((size_t)DW * DH);

    float ry = (float)(SH - 1) / (float)(DH - 1);
    float rx = (float)(SWd - 1) / (float)(DW - 1);
    float ys = oy * ry, xs = ox * rx;
    int y0 = (int)ys; if (y0 > SH - 1) y0 = SH - 1;
    int x0 = (int)xs; if (x0 > SWd - 1) x0 = SWd - 1;
    int y1 = min(y0 + 1, SH - 1);
    int x1 = min(x0 + 1, SWd - 1);
    float tty = ys - (float)y0, ttx = xs - (float)x0;

    const float* sp = src + bc * (size_t)(SH * SWd);
    float v00 = sp[y0 * SWd + x0], v01 = sp[y0 * SWd + x1];
    float v10 = sp[y1 * SWd + x0], v11 = sp[y1 * SWd + x1];
    float val = v00 * (1.f - tty) * (1.f - ttx) + v01 * (1.f - tty) * ttx
              + v10 * tty * (1.f - ttx) + v11 * tty * ttx;
    float g = gptr ? *gptr : 1.f;
    dst[i] = add[i] + g * val;
}

// ---------------------------------------------------------------------------
// Host side
// ---------------------------------------------------------------------------
static inline unsigned cdiv(unsigned a, unsigned b) { return (a + b - 1) / b; }

struct Bufs {
    float *d2, *d3, *d4, *att, *p2, *p3, *p4, *t3, *t2, *scale, *shift, *qkb;
    __half *xh, *d2h, *d3h, *d4h, *qkt, *vh, *ph, *wh, *qkwh, *vwh;
};

static void run_pam(const __half* dh, int HW,
                    const float* qw, const float* qb,
                    const float* kw, const float* kb,
                    const float* vw, const float* vb,
                    const float* g, float* pout, const Bufs& B)
{
    dim3 thr(256);
    unsigned nb = cdiv(HW, 128);
    long long dhS  = (long long)HW * CH;
    long long qkS  = (long long)HW * 2 * KDIM;
    long long vS   = (long long)CH * HW;
    long long aS   = (long long)HW * HW;

    f2h_k<<<cdiv(KDIM * CH, 256), 256>>>(qw, B.qkwh, KDIM * CH);
    f2h_k<<<cdiv(KDIM * CH, 256), 256>>>(kw, B.qkwh + KDIM * CH, KDIM * CH);
    f2h_k<<<cdiv(CH * CH, 256), 256>>>(vw, B.vwh, CH * CH);
    cudaMemcpyAsync(B.qkb, qb, KDIM * sizeof(float), cudaMemcpyDeviceToDevice);
    cudaMemcpyAsync(B.qkb + KDIM, kb, KDIM * sizeof(float), cudaMemcpyDeviceToDevice);

    // [q|k]^T = dh * qkw^T + qkb  (M=HW, N=256, K=512), fp16 out
    gemm_h<1, 0><<<dim3(2, nb, BATCH), thr, GH_SMEM>>>(dh, B.qkwh, nullptr, B.qkt,
        HW, 2 * KDIM, CH, CH, CH, dhS, 0, qkS, nullptr, B.qkb, nullptr, nullptr);
    // v = vw * d + vb  (M=512, N=HW, K=512), fp16 out
    gemm_h<1, 0><<<dim3(nb, 4, BATCH), thr, GH_SMEM>>>(B.vwh, dh, nullptr, B.vh,
        CH, HW, CH, CH, CH, 0, dhS, vS, vb, nullptr, nullptr, nullptr);
    // energy = q^T k  (M=N=HW, K=128), fp32 out
    gemm_h<0, 0><<<dim3(nb, nb, BATCH), thr, GH_SMEM>>>(B.qkt, B.qkt + KDIM,
        B.att, nullptr, HW, HW, KDIM, 2 * KDIM, 2 * KDIM, qkS, qkS, aS,
        nullptr, nullptr, nullptr, nullptr);
    softmax_k<<<BATCH * HW, 256, (HW + 32) * sizeof(float)>>>(B.att, B.ph, HW);
    // p = g*(v @ attn^T) + v  (M=512, N=HW, K=HW), fp32 out
    gemm_h<0, 0><<<dim3(nb, 4, BATCH), thr, GH_SMEM>>>(B.vh, B.ph, pout, nullptr,
        CH, HW, HW, HW, HW, vS, aS, vS, nullptr, nullptr, B.vh, g);
}

template <int IH>
static void run_conv(const __half* src_h, const float* wgt, float* out,
                     const Bufs& B)
{
    constexpr int OH = IH / 2, OHOW = OH * OH;
    conv_w2h_k<<<cdiv(CH * KC, 256), 256>>>(wgt, B.wh);
    // implicit-im2col conv GEMM: A = weights [oc][k], B = activations [pix][c]
    gemm_h<0, IH><<<dim3(cdiv(OHOW, 128), 4, BATCH), dim3(256), GH_SMEM>>>(
        B.wh, src_h, out, nullptr, CH, OHOW, KC, KC, 0,
        0, (long long)IH * IH * CH, (long long)CH * OHOW,
        nullptr, nullptr, nullptr, nullptr);
}

extern "C" void kernel_launch(void* const* d_in, const int* in_sizes, int n_in,
                              void* d_out, int out_size)
{
    (void)in_sizes; (void)n_in; (void)out_size;

    cudaFuncSetAttribute(gemm_h<0, 0>,  cudaFuncAttributeMaxDynamicSharedMemorySize, GH_SMEM);
    cudaFuncSetAttribute(gemm_h<1, 0>,  cudaFuncAttributeMaxDynamicSharedMemorySize, GH_SMEM);
    cudaFuncSetAttribute(gemm_h<0, 96>, cudaFuncAttributeMaxDynamicSharedMemorySize, GH_SMEM);
    cudaFuncSetAttribute(gemm_h<0, 48>, cudaFuncAttributeMaxDynamicSharedMemorySize, GH_SMEM);
    cudaFuncSetAttribute(gemm_h<0, 24>, cudaFuncAttributeMaxDynamicSharedMemorySize, GH_SMEM);

    const float* x = (const float*)d_in[0];
    const float* w2   = (const float*)d_in[1];
    const float* bnw2 = (const float*)d_in[2];
    const float* bnb2 = (const float*)d_in[3];
    const float* w3   = (const float*)d_in[11];
    const float* bnw3 = (const float*)d_in[12];
    const float* bnb3 = (const float*)d_in[13];
    const float* w4   = (const float*)d_in[21];
    const float* bnw4 = (const float*)d_in[22];
    const float* bnb4 = (const float*)d_in[23];
    const float* gamma = (const float*)d_in[31];
    float* out = (float*)d_out;

    Bufs B;
    void* p;
    cudaGetSymbolAddress(&p, g_d2);    B.d2    = (float*)p;
    cudaGetSymbolAddress(&p, g_d3);    B.d3    = (float*)p;
    cudaGetSymbolAddress(&p, g_d4);    B.d4    = (float*)p;
    cudaGetSymbolAddress(&p, g_att);   B.att   = (float*)p;
    cudaGetSymbolAddress(&p, g_p2);    B.p2    = (float*)p;
    cudaGetSymbolAddress(&p, g_p3);    B.p3    = (float*)p;
    cudaGetSymbolAddress(&p, g_p4);    B.p4    = (float*)p;
    cudaGetSymbolAddress(&p, g_t3);    B.t3    = (float*)p;
    cudaGetSymbolAddress(&p, g_t2);    B.t2    = (float*)p;
    cudaGetSymbolAddress(&p, g_scale); B.scale = (float*)p;
    cudaGetSymbolAddress(&p, g_shift); B.shift = (float*)p;
    cudaGetSymbolAddress(&p, g_qkb);   B.qkb   = (float*)p;
    cudaGetSymbolAddress(&p, g_xh);    B.xh    = (__half*)p;
    cudaGetSymbolAddress(&p, g_d2h);   B.d2h   = (__half*)p;
    cudaGetSymbolAddress(&p, g_d3h);   B.d3h   = (__half*)p;
    cudaGetSymbolAddress(&p, g_d4h);   B.d4h   = (__half*)p;
    cudaGetSymbolAddress(&p, g_qkt);   B.qkt   = (__half*)p;
    cudaGetSymbolAddress(&p, g_vh);    B.vh    = (__half*)p;
    cudaGetSymbolAddress(&p, g_ph);    B.ph    = (__half*)p;
    cudaGetSymbolAddress(&p, g_wh);    B.wh    = (__half*)p;
    cudaGetSymbolAddress(&p, g_qkwh);  B.qkwh  = (__half*)p;
    cudaGetSymbolAddress(&p, g_vwh);   B.vwh   = (__half*)p;

    dim3 tb(32, 8);

    // x -> fp16 transposed [pix][c]
    bnT_k<0><<<dim3(cdiv(HW1, 32), 16, BATCH), tb>>>(x, nullptr, nullptr, B.xh, HW1);

    // ---- encoder ----
    run_conv<96>(B.xh, w2, B.d2, B);
    bn_stats_k<<<CH, 256>>>(B.d2, HW2, bnw2, bnb2, B.scale, B.shift);
    bnT_k<1><<<dim3(cdiv(HW2, 32), 16, BATCH), tb>>>(B.d2, B.scale, B.shift, B.d2h, HW2);

    run_conv<48>(B.d2h, w3, B.d3, B);
    bn_stats_k<<<CH, 256>>>(B.d3, HW3, bnw3, bnb3, B.scale, B.shift);
    bnT_k<1><<<dim3(cdiv(HW3, 32), 16, BATCH), tb>>>(B.d3, B.scale, B.shift, B.d3h, HW3);

    run_conv<24>(B.d3h, w4, B.d4, B);
    bn_stats_k<<<CH, 256>>>(B.d4, HW4, bnw4, bnb4, B.scale, B.shift);
    bnT_k<1><<<dim3(cdiv(HW4, 32), 16, BATCH), tb>>>(B.d4, B.scale, B.shift, B.d4h, HW4);

    // ---- PAM at each level ----
    run_pam(B.d2h, HW2, (const float*)d_in[4],  (const float*)d_in[5],
                        (const float*)d_in[6],  (const float*)d_in[7],
                        (const float*)d_in[8],  (const float*)d_in[9],
                        (const float*)d_in[10], B.p2, B);
    run_pam(B.d3h, HW3, (const float*)d_in[14], (const float*)d_in[15],
                        (const float*)d_in[16], (const float*)d_in[17],
                        (const float*)d_in[18], (const float*)d_in[19],
                        (const float*)d_in[20], B.p3, B);
    run_pam(B.d4h, HW4, (const float*)d_in[24], (const float*)d_in[25],
                        (const float*)d_in[26], (const float*)d_in[27],
                        (const float*)d_in[28], (const float*)d_in[29],
                        (const float*)d_in[30], B.p4, B);

    // ---- top-down upsample chain ----
    {
        size_t tot = (size_t)BATCH * CH * HW3;
        up_fma_k<<<(unsigned)((tot + 255) / 256), 256>>>(B.p4, 12, 12, B.p3, B.t3,
                                                         24, 24, nullptr, tot);
    }
    {
        size_t tot = (size_t)BATCH * CH * HW2;
        up_fma_k<<<(unsigned)((tot + 255) / 256), 256>>>(B.t3, 24, 24, B.p2, B.t2,
                                                         48, 48, nullptr, tot);
    }
    {
        size_t tot = (size_t)BATCH * CH * HW1;
        up_fma_k<<<(unsigned)((tot + 255) / 256), 256>>>(B.t2, 48, 48, x, out,
                                                         96, 96, gamma, tot);
    }
}

// round 13
// speedup vs baseline: 6.8961x; 1.0044x over previous
#include <cuda_runtime.h>
#include <cuda_fp16.h>
#include <cstddef>
#include <cstdint>
#include <math.h>

// ---------------------------------------------------------------------------
// Problem constants
// ---------------------------------------------------------------------------
#define BATCH 8
#define CH    512
#define KDIM  128
#define EPSV  1e-5f

#define HW1 9216           // 96*96
#define HW2 2304           // 48*48
#define HW3 576            // 24*24
#define HW4 144            // 12*12
#define KC  4608           // 512*9 im2col K

// ---------------------------------------------------------------------------
// Scratch (allocation-free: __device__ globals)
// ---------------------------------------------------------------------------
__device__ float g_d2[BATCH * CH * HW2];
__device__ float g_d3[BATCH * CH * HW3];
__device__ float g_d4[BATCH * CH * HW4];
__device__ float g_att[(size_t)BATCH * HW2 * HW2];   // fp32 energy
__device__ float g_scale[CH];
__device__ float g_shift[CH];

__device__ __half g_p2h[BATCH * CH * HW2];
__device__ __half g_p3h[BATCH * CH * HW3];
__device__ __half g_p4h[BATCH * CH * HW4];
__device__ __half g_t3h[BATCH * CH * HW3];
__device__ __half g_t2h[BATCH * CH * HW2];

__device__ __half g_xh [(size_t)BATCH * HW1 * CH];   // x transposed fp16 [pix][c]
__device__ __half g_d2h[(size_t)BATCH * HW2 * CH];   // bn+relu+T fp16
__device__ __half g_d3h[(size_t)BATCH * HW3 * CH];
__device__ __half g_d4h[(size_t)BATCH * HW4 * CH];
__device__ __half g_qkt[(size_t)BATCH * HW2 * 2 * KDIM]; // q|k fp16 [pix][256]
__device__ __half g_vh [(size_t)BATCH * CH * HW2];   // v fp16 [c][pix]
__device__ __half g_ph [(size_t)BATCH * HW2 * HW2];  // softmax probs fp16

// per-level converted weights
__device__ __half g_wh2[CH * KC];
__device__ __half g_wh3[CH * KC];
__device__ __half g_wh4[CH * KC];
__device__ __half g_qkwh2[2 * KDIM * CH];
__device__ __half g_qkwh3[2 * KDIM * CH];
__device__ __half g_qkwh4[2 * KDIM * CH];
__device__ __half g_vwh2[CH * CH];
__device__ __half g_vwh3[CH * CH];
__device__ __half g_vwh4[CH * CH];
__device__ float  g_qkb2[2 * KDIM];
__device__ float  g_qkb3[2 * KDIM];
__device__ float  g_qkb4[2 * KDIM];

// ---------------------------------------------------------------------------
// One-shot weight prep: converts everything for all 3 levels.
// ---------------------------------------------------------------------------
#define CONVN (CH * KC)            // 2359296
#define QKWN  (2 * KDIM * CH)      // 131072
#define VWN   (CH * CH)            // 262144
#define PREP_TOTAL (3 * CONVN + 3 * QKWN + 3 * VWN + 3 * 256)

__global__ void prep_w_k(const float* __restrict__ w2, const float* __restrict__ w3,
                         const float* __restrict__ w4,
                         const float* __restrict__ qw2, const float* __restrict__ kw2,
                         const float* __restrict__ vw2,
                         const float* __restrict__ qb2, const float* __restrict__ kb2,
                         const float* __restrict__ qw3, const float* __restrict__ kw3,
                         const float* __restrict__ vw3,
                         const float* __restrict__ qb3, const float* __restrict__ kb3,
                         const float* __restrict__ qw4, const float* __restrict__ kw4,
                         const float* __restrict__ vw4,
                         const float* __restrict__ qb4, const float* __restrict__ kb4)
{
    int i = blockIdx.x * blockDim.x + threadIdx.x;
    if (i >= PREP_TOTAL) return;

    if (i < 3 * CONVN) {
        int lvl = i / CONVN, j = i - lvl * CONVN;
        const float* w = lvl == 0 ? w2 : (lvl == 1 ? w3 : w4);
        __half* o = lvl == 0 ? g_wh2 : (lvl == 1 ? g_wh3 : g_wh4);
        int ic = j & 511, kk = (j >> 9) % 9, oc = j / KC;
        o[j] = __float2half(w[((size_t)oc * CH + ic) * 9 + kk]);
        return;
    }
    i -= 3 * CONVN;
    if (i < 3 * QKWN) {
        int lvl = i / QKWN, j = i - lvl * QKWN;
        const float* q = lvl == 0 ? qw2 : (lvl == 1 ? qw3 : qw4);
        const float* k = lvl == 0 ? kw2 : (lvl == 1 ? kw3 : kw4);
        __half* o = lvl == 0 ? g_qkwh2 : (lvl == 1 ? g_qkwh3 : g_qkwh4);
        o[j] = __float2half(j < KDIM * CH ? q[j] : k[j - KDIM * CH]);
        return;
    }
    i -= 3 * QKWN;
    if (i < 3 * VWN) {
        int lvl = i / VWN, j = i - lvl * VWN;
        const float* v = lvl == 0 ? vw2 : (lvl == 1 ? vw3 : vw4);
        __half* o = lvl == 0 ? g_vwh2 : (lvl == 1 ? g_vwh3 : g_vwh4);
        o[j] = __float2half(v[j]);
        return;
    }
    i -= 3 * VWN;
    {
        int lvl = i / 256, j = i - lvl * 256;
        const float* q = lvl == 0 ? qb2 : (lvl == 1 ? qb3 : qb4);
        const float* k = lvl == 0 ? kb2 : (lvl == 1 ? kb3 : kb4);
        float* o = lvl == 0 ? g_qkb2 : (lvl == 1 ? g_qkb3 : g_qkb4);
        o[j] = j < KDIM ? q[j] : k[j - KDIM];
    }
}

// ---------------------------------------------------------------------------
// Transpose (+optional BN+ReLU): fp32 [b][c][pix] -> fp16 [b][pix][c]
// ---------------------------------------------------------------------------
template <int BN_ON>
__global__ void bnT_k(const float* __restrict__ y,
                      const float* __restrict__ scale,
                      const float* __restrict__ shift,
                      __half* __restrict__ out, int HW)
{
    __shared__ float tile[32][33];
    int b = blockIdx.z;
    int p0 = blockIdx.x * 32, c0 = blockIdx.y * 32;
    int tx = threadIdx.x, ty = threadIdx.y;
#pragma unroll
    for (int j = 0; j < 4; j++) {
        int c = c0 + ty + j * 8;
        int p = p0 + tx;
        float v = 0.f;
        if (p < HW) v = y[((size_t)b * CH + c) * HW + p];
        if (BN_ON) { v = v * scale[c] + shift[c]; v = v > 0.f ? v : 0.f; }
        tile[ty + j * 8][tx] = v;
    }
    __syncthreads();
#pragma unroll
    for (int j = 0; j < 4; j++) {
        int p = p0 + ty + j * 8;
        int c = c0 + tx;
        if (p < HW) out[((size_t)b * HW + p) * CH + c] = __float2half(tile[tx][ty + j * 8]);
    }
}

// ---------------------------------------------------------------------------
// fp16 tensor-core GEMM, cp.async 3-stage pipeline, K-chunk 64, ldmatrix.
// C(M,N) = A(M,K)[m][k] * B(N,K)[n][k]^T, k-contiguous fp16 operands.
// CDIM > 0: implicit-im2col B operand (3x3 s2 p1 conv, input [pix][c],
// spatial CDIM x CDIM).  OUT=0: fp32 C; OUT=1: fp16 C.
// Epilogue: C = s*acc + biasM[row] + biasN[col] + addm (all optional).
// ---------------------------------------------------------------------------
#define GH_STG (128 * 72)                 // halves per operand per stage
#define GH_SMEM (6 * GH_STG * 2)          // 110592 bytes (3 stages x 2 ops)

template <int OUT, int CDIM>
__global__ __launch_bounds__(256)
void gemm_h(const __half* __restrict__ A, const __half* __restrict__ B,
            float* __restrict__ Cf, __half* __restrict__ Ch,
            int M, int N, int K, int lda, int ldb,
            long long sA, long long sB, long long sC,
            const float* __restrict__ biasM, const float* __restrict__ biasN,
            const __half* __restrict__ addm, const float* __restrict__ scl)
{
    extern __shared__ __align__(16) __half smh[];

    const int bz = blockIdx.z;
    const __half* Ab = A + (size_t)bz * sA;
    const __half* Bb = B + (size_t)bz * sB;

    const int n0 = blockIdx.x * 128, m0 = blockIdx.y * 128;
    const int t = threadIdx.x, lane = t & 31, w = t >> 5;
    const int wm = w & 1, wn = w >> 1;
    const int g = lane >> 2, tg = lane & 3;

    const uint32_t sb0 = (uint32_t)__cvta_generic_to_shared(smh);

    const int aRow = (lane & 7) + ((lane >> 3) & 1) * 8;
    const int aK   = ((lane >> 4) & 1) * 8;
    const int bRow = (lane & 7) + ((lane >> 4) & 1) * 8;
    const int bK   = ((lane >> 3) & 1) * 8;

    auto loadA = [&](uint32_t sb, int k0) {
#pragma unroll
        for (int i = 0; i < 4; i++) {
            int u = t + i * 256;
            int row = u >> 3, ch = (u & 7) << 3;
            bool p = (m0 + row < M) && (k0 + ch < K);
            const __half* sp = p ? Ab + (size_t)(m0 + row) * lda + k0 + ch : Ab;
            asm volatile("cp.async.cg.shared.global [%0], [%1], 16, %2;"
                         :: "r"(sb + (uint32_t)(row * 72 + ch) * 2u),
                            "l"(sp), "r"(p ? 16 : 0));
        }
    };
    auto loadB = [&](uint32_t sb, int k0) {
#pragma unroll
        for (int i = 0; i < 4; i++) {
            int u = t + i * 256;
            int row = u >> 3, ch = (u & 7) << 3;
            if (CDIM == 0) {
                bool p = (n0 + row < N) && (k0 + ch < K);
                const __half* sp = p ? Bb + (size_t)(n0 + row) * ldb + k0 + ch : Bb;
                asm volatile("cp.async.cg.shared.global [%0], [%1], 16, %2;"
                             :: "r"(sb + (uint32_t)(row * 72 + ch) * 2u),
                                "l"(sp), "r"(p ? 16 : 0));
            } else {
                constexpr int OW = CDIM / 2;
                int k   = k0 + ch;
                int kk  = k >> 9;
                int icc = k & 511;
                int pix = n0 + row;
                int oh = pix / OW, ow = pix - oh * OW;
                int kh = kk / 3, kw = kk - kh * 3;
                int ih = 2 * oh - 1 + kh, iw = 2 * ow - 1 + kw;
                bool p = (pix < N) && (ih >= 0) && (ih < CDIM)
                       && (iw >= 0) && (iw < CDIM);
                const __half* sp = p ? Bb + ((size_t)ih * CDIM + iw) * CH + icc : Bb;
                asm volatile("cp.async.cg.shared.global [%0], [%1], 16, %2;"
                             :: "r"(sb + (uint32_t)(row * 72 + ch) * 2u),
                                "l"(sp), "r"(p ? 16 : 0));
            }
        }
    };

    float acc[4][4][4];
#pragma unroll
    for (int a = 0; a < 4; a++)
#pragma unroll
        for (int b = 0; b < 4; b++)
#pragma unroll
            for (int c = 0; c < 4; c++) acc[a][b][c] = 0.f;

    const uint32_t stA[3] = { sb0, sb0 + GH_STG * 2, sb0 + 2 * GH_STG * 2 };
    const uint32_t stB[3] = { sb0 + 3 * GH_STG * 2, sb0 + 4 * GH_STG * 2,
                              sb0 + 5 * GH_STG * 2 };

    const int nk = (K + 63) >> 6;
    loadA(stA[0], 0);
    loadB(stB[0], 0);
    asm volatile("cp.async.commit_group;");
    if (nk > 1) {
        loadA(stA[1], 64);
        loadB(stB[1], 64);
    }
    asm volatile("cp.async.commit_group;");

    int cur = 0, nxt = 2;
    for (int kt = 0; kt < nk; kt++) {
        asm volatile("cp.async.wait_group 1;");
        __syncthreads();

        if (kt + 2 < nk) {
            loadA(stA[nxt], (kt + 2) * 64);
            loadB(stB[nxt], (kt + 2) * 64);
        }
        asm volatile("cp.async.commit_group;");

        const uint32_t As = stA[cur];
        const uint32_t Bs = stB[cur];

#pragma unroll
        for (int s = 0; s < 64; s += 16) {
            uint32_t a[4][4], b[4][2];
#pragma unroll
            for (int mt = 0; mt < 4; mt++) {
                uint32_t ad = As + (uint32_t)((wm * 64 + mt * 16 + aRow) * 72
                                              + s + aK) * 2u;
                asm volatile(
                    "ldmatrix.sync.aligned.m8n8.x4.shared.b16 {%0,%1,%2,%3}, [%4];"
                    : "=r"(a[mt][0]), "=r"(a[mt][1]), "=r"(a[mt][2]), "=r"(a[mt][3])
                    : "r"(ad));
            }
#pragma unroll
            for (int nt2 = 0; nt2 < 2; nt2++) {
                uint32_t bd = Bs + (uint32_t)((wn * 32 + nt2 * 16 + bRow) * 72
                                              + s + bK) * 2u;
                asm volatile(
                    "ldmatrix.sync.aligned.m8n8.x4.shared.b16 {%0,%1,%2,%3}, [%4];"
                    : "=r"(b[2 * nt2][0]), "=r"(b[2 * nt2][1]),
                      "=r"(b[2 * nt2 + 1][0]), "=r"(b[2 * nt2 + 1][1])
                    : "r"(bd));
            }
#pragma unroll
            for (int mt = 0; mt < 4; mt++)
#pragma unroll
                for (int nt = 0; nt < 4; nt++) {
                    asm volatile(
                        "mma.sync.aligned.m16n8k16.row.col.f32.f16.f16.f32 "
                        "{%0,%1,%2,%3}, {%4,%5,%6,%7}, {%8,%9}, {%0,%1,%2,%3};"
                        : "+f"(acc[mt][nt][0]), "+f"(acc[mt][nt][1]),
                          "+f"(acc[mt][nt][2]), "+f"(acc[mt][nt][3])
                        : "r"(a[mt][0]), "r"(a[mt][1]), "r"(a[mt][2]), "r"(a[mt][3]),
                          "r"(b[nt][0]), "r"(b[nt][1]));
                }
        }
        cur = (cur + 1) == 3 ? 0 : cur + 1;
        nxt = (nxt + 1) == 3 ? 0 : nxt + 1;
    }

    float s = scl ? *scl : 1.f;
#pragma unroll
    for (int mt = 0; mt < 4; mt++) {
#pragma unroll
        for (int half = 0; half < 2; half++) {
            int gr = m0 + wm * 64 + mt * 16 + g + half * 8;
            if (gr >= M) continue;
            float bm = biasM ? biasM[gr] : 0.f;
#pragma unroll
            for (int nt = 0; nt < 4; nt++) {
                int gc = n0 + wn * 32 + nt * 8 + tg * 2;
                if (gc + 1 >= N) continue;
                float v0 = s * acc[mt][nt][half * 2 + 0] + bm;
                float v1 = s * acc[mt][nt][half * 2 + 1] + bm;
                if (biasN) { v0 += biasN[gc]; v1 += biasN[gc + 1]; }
                size_t idx = (size_t)bz * sC + (size_t)gr * N + gc;
                if (addm) {
                    __half2 av = *(const __half2*)(addm + idx);
                    v0 += __half2float(av.x);
                    v1 += __half2float(av.y);
                }
                if (OUT == 0) {
                    *(float2*)(Cf + idx) = make_float2(v0, v1);
                } else {
                    *(__half2*)(Ch + idx) = __floats2half2_rn(v0, v1);
                }
            }
        }
    }
}

// ---------------------------------------------------------------------------
// BN statistics: one block per channel, deterministic tree reduction.
// ---------------------------------------------------------------------------
__global__ void bn_stats_k(const float* __restrict__ y, int HW,
                           const float* __restrict__ gw,
                           const float* __restrict__ gb,
                           float* __restrict__ scale,
                           float* __restrict__ shift)
{
    const int c = blockIdx.x;
    const int t = threadIdx.x;
    float s = 0.f, s2 = 0.f;
    for (int b = 0; b < BATCH; b++) {
        const float* p = y + ((size_t)b * CH + c) * HW;
        for (int i = t; i < HW; i += 256) {
            float v = p[i];
            s += v; s2 += v * v;
        }
    }
#pragma unroll
    for (int o = 16; o; o >>= 1) {
        s  += __shfl_xor_sync(0xffffffffu, s, o);
        s2 += __shfl_xor_sync(0xffffffffu, s2, o);
    }
    __shared__ float r1[8], r2[8];
    if ((t & 31) == 0) { r1[t >> 5] = s; r2[t >> 5] = s2; }
    __syncthreads();
    if (t == 0) {
        float a = 0.f, b2 = 0.f;
        for (int i = 0; i < 8; i++) { a += r1[i]; b2 += r2[i]; }
        float n   = (float)(BATCH * HW);
        float m   = a / n;
        float var = b2 / n - m * m;
        float sc  = gw[c] * rsqrtf(var + EPSV);
        scale[c] = sc;
        shift[c] = gb[c] - m * sc;
    }
}

// ---------------------------------------------------------------------------
// Row softmax: fp32 energy in, fp16 probs out.
// ---------------------------------------------------------------------------
__global__ void softmax_k(const float* __restrict__ E, __half* __restrict__ P, int L)
{
    extern __shared__ float sm[];
    float* red = sm + L;
    const size_t row = blockIdx.x;
    const float* p = E + row * (size_t)L;
    __half* q = P + row * (size_t)L;
    const int t = threadIdx.x;

    float mx = -3.4e38f;
    for (int i = t; i < L; i += 256) {
        float v = p[i];
        sm[i] = v;
        mx = fmaxf(mx, v);
    }
#pragma unroll
    for (int o = 16; o; o >>= 1) mx = fmaxf(mx, __shfl_xor_sync(0xffffffffu, mx, o));
    if ((t & 31) == 0) red[t >> 5] = mx;
    __syncthreads();
    if (t < 32) {
        float v = (t < 8) ? red[t] : -3.4e38f;
#pragma unroll
        for (int o = 4; o; o >>= 1) v = fmaxf(v, __shfl_xor_sync(0xffffffffu, v, o));
        if (t == 0) red[0] = v;
    }
    __syncthreads();
    mx = red[0];
    __syncthreads();

    float ss = 0.f;
    for (int i = t; i < L; i += 256) {
        float e = __expf(sm[i] - mx);
        sm[i] = e;
        ss += e;
    }
#pragma unroll
    for (int o = 16; o; o >>= 1) ss += __shfl_xor_sync(0xffffffffu, ss, o);
    if ((t & 31) == 0) red[t >> 5] = ss;
    __syncthreads();
    if (t < 32) {
        float v = (t < 8) ? red[t] : 0.f;
#pragma unroll
        for (int o = 4; o; o >>= 1) v += __shfl_xor_sync(0xffffffffu, v, o);
        if (t == 0) red[0] = v;
    }
    __syncthreads();
    float inv = 1.f / red[0];
    for (int i = t; i < L; i += 256) q[i] = __float2half(sm[i] * inv);
}

// ---------------------------------------------------------------------------
// dst = add + g * bilinear_upsample(src)   (templated element types)
// ---------------------------------------------------------------------------
__device__ __forceinline__ float ldv(const float* p)  { return *p; }
__device__ __forceinline__ float ldv(const __half* p) { return __half2float(*p); }
__device__ __forceinline__ void stv(float* p, float v)  { *p = v; }
__device__ __forceinline__ void stv(__half* p, float v) { *p = __float2half(v); }

template <typename TS, typename TA, typename TD>
__global__ void up_fma_k(const TS* __restrict__ src, int SH, int SWd,
                         const TA* __restrict__ add, TD* __restrict__ dst,
                         int DH, int DW, const float* __restrict__ gptr,
                         size_t total)
{
    size_t i = (size_t)blockIdx.x * blockDim.x + threadIdx.x;
    if (i >= total) return;
    int ox = (int)(i % DW);
    int oy = (int)((i / DW) % DH);
    size_t bc = i / ((size_t)DW * DH);

    float ry = (float)(SH - 1) / (float)(DH - 1);
    float rx = (float)(SWd - 1) / (float)(DW - 1);
    float ys = oy * ry, xs = ox * rx;
    int y0 = (int)ys; if (y0 > SH - 1) y0 = SH - 1;
    int x0 = (int)xs; if (x0 > SWd - 1) x0 = SWd - 1;
    int y1 = min(y0 + 1, SH - 1);
    int x1 = min(x0 + 1, SWd - 1);
    float tty = ys - (float)y0, ttx = xs - (float)x0;

    const TS* sp = src + bc * (size_t)(SH * SWd);
    float v00 = ldv(sp + y0 * SWd + x0), v01 = ldv(sp + y0 * SWd + x1);
    float v10 = ldv(sp + y1 * SWd + x0), v11 = ldv(sp + y1 * SWd + x1);
    float val = v00 * (1.f - tty) * (1.f - ttx) + v01 * (1.f - tty) * ttx
              + v10 * tty * (1.f - ttx) + v11 * tty * ttx;
    float g = gptr ? *gptr : 1.f;
    stv(dst + i, ldv(add + i) + g * val);
}

// ---------------------------------------------------------------------------
// Host side
// ---------------------------------------------------------------------------
static inline unsigned cdiv(unsigned a, unsigned b) { return (a + b - 1) / b; }

struct Bufs {
    float *d2, *d3, *d4, *att, *scale, *shift;
    __half *p2h, *p3h, *p4h, *t3h, *t2h;
    __half *xh, *d2h, *d3h, *d4h, *qkt, *vh, *ph;
    __half *wh2, *wh3, *wh4, *qkwh2, *qkwh3, *qkwh4, *vwh2, *vwh3, *vwh4;
    float *qkb2, *qkb3, *qkb4;
};

static void run_pam(const __half* dh, int HW,
                    const __half* qkwh, const float* qkb,
                    const __half* vwh, const float* vb,
                    const float* g, __half* pout, const Bufs& B)
{
    dim3 thr(256);
    unsigned nb = cdiv(HW, 128);
    long long dhS  = (long long)HW * CH;
    long long qkS  = (long long)HW * 2 * KDIM;
    long long vS   = (long long)CH * HW;
    long long aS   = (long long)HW * HW;

    // [q|k]^T = dh * qkw^T + qkb  (M=HW, N=256, K=512), fp16 out
    gemm_h<1, 0><<<dim3(2, nb, BATCH), thr, GH_SMEM>>>(dh, qkwh, nullptr, B.qkt,
        HW, 2 * KDIM, CH, CH, CH, dhS, 0, qkS, nullptr, qkb, nullptr, nullptr);
    // v = vw * d + vb  (M=512, N=HW, K=512), fp16 out
    gemm_h<1, 0><<<dim3(nb, 4, BATCH), thr, GH_SMEM>>>(vwh, dh, nullptr, B.vh,
        CH, HW, CH, CH, CH, 0, dhS, vS, vb, nullptr, nullptr, nullptr);
    // energy = q^T k  (M=N=HW, K=128), fp32 out
    gemm_h<0, 0><<<dim3(nb, nb, BATCH), thr, GH_SMEM>>>(B.qkt, B.qkt + KDIM,
        B.att, nullptr, HW, HW, KDIM, 2 * KDIM, 2 * KDIM, qkS, qkS, aS,
        nullptr, nullptr, nullptr, nullptr);
    softmax_k<<<BATCH * HW, 256, (HW + 32) * sizeof(float)>>>(B.att, B.ph, HW);
    // p = g*(v @ attn^T) + v  (M=512, N=HW, K=HW), fp16 out
    gemm_h<1, 0><<<dim3(nb, 4, BATCH), thr, GH_SMEM>>>(B.vh, B.ph, nullptr, pout,
        CH, HW, HW, HW, HW, vS, aS, vS, nullptr, nullptr, B.vh, g);
}

template <int IH>
static void run_conv(const __half* src_h, const __half* wh, float* out)
{
    constexpr int OH = IH / 2, OHOW = OH * OH;
    gemm_h<0, IH><<<dim3(cdiv(OHOW, 128), 4, BATCH), dim3(256), GH_SMEM>>>(
        wh, src_h, out, nullptr, CH, OHOW, KC, KC, 0,
        0, (long long)IH * IH * CH, (long long)CH * OHOW,
        nullptr, nullptr, nullptr, nullptr);
}

extern "C" void kernel_launch(void* const* d_in, const int* in_sizes, int n_in,
                              void* d_out, int out_size)
{
    (void)in_sizes; (void)n_in; (void)out_size;

    cudaFuncSetAttribute(gemm_h<0, 0>,  cudaFuncAttributeMaxDynamicSharedMemorySize, GH_SMEM);
    cudaFuncSetAttribute(gemm_h<1, 0>,  cudaFuncAttributeMaxDynamicSharedMemorySize, GH_SMEM);
    cudaFuncSetAttribute(gemm_h<0, 96>, cudaFuncAttributeMaxDynamicSharedMemorySize, GH_SMEM);
    cudaFuncSetAttribute(gemm_h<0, 48>, cudaFuncAttributeMaxDynamicSharedMemorySize, GH_SMEM);
    cudaFuncSetAttribute(gemm_h<0, 24>, cudaFuncAttributeMaxDynamicSharedMemorySize, GH_SMEM);

    const float* x = (const float*)d_in[0];
    const float* w2   = (const float*)d_in[1];
    const float* bnw2 = (const float*)d_in[2];
    const float* bnb2 = (const float*)d_in[3];
    const float* w3   = (const float*)d_in[11];
    const float* bnw3 = (const float*)d_in[12];
    const float* bnb3 = (const float*)d_in[13];
    const float* w4   = (const float*)d_in[21];
    const float* bnw4 = (const float*)d_in[22];
    const float* bnb4 = (const float*)d_in[23];
    const float* gamma = (const float*)d_in[31];
    float* out = (float*)d_out;

    Bufs B;
    void* p;
    cudaGetSymbolAddress(&p, g_d2);    B.d2    = (float*)p;
    cudaGetSymbolAddress(&p, g_d3);    B.d3    = (float*)p;
    cudaGetSymbolAddress(&p, g_d4);    B.d4    = (float*)p;
    cudaGetSymbolAddress(&p, g_att);   B.att   = (float*)p;
    cudaGetSymbolAddress(&p, g_scale); B.scale = (float*)p;
    cudaGetSymbolAddress(&p, g_shift); B.shift = (float*)p;
    cudaGetSymbolAddress(&p, g_p2h);   B.p2h   = (__half*)p;
    cudaGetSymbolAddress(&p, g_p3h);   B.p3h   = (__half*)p;
    cudaGetSymbolAddress(&p, g_p4h);   B.p4h   = (__half*)p;
    cudaGetSymbolAddress(&p, g_t3h);   B.t3h   = (__half*)p;
    cudaGetSymbolAddress(&p, g_t2h);   B.t2h   = (__half*)p;
    cudaGetSymbolAddress(&p, g_xh);    B.xh    = (__half*)p;
    cudaGetSymbolAddress(&p, g_d2h);   B.d2h   = (__half*)p;
    cudaGetSymbolAddress(&p, g_d3h);   B.d3h   = (__half*)p;
    cudaGetSymbolAddress(&p, g_d4h);   B.d4h   = (__half*)p;
    cudaGetSymbolAddress(&p, g_qkt);   B.qkt   = (__half*)p;
    cudaGetSymbolAddress(&p, g_vh);    B.vh    = (__half*)p;
    cudaGetSymbolAddress(&p, g_ph);    B.ph    = (__half*)p;
    cudaGetSymbolAddress(&p, g_wh2);   B.wh2   = (__half*)p;
    cudaGetSymbolAddress(&p, g_wh3);   B.wh3   = (__half*)p;
    cudaGetSymbolAddress(&p, g_wh4);   B.wh4   = (__half*)p;
    cudaGetSymbolAddress(&p, g_qkwh2); B.qkwh2 = (__half*)p;
    cudaGetSymbolAddress(&p, g_qkwh3); B.qkwh3 = (__half*)p;
    cudaGetSymbolAddress(&p, g_qkwh4); B.qkwh4 = (__half*)p;
    cudaGetSymbolAddress(&p, g_vwh2);  B.vwh2  = (__half*)p;
    cudaGetSymbolAddress(&p, g_vwh3);  B.vwh3  = (__half*)p;
    cudaGetSymbolAddress(&p, g_vwh4);  B.vwh4  = (__half*)p;
    cudaGetSymbolAddress(&p, g_qkb2);  B.qkb2  = (float*)p;
    cudaGetSymbolAddress(&p, g_qkb3);  B.qkb3  = (float*)p;
    cudaGetSymbolAddress(&p, g_qkb4);  B.qkb4  = (float*)p;

    dim3 tb(32, 8);

    // one-shot weight prep for all levels
    prep_w_k<<<cdiv(PREP_TOTAL, 256), 256>>>(
        w2, w3, w4,
        (const float*)d_in[4],  (const float*)d_in[6],  (const float*)d_in[8],
        (const float*)d_in[5],  (const float*)d_in[7],
        (const float*)d_in[14], (const float*)d_in[16], (const float*)d_in[18],
        (const float*)d_in[15], (const float*)d_in[17],
        (const float*)d_in[24], (const float*)d_in[26], (const float*)d_in[28],
        (const float*)d_in[25], (const float*)d_in[27]);

    // x -> fp16 transposed [pix][c]
    bnT_k<0><<<dim3(cdiv(HW1, 32), 16, BATCH), tb>>>(x, nullptr, nullptr, B.xh, HW1);

    // ---- encoder ----
    run_conv<96>(B.xh, B.wh2, B.d2);
    bn_stats_k<<<CH, 256>>>(B.d2, HW2, bnw2, bnb2, B.scale, B.shift);
    bnT_k<1><<<dim3(cdiv(HW2, 32), 16, BATCH), tb>>>(B.d2, B.scale, B.shift, B.d2h, HW2);

    run_conv<48>(B.d2h, B.wh3, B.d3);
    bn_stats_k<<<CH, 256>>>(B.d3, HW3, bnw3, bnb3, B.scale, B.shift);
    bnT_k<1><<<dim3(cdiv(HW3, 32), 16, BATCH), tb>>>(B.d3, B.scale, B.shift, B.d3h, HW3);

    run_conv<24>(B.d3h, B.wh4, B.d4);
    bn_stats_k<<<CH, 256>>>(B.d4, HW4, bnw4, bnb4, B.scale, B.shift);
    bnT_k<1><<<dim3(cdiv(HW4, 32), 16, BATCH), tb>>>(B.d4, B.scale, B.shift, B.d4h, HW4);

    // ---- PAM at each level ----
    run_pam(B.d2h, HW2, B.qkwh2, B.qkb2, B.vwh2, (const float*)d_in[9],
            (const float*)d_in[10], B.p2h, B);
    run_pam(B.d3h, HW3, B.qkwh3, B.qkb3, B.vwh3, (const float*)d_in[19],
            (const float*)d_in[20], B.p3h, B);
    run_pam(B.d4h, HW4, B.qkwh4, B.qkb4, B.vwh4, (const float*)d_in[29],
            (const float*)d_in[30], B.p4h, B);

    // ---- top-down upsample chain (fp16 intermediates) ----
    {
        size_t tot = (size_t)BATCH * CH * HW3;
        up_fma_k<<<(unsigned)((tot + 255) / 256), 256>>>(B.p4h, 12, 12, B.p3h, B.t3h,
                                                         24, 24, nullptr, tot);
    }
    {
        size_t tot = (size_t)BATCH * CH * HW2;
        up_fma_k<<<(unsigned)((tot + 255) / 256), 256>>>(B.t3h, 24, 24, B.p2h, B.t2h,
                                                         48, 48, nullptr, tot);
    }
    {
        size_t tot = (size_t)BATCH * CH * HW1;
        up_fma_k<<<(unsigned)((tot + 255) / 256), 256>>>(B.t2h, 48, 48, x, out,
                                                         96, 96, gamma, tot);
    }
}

// round 15
// speedup vs baseline: 6.9801x; 1.0122x over previous
#include <cuda_runtime.h>
#include <cuda_fp16.h>
#include <cstddef>
#include <cstdint>
#include <math.h>

// ---------------------------------------------------------------------------
// Problem constants
// ---------------------------------------------------------------------------
#define BATCH 8
#define CH    512
#define KDIM  128
#define EPSV  1e-5f

#define HW1 9216           // 96*96
#define HW2 2304           // 48*48
#define HW3 576            // 24*24
#define HW4 144            // 12*12
#define KC  4608           // 512*9 im2col K

// ---------------------------------------------------------------------------
// Scratch (allocation-free: __device__ globals)
// ---------------------------------------------------------------------------
__device__ float g_scale[CH];
__device__ float g_shift[CH];

__device__ __half g_c2[BATCH * CH * HW2];            // conv out fp16 [c][pix]
__device__ __half g_c3[BATCH * CH * HW3];
__device__ __half g_c4[BATCH * CH * HW4];
__device__ __half g_eh[(size_t)BATCH * HW2 * HW2];   // fp16 energy
__device__ __half g_ph[(size_t)BATCH * HW2 * HW2];   // fp16 softmax probs

__device__ __half g_p2h[BATCH * CH * HW2];
__device__ __half g_p3h[BATCH * CH * HW3];
__device__ __half g_p4h[BATCH * CH * HW4];
__device__ __half g_t3h[BATCH * CH * HW3];
__device__ __half g_t2h[BATCH * CH * HW2];

__device__ __half g_xh [(size_t)BATCH * HW1 * CH];   // x transposed fp16 [pix][c]
__device__ __half g_d2h[(size_t)BATCH * HW2 * CH];   // bn+relu+T fp16
__device__ __half g_d3h[(size_t)BATCH * HW3 * CH];
__device__ __half g_d4h[(size_t)BATCH * HW4 * CH];
__device__ __half g_qkt[(size_t)BATCH * HW2 * 2 * KDIM]; // q|k fp16 [pix][256]
__device__ __half g_vh [(size_t)BATCH * CH * HW2];   // v fp16 [c][pix]

// per-level converted weights
__device__ __half g_wh2[CH * KC];
__device__ __half g_wh3[CH * KC];
__device__ __half g_wh4[CH * KC];
__device__ __half g_qkwh2[2 * KDIM * CH];
__device__ __half g_qkwh3[2 * KDIM * CH];
__device__ __half g_qkwh4[2 * KDIM * CH];
__device__ __half g_vwh2[CH * CH];
__device__ __half g_vwh3[CH * CH];
__device__ __half g_vwh4[CH * CH];
__device__ float  g_qkb2[2 * KDIM];
__device__ float  g_qkb3[2 * KDIM];
__device__ float  g_qkb4[2 * KDIM];

// ---------------------------------------------------------------------------
// Load/store helpers
// ---------------------------------------------------------------------------
__device__ __forceinline__ float ldv(const float* p)  { return *p; }
__device__ __forceinline__ float ldv(const __half* p) { return __half2float(*p); }
__device__ __forceinline__ void stv(float* p, float v)  { *p = v; }
__device__ __forceinline__ void stv(__half* p, float v) { *p = __float2half(v); }

// ---------------------------------------------------------------------------
// One-shot weight prep: converts everything for all 3 levels.
// ---------------------------------------------------------------------------
#define CONVN (CH * KC)            // 2359296
#define QKWN  (2 * KDIM * CH)      // 131072
#define VWN   (CH * CH)            // 262144
#define PREP_TOTAL (3 * CONVN + 3 * QKWN + 3 * VWN + 3 * 256)

__global__ void prep_w_k(const float* __restrict__ w2, const float* __restrict__ w3,
                         const float* __restrict__ w4,
                         const float* __restrict__ qw2, const float* __restrict__ kw2,
                         const float* __restrict__ vw2,
                         const float* __restrict__ qb2, const float* __restrict__ kb2,
                         const float* __restrict__ qw3, const float* __restrict__ kw3,
                         const float* __restrict__ vw3,
                         const float* __restrict__ qb3, const float* __restrict__ kb3,
                         const float* __restrict__ qw4, const float* __restrict__ kw4,
                         const float* __restrict__ vw4,
                         const float* __restrict__ qb4, const float* __restrict__ kb4)
{
    int i = blockIdx.x * blockDim.x + threadIdx.x;
    if (i >= PREP_TOTAL) return;

    if (i < 3 * CONVN) {
        int lvl = i / CONVN, j = i - lvl * CONVN;
        const float* w = lvl == 0 ? w2 : (lvl == 1 ? w3 : w4);
        __half* o = lvl == 0 ? g_wh2 : (lvl == 1 ? g_wh3 : g_wh4);
        int ic = j & 511, kk = (j >> 9) % 9, oc = j / KC;
        o[j] = __float2half(w[((size_t)oc * CH + ic) * 9 + kk]);
        return;
    }
    i -= 3 * CONVN;
    if (i < 3 * QKWN) {
        int lvl = i / QKWN, j = i - lvl * QKWN;
        const float* q = lvl == 0 ? qw2 : (lvl == 1 ? qw3 : qw4);
        const float* k = lvl == 0 ? kw2 : (lvl == 1 ? kw3 : kw4);
        __half* o = lvl == 0 ? g_qkwh2 : (lvl == 1 ? g_qkwh3 : g_qkwh4);
        o[j] = __float2half(j < KDIM * CH ? q[j] : k[j - KDIM * CH]);
        return;
    }
    i -= 3 * QKWN;
    if (i < 3 * VWN) {
        int lvl = i / VWN, j = i - lvl * VWN;
        const float* v = lvl == 0 ? vw2 : (lvl == 1 ? vw3 : vw4);
        __half* o = lvl == 0 ? g_vwh2 : (lvl == 1 ? g_vwh3 : g_vwh4);
        o[j] = __float2half(v[j]);
        return;
    }
    i -= 3 * VWN;
    {
        int lvl = i / 256, j = i - lvl * 256;
        const float* q = lvl == 0 ? qb2 : (lvl == 1 ? qb3 : qb4);
        const float* k = lvl == 0 ? kb2 : (lvl == 1 ? kb3 : kb4);
        float* o = lvl == 0 ? g_qkb2 : (lvl == 1 ? g_qkb3 : g_qkb4);
        o[j] = j < KDIM ? q[j] : k[j - KDIM];
    }
}

// ---------------------------------------------------------------------------
// Transpose (+optional BN+ReLU): [b][c][pix] (TS) -> fp16 [b][pix][c]
// ---------------------------------------------------------------------------
template <int BN_ON, typename TS>
__global__ void bnT_k(const TS* __restrict__ y,
                      const float* __restrict__ scale,
                      const float* __restrict__ shift,
                      __half* __restrict__ out, int HW)
{
    __shared__ float tile[32][33];
    int b = blockIdx.z;
    int p0 = blockIdx.x * 32, c0 = blockIdx.y * 32;
    int tx = threadIdx.x, ty = threadIdx.y;
#pragma unroll
    for (int j = 0; j < 4; j++) {
        int c = c0 + ty + j * 8;
        int p = p0 + tx;
        float v = 0.f;
        if (p < HW) v = ldv(y + ((size_t)b * CH + c) * HW + p);
        if (BN_ON) { v = v * scale[c] + shift[c]; v = v > 0.f ? v : 0.f; }
        tile[ty + j * 8][tx] = v;
    }
    __syncthreads();
#pragma unroll
    for (int j = 0; j < 4; j++) {
        int p = p0 + ty + j * 8;
        int c = c0 + tx;
        if (p < HW) out[((size_t)b * HW + p) * CH + c] = __float2half(tile[tx][ty + j * 8]);
    }
}

// ---------------------------------------------------------------------------
// fp16 tensor-core GEMM, cp.async 3-stage pipeline, K-chunk 64, ldmatrix.
// C(M,N) = A(M,K)[m][k] * B(N,K)[n][k]^T, k-contiguous fp16 operands.
// CDIM > 0: implicit-im2col B operand (3x3 s2 p1 conv, input [pix][c],
// spatial CDIM x CDIM).  OUT=0: fp32 C; OUT=1: fp16 C.
// Epilogue: C = s*acc + biasM[row] + biasN[col] + addm (all optional).
// ---------------------------------------------------------------------------
#define GH_STG (128 * 72)                 // halves per operand per stage
#define GH_SMEM (6 * GH_STG * 2)          // 110592 bytes (3 stages x 2 ops)

template <int OUT, int CDIM>
__global__ __launch_bounds__(256)
void gemm_h(const __half* __restrict__ A, const __half* __restrict__ B,
            float* __restrict__ Cf, __half* __restrict__ Ch,
            int M, int N, int K, int lda, int ldb,
            long long sA, long long sB, long long sC,
            const float* __restrict__ biasM, const float* __restrict__ biasN,
            const __half* __restrict__ addm, const float* __restrict__ scl)
{
    extern __shared__ __align__(16) __half smh[];

    const int bz = blockIdx.z;
    const __half* Ab = A + (size_t)bz * sA;
    const __half* Bb = B + (size_t)bz * sB;

    const int n0 = blockIdx.x * 128, m0 = blockIdx.y * 128;
    const int t = threadIdx.x, lane = t & 31, w = t >> 5;
    const int wm = w & 1, wn = w >> 1;
    const int g = lane >> 2, tg = lane & 3;

    const uint32_t sb0 = (uint32_t)__cvta_generic_to_shared(smh);

    const int aRow = (lane & 7) + ((lane >> 3) & 1) * 8;
    const int aK   = ((lane >> 4) & 1) * 8;
    const int bRow = (lane & 7) + ((lane >> 4) & 1) * 8;
    const int bK   = ((lane >> 3) & 1) * 8;

    auto loadA = [&](uint32_t sb, int k0) {
#pragma unroll
        for (int i = 0; i < 4; i++) {
            int u = t + i * 256;
            int row = u >> 3, ch = (u & 7) << 3;
            bool p = (m0 + row < M) && (k0 + ch < K);
            const __half* sp = p ? Ab + (size_t)(m0 + row) * lda + k0 + ch : Ab;
            asm volatile("cp.async.cg.shared.global [%0], [%1], 16, %2;"
                         :: "r"(sb + (uint32_t)(row * 72 + ch) * 2u),
                            "l"(sp), "r"(p ? 16 : 0));
        }
    };
    auto loadB = [&](uint32_t sb, int k0) {
#pragma unroll
        for (int i = 0; i < 4; i++) {
            int u = t + i * 256;
            int row = u >> 3, ch = (u & 7) << 3;
            if (CDIM == 0) {
                bool p = (n0 + row < N) && (k0 + ch < K);
                const __half* sp = p ? Bb + (size_t)(n0 + row) * ldb + k0 + ch : Bb;
                asm volatile("cp.async.cg.shared.global [%0], [%1], 16, %2;"
                             :: "r"(sb + (uint32_t)(row * 72 + ch) * 2u),
                                "l"(sp), "r"(p ? 16 : 0));
            } else {
                constexpr int OW = CDIM / 2;
                int k   = k0 + ch;
                int kk  = k >> 9;
                int icc = k & 511;
                int pix = n0 + row;
                int oh = pix / OW, ow = pix - oh * OW;
                int kh = kk / 3, kw = kk - kh * 3;
                int ih = 2 * oh - 1 + kh, iw = 2 * ow - 1 + kw;
                bool p = (pix < N) && (ih >= 0) && (ih < CDIM)
                       && (iw >= 0) && (iw < CDIM);
                const __half* sp = p ? Bb + ((size_t)ih * CDIM + iw) * CH + icc : Bb;
                asm volatile("cp.async.cg.shared.global [%0], [%1], 16, %2;"
                             :: "r"(sb + (uint32_t)(row * 72 + ch) * 2u),
                                "l"(sp), "r"(p ? 16 : 0));
            }
        }
    };

    float acc[4][4][4];
#pragma unroll
    for (int a = 0; a < 4; a++)
#pragma unroll
        for (int b = 0; b < 4; b++)
#pragma unroll
            for (int c = 0; c < 4; c++) acc[a][b][c] = 0.f;

    const uint32_t stA[3] = { sb0, sb0 + GH_STG * 2, sb0 + 2 * GH_STG * 2 };
    const uint32_t stB[3] = { sb0 + 3 * GH_STG * 2, sb0 + 4 * GH_STG * 2,
                              sb0 + 5 * GH_STG * 2 };

    const int nk = (K + 63) >> 6;
    loadA(stA[0], 0);
    loadB(stB[0], 0);
    asm volatile("cp.async.commit_group;");
    if (nk > 1) {
        loadA(stA[1], 64);
        loadB(stB[1], 64);
    }
    asm volatile("cp.async.commit_group;");

    int cur = 0, nxt = 2;
    for (int kt = 0; kt < nk; kt++) {
        asm volatile("cp.async.wait_group 1;");
        __syncthreads();

        if (kt + 2 < nk) {
            loadA(stA[nxt], (kt + 2) * 64);
            loadB(stB[nxt], (kt + 2) * 64);
        }
        asm volatile("cp.async.commit_group;");

        const uint32_t As = stA[cur];
        const uint32_t Bs = stB[cur];

#pragma unroll
        for (int s = 0; s < 64; s += 16) {
            uint32_t a[4][4], b[4][2];
#pragma unroll
            for (int mt = 0; mt < 4; mt++) {
                uint32_t ad = As + (uint32_t)((wm * 64 + mt * 16 + aRow) * 72
                                              + s + aK) * 2u;
                asm volatile(
                    "ldmatrix.sync.aligned.m8n8.x4.shared.b16 {%0,%1,%2,%3}, [%4];"
                    : "=r"(a[mt][0]), "=r"(a[mt][1]), "=r"(a[mt][2]), "=r"(a[mt][3])
                    : "r"(ad));
            }
#pragma unroll
            for (int nt2 = 0; nt2 < 2; nt2++) {
                uint32_t bd = Bs + (uint32_t)((wn * 32 + nt2 * 16 + bRow) * 72
                                              + s + bK) * 2u;
                asm volatile(
                    "ldmatrix.sync.aligned.m8n8.x4.shared.b16 {%0,%1,%2,%3}, [%4];"
                    : "=r"(b[2 * nt2][0]), "=r"(b[2 * nt2][1]),
                      "=r"(b[2 * nt2 + 1][0]), "=r"(b[2 * nt2 + 1][1])
                    : "r"(bd));
            }
#pragma unroll
            for (int mt = 0; mt < 4; mt++)
#pragma unroll
                for (int nt = 0; nt < 4; nt++) {
                    asm volatile(
                        "mma.sync.aligned.m16n8k16.row.col.f32.f16.f16.f32 "
                        "{%0,%1,%2,%3}, {%4,%5,%6,%7}, {%8,%9}, {%0,%1,%2,%3};"
                        : "+f"(acc[mt][nt][0]), "+f"(acc[mt][nt][1]),
                          "+f"(acc[mt][nt][2]), "+f"(acc[mt][nt][3])
                        : "r"(a[mt][0]), "r"(a[mt][1]), "r"(a[mt][2]), "r"(a[mt][3]),
                          "r"(b[nt][0]), "r"(b[nt][1]));
                }
        }
        cur = (cur + 1) == 3 ? 0 : cur + 1;
        nxt = (nxt + 1) == 3 ? 0 : nxt + 1;
    }

    float s = scl ? *scl : 1.f;
#pragma unroll
    for (int mt = 0; mt < 4; mt++) {
#pragma unroll
        for (int half = 0; half < 2; half++) {
            int gr = m0 + wm * 64 + mt * 16 + g + half * 8;
            if (gr >= M) continue;
            float bm = biasM ? biasM[gr] : 0.f;
#pragma unroll
            for (int nt = 0; nt < 4; nt++) {
                int gc = n0 + wn * 32 + nt * 8 + tg * 2;
                if (gc + 1 >= N) continue;
                float v0 = s * acc[mt][nt][half * 2 + 0] + bm;
                float v1 = s * acc[mt][nt][half * 2 + 1] + bm;
                if (biasN) { v0 += biasN[gc]; v1 += biasN[gc + 1]; }
                size_t idx = (size_t)bz * sC + (size_t)gr * N + gc;
                if (addm) {
                    __half2 av = *(const __half2*)(addm + idx);
                    v0 += __half2float(av.x);
                    v1 += __half2float(av.y);
                }
                if (OUT == 0) {
                    *(float2*)(Cf + idx) = make_float2(v0, v1);
                } else {
                    *(__half2*)(Ch + idx) = __floats2half2_rn(v0, v1);
                }
            }
        }
    }
}

// ---------------------------------------------------------------------------
// BN statistics from fp16 conv output (fp32 accumulators).
// ---------------------------------------------------------------------------
__global__ void bn_stats_k(const __half* __restrict__ y, int HW,
                           const float* __restrict__ gw,
                           const float* __restrict__ gb,
                           float* __restrict__ scale,
                           float* __restrict__ shift)
{
    const int c = blockIdx.x;
    const int t = threadIdx.x;
    float s = 0.f, s2 = 0.f;
    for (int b = 0; b < BATCH; b++) {
        const __half* p = y + ((size_t)b * CH + c) * HW;
        for (int i = t; i < HW; i += 256) {
            float v = __half2float(p[i]);
            s += v; s2 += v * v;
        }
    }
#pragma unroll
    for (int o = 16; o; o >>= 1) {
        s  += __shfl_xor_sync(0xffffffffu, s, o);
        s2 += __shfl_xor_sync(0xffffffffu, s2, o);
    }
    __shared__ float r1[8], r2[8];
    if ((t & 31) == 0) { r1[t >> 5] = s; r2[t >> 5] = s2; }
    __syncthreads();
    if (t == 0) {
        float a = 0.f, b2 = 0.f;
        for (int i = 0; i < 8; i++) { a += r1[i]; b2 += r2[i]; }
        float n   = (float)(BATCH * HW);
        float m   = a / n;
        float var = b2 / n - m * m;
        float sc  = gw[c] * rsqrtf(var + EPSV);
        scale[c] = sc;
        shift[c] = gb[c] - m * sc;
    }
}

// ---------------------------------------------------------------------------
// Row softmax: fp16 energy in, fp16 probs out.
// ---------------------------------------------------------------------------
__global__ void softmax_k(const __half* __restrict__ E, __half* __restrict__ P, int L)
{
    extern __shared__ float sm[];
    float* red = sm + L;
    const size_t row = blockIdx.x;
    const __half* p = E + row * (size_t)L;
    __half* q = P + row * (size_t)L;
    const int t = threadIdx.x;

    float mx = -3.4e38f;
    for (int i = t; i < L; i += 256) {
        float v = __half2float(p[i]);
        sm[i] = v;
        mx = fmaxf(mx, v);
    }
#pragma unroll
    for (int o = 16; o; o >>= 1) mx = fmaxf(mx, __shfl_xor_sync(0xffffffffu, mx, o));
    if ((t & 31) == 0) red[t >> 5] = mx;
    __syncthreads();
    if (t < 32) {
        float v = (t < 8) ? red[t] : -3.4e38f;
#pragma unroll
        for (int o = 4; o; o >>= 1) v = fmaxf(v, __shfl_xor_sync(0xffffffffu, v, o));
        if (t == 0) red[0] = v;
    }
    __syncthreads();
    mx = red[0];
    __syncthreads();

    float ss = 0.f;
    for (int i = t; i < L; i += 256) {
        float e = __expf(sm[i] - mx);
        sm[i] = e;
        ss += e;
    }
#pragma unroll
    for (int o = 16; o; o >>= 1) ss += __shfl_xor_sync(0xffffffffu, ss, o);
    if ((t & 31) == 0) red[t >> 5] = ss;
    __syncthreads();
    if (t < 32) {
        float v = (t < 8) ? red[t] : 0.f;
#pragma unroll
        for (int o = 4; o; o >>= 1) v += __shfl_xor_sync(0xffffffffu, v, o);
        if (t == 0) red[0] = v;
    }
    __syncthreads();
    float inv = 1.f / red[0];
    for (int i = t; i < L; i += 256) q[i] = __float2half(sm[i] * inv);
}

// ---------------------------------------------------------------------------
// dst = add + g * bilinear_upsample(src)   (templated element types)
// ---------------------------------------------------------------------------
template <typename TS, typename TA, typename TD>
__global__ void up_fma_k(const TS* __restrict__ src, int SH, int SWd,
                         const TA* __restrict__ add, TD* __restrict__ dst,
                         int DH, int DW, const float* __restrict__ gptr,
                         size_t total)
{
    size_t i = (size_t)blockIdx.x * blockDim.x + threadIdx.x;
    if (i >= total) return;
    int ox = (int)(i % DW);
    int oy = (int)((i / DW) % DH);
    size_t bc = i / ((size_t)DW * DH);

    float ry = (float)(SH - 1) / (float)(DH - 1);
    float rx = (float)(SWd - 1) / (float)(DW - 1);
    float ys = oy * ry, xs = ox * rx;
    int y0 = (int)ys; if (y0 > SH - 1) y0 = SH - 1;
    int x0 = (int)xs; if (x0 > SWd - 1) x0 = SWd - 1;
    int y1 = min(y0 + 1, SH - 1);
    int x1 = min(x0 + 1, SWd - 1);
    float tty = ys - (float)y0, ttx = xs - (float)x0;

    const TS* sp = src + bc * (size_t)(SH * SWd);
    float v00 = ldv(sp + y0 * SWd + x0), v01 = ldv(sp + y0 * SWd + x1);
    float v10 = ldv(sp + y1 * SWd + x0), v11 = ldv(sp + y1 * SWd + x1);
    float val = v00 * (1.f - tty) * (1.f - ttx) + v01 * (1.f - tty) * ttx
              + v10 * tty * (1.f - ttx) + v11 * tty * ttx;
    float g = gptr ? *gptr : 1.f;
    stv(dst + i, ldv(add + i) + g * val);
}

// ---------------------------------------------------------------------------
// Host side
// ---------------------------------------------------------------------------
static inline unsigned cdiv(unsigned a, unsigned b) { return (a + b - 1) / b; }

struct Bufs {
    float *scale, *shift;
    __half *c2, *c3, *c4, *eh, *ph;
    __half *p2h, *p3h, *p4h, *t3h, *t2h;
    __half *xh, *d2h, *d3h, *d4h, *qkt, *vh;
    __half *wh2, *wh3, *wh4, *qkwh2, *qkwh3, *qkwh4, *vwh2, *vwh3, *vwh4;
    float *qkb2, *qkb3, *qkb4;
};

static void run_pam(const __half* dh, int HW,
                    const __half* qkwh, const float* qkb,
                    const __half* vwh, const float* vb,
                    const float* g, __half* pout, const Bufs& B)
{
    dim3 thr(256);
    unsigned nb = cdiv(HW, 128);
    long long dhS  = (long long)HW * CH;
    long long qkS  = (long long)HW * 2 * KDIM;
    long long vS   = (long long)CH * HW;
    long long aS   = (long long)HW * HW;

    // [q|k]^T = dh * qkw^T + qkb  (M=HW, N=256, K=512), fp16 out
    gemm_h<1, 0><<<dim3(2, nb, BATCH), thr, GH_SMEM>>>(dh, qkwh, nullptr, B.qkt,
        HW, 2 * KDIM, CH, CH, CH, dhS, 0, qkS, nullptr, qkb, nullptr, nullptr);
    // v = vw * d + vb  (M=512, N=HW, K=512), fp16 out
    gemm_h<1, 0><<<dim3(nb, 4, BATCH), thr, GH_SMEM>>>(vwh, dh, nullptr, B.vh,
        CH, HW, CH, CH, CH, 0, dhS, vS, vb, nullptr, nullptr, nullptr);
    // energy = q^T k  (M=N=HW, K=128), fp16 out
    gemm_h<1, 0><<<dim3(nb, nb, BATCH), thr, GH_SMEM>>>(B.qkt, B.qkt + KDIM,
        nullptr, B.eh, HW, HW, KDIM, 2 * KDIM, 2 * KDIM, qkS, qkS, aS,
        nullptr, nullptr, nullptr, nullptr);
    softmax_k<<<BATCH * HW, 256, (HW + 32) * sizeof(float)>>>(B.eh, B.ph, HW);
    // p = g*(v @ attn^T) + v  (M=512, N=HW, K=HW), fp16 out
    gemm_h<1, 0><<<dim3(nb, 4, BATCH), thr, GH_SMEM>>>(B.vh, B.ph, nullptr, pout,
        CH, HW, HW, HW, HW, vS, aS, vS, nullptr, nullptr, B.vh, g);
}

template <int IH>
static void run_conv(const __half* src_h, const __half* wh, __half* out)
{
    constexpr int OH = IH / 2, OHOW = OH * OH;
    gemm_h<1, IH><<<dim3(cdiv(OHOW, 128), 4, BATCH), dim3(256), GH_SMEM>>>(
        wh, src_h, nullptr, out, CH, OHOW, KC, KC, 0,
        0, (long long)IH * IH * CH, (long long)CH * OHOW,
        nullptr, nullptr, nullptr, nullptr);
}

extern "C" void kernel_launch(void* const* d_in, const int* in_sizes, int n_in,
                              void* d_out, int out_size)
{
    (void)in_sizes; (void)n_in; (void)out_size;

    cudaFuncSetAttribute(gemm_h<0, 0>,  cudaFuncAttributeMaxDynamicSharedMemorySize, GH_SMEM);
    cudaFuncSetAttribute(gemm_h<1, 0>,  cudaFuncAttributeMaxDynamicSharedMemorySize, GH_SMEM);
    cudaFuncSetAttribute(gemm_h<1, 96>, cudaFuncAttributeMaxDynamicSharedMemorySize, GH_SMEM);
    cudaFuncSetAttribute(gemm_h<1, 48>, cudaFuncAttributeMaxDynamicSharedMemorySize, GH_SMEM);
    cudaFuncSetAttribute(gemm_h<1, 24>, cudaFuncAttributeMaxDynamicSharedMemorySize, GH_SMEM);

    const float* x = (const float*)d_in[0];
    const float* w2   = (const float*)d_in[1];
    const float* bnw2 = (const float*)d_in[2];
    const float* bnb2 = (const float*)d_in[3];
    const float* w3   = (const float*)d_in[11];
    const float* bnw3 = (const float*)d_in[12];
    const float* bnb3 = (const float*)d_in[13];
    const float* w4   = (const float*)d_in[21];
    const float* bnw4 = (const float*)d_in[22];
    const float* bnb4 = (const float*)d_in[23];
    const float* gamma = (const float*)d_in[31];
    float* out = (float*)d_out;

    Bufs B;
    void* p;
    cudaGetSymbolAddress(&p, g_scale); B.scale = (float*)p;
    cudaGetSymbolAddress(&p, g_shift); B.shift = (float*)p;
    cudaGetSymbolAddress(&p, g_c2);    B.c2    = (__half*)p;
    cudaGetSymbolAddress(&p, g_c3);    B.c3    = (__half*)p;
    cudaGetSymbolAddress(&p, g_c4);    B.c4    = (__half*)p;
    cudaGetSymbolAddress(&p, g_eh);    B.eh    = (__half*)p;
    cudaGetSymbolAddress(&p, g_ph);    B.ph    = (__half*)p;
    cudaGetSymbolAddress(&p, g_p2h);   B.p2h   = (__half*)p;
    cudaGetSymbolAddress(&p, g_p3h);   B.p3h   = (__half*)p;
    cudaGetSymbolAddress(&p, g_p4h);   B.p4h   = (__half*)p;
    cudaGetSymbolAddress(&p, g_t3h);   B.t3h   = (__half*)p;
    cudaGetSymbolAddress(&p, g_t2h);   B.t2h   = (__half*)p;
    cudaGetSymbolAddress(&p, g_xh);    B.xh    = (__half*)p;
    cudaGetSymbolAddress(&p, g_d2h);   B.d2h   = (__half*)p;
    cudaGetSymbolAddress(&p, g_d3h);   B.d3h   = (__half*)p;
    cudaGetSymbolAddress(&p, g_d4h);   B.d4h   = (__half*)p;
    cudaGetSymbolAddress(&p, g_qkt);   B.qkt   = (__half*)p;
    cudaGetSymbolAddress(&p, g_vh);    B.vh    = (__half*)p;
    cudaGetSymbolAddress(&p, g_wh2);   B.wh2   = (__half*)p;
    cudaGetSymbolAddress(&p, g_wh3);   B.wh3   = (__half*)p;
    cudaGetSymbolAddress(&p, g_wh4);   B.wh4   = (__half*)p;
    cudaGetSymbolAddress(&p, g_qkwh2); B.qkwh2 = (__half*)p;
    cudaGetSymbolAddress(&p, g_qkwh3); B.qkwh3 = (__half*)p;
    cudaGetSymbolAddress(&p, g_qkwh4); B.qkwh4 = (__half*)p;
    cudaGetSymbolAddress(&p, g_vwh2);  B.vwh2  = (__half*)p;
    cudaGetSymbolAddress(&p, g_vwh3);  B.vwh3  = (__half*)p;
    cudaGetSymbolAddress(&p, g_vwh4);  B.vwh4  = (__half*)p;
    cudaGetSymbolAddress(&p, g_qkb2);  B.qkb2  = (float*)p;
    cudaGetSymbolAddress(&p, g_qkb3);  B.qkb3  = (float*)p;
    cudaGetSymbolAddress(&p, g_qkb4);  B.qkb4  = (float*)p;

    dim3 tb(32, 8);

    // one-shot weight prep for all levels
    prep_w_k<<<cdiv(PREP_TOTAL, 256), 256>>>(
        w2, w3, w4,
        (const float*)d_in[4],  (const float*)d_in[6],  (const float*)d_in[8],
        (const float*)d_in[5],  (const float*)d_in[7],
        (const float*)d_in[14], (const float*)d_in[16], (const float*)d_in[18],
        (const float*)d_in[15], (const float*)d_in[17],
        (const float*)d_in[24], (const float*)d_in[26], (const float*)d_in[28],
        (const float*)d_in[25], (const float*)d_in[27]);

    // x -> fp16 transposed [pix][c]
    bnT_k<0><<<dim3(cdiv(HW1, 32), 16, BATCH), tb>>>(x, (const float*)nullptr,
                                                     (const float*)nullptr, B.xh, HW1);

    // ---- encoder (conv out fp16, BN stats fp16) ----
    run_conv<96>(B.xh, B.wh2, B.c2);
    bn_stats_k<<<CH, 256>>>(B.c2, HW2, bnw2, bnb2, B.scale, B.shift);
    bnT_k<1><<<dim3(cdiv(HW2, 32), 16, BATCH), tb>>>(B.c2, B.scale, B.shift, B.d2h, HW2);

    run_conv<48>(B.d2h, B.wh3, B.c3);
    bn_stats_k<<<CH, 256>>>(B.c3, HW3, bnw3, bnb3, B.scale, B.shift);
    bnT_k<1><<<dim3(cdiv(HW3, 32), 16, BATCH), tb>>>(B.c3, B.scale, B.shift, B.d3h, HW3);

    run_conv<24>(B.d3h, B.wh4, B.c4);
    bn_stats_k<<<CH, 256>>>(B.c4, HW4, bnw4, bnb4, B.scale, B.shift);
    bnT_k<1><<<dim3(cdiv(HW4, 32), 16, BATCH), tb>>>(B.c4, B.scale, B.shift, B.d4h, HW4);

    // ---- PAM at each level ----
    run_pam(B.d2h, HW2, B.qkwh2, B.qkb2, B.vwh2, (const float*)d_in[9],
            (const float*)d_in[10], B.p2h, B);
    run_pam(B.d3h, HW3, B.qkwh3, B.qkb3, B.vwh3, (const float*)d_in[19],
            (const float*)d_in[20], B.p3h, B);
    run_pam(B.d4h, HW4, B.qkwh4, B.qkb4, B.vwh4, (const float*)d_in[29],
            (const float*)d_in[30], B.p4h, B);

    // ---- top-down upsample chain (fp16 intermediates) ----
    {
        size_t tot = (size_t)BATCH * CH * HW3;
        up_fma_k<<<(unsigned)((tot + 255) / 256), 256>>>(B.p4h, 12, 12, B.p3h, B.t3h,
                                                         24, 24, nullptr, tot);
    }
    {
        size_t tot = (size_t)BATCH * CH * HW2;
        up_fma_k<<<(unsigned)((tot + 255) / 256), 256>>>(B.t3h, 24, 24, B.p2h, B.t2h,
                                                         48, 48, nullptr, tot);
    }
    {
        size_t tot = (size_t)BATCH * CH * HW1;
        up_fma_k<<<(unsigned)((tot + 255) / 256), 256>>>(B.t2h, 48, 48, x, out,
                                                         96, 96, gamma, tot);
    }
}